// round 1
// baseline (speedup 1.0000x reference)
#include <cuda_runtime.h>
#include <math.h>

// ---------------------------------------------------------------------------
// Problem constants (from reference setup_inputs: B=4, S=4096, D=1024)
// ---------------------------------------------------------------------------
#define MAXM   (4 * 4096)
#define DD     1024
#define NELEM  ((size_t)MAXM * DD)

// Scratch buffers (static device allocation — allowed by harness rules)
__device__ float g_key[NELEM];
__device__ float g_val[NELEM];
__device__ float g_qry[NELEM];
__device__ float g_kc [NELEM];
__device__ float g_ks [NELEM];
__device__ float g_qc [NELEM];
__device__ float g_qs [NELEM];
__device__ float g_ret[NELEM];
__device__ float g_ortho_part[8192];

// ---------------------------------------------------------------------------
// SGEMM: C[M,N] = A[M,K] @ B[K,N] + bias[N], with fused epilogues.
//   EPI 0: plain store
//   EPI 1: C = cos(v), C2 = sin(v)
//   EPI 2: C = v + resid  (residual add)
// Tile: 128x128x8, 256 threads, 8x8 per thread.
// ---------------------------------------------------------------------------
#define BM 128
#define BN 128
#define BK 8
#define TM 8
#define TN 8

template <int EPI>
__global__ __launch_bounds__(256)
void sgemm_epi(int M, int N, int K,
               const float* __restrict__ A,
               const float* __restrict__ Bw,
               const float* __restrict__ bias,
               float* __restrict__ C,
               float* __restrict__ C2,
               const float* __restrict__ resid)
{
    __shared__ float As[BK][BM];   // transposed: As[k][m]
    __shared__ float Bs[BK][BN];

    const int cRow = blockIdx.y;
    const int cCol = blockIdx.x;
    const int tid  = threadIdx.x;

    const int tRow = tid / (BN / TN);   // 0..15
    const int tCol = tid % (BN / TN);   // 0..15

    // A tile load: 128x8 floats, one float4 per thread
    const int aRow = tid >> 1;          // 0..127
    const int aCol = (tid & 1) * 4;     // 0 or 4
    // B tile load: 8x128 floats, one float4 per thread
    const int bRow = tid >> 5;          // 0..7
    const int bCol = (tid & 31) * 4;    // 0..124

    const float* Aptr = A + (size_t)cRow * BM * K;
    const float* Bptr = Bw + cCol * BN;

    float acc[TM][TN];
    #pragma unroll
    for (int i = 0; i < TM; ++i)
        #pragma unroll
        for (int j = 0; j < TN; ++j)
            acc[i][j] = 0.0f;

    float regA[TM], regB[TN];

    for (int k0 = 0; k0 < K; k0 += BK) {
        float4 a4 = *(const float4*)(Aptr + (size_t)aRow * K + k0 + aCol);
        As[aCol + 0][aRow] = a4.x;
        As[aCol + 1][aRow] = a4.y;
        As[aCol + 2][aRow] = a4.z;
        As[aCol + 3][aRow] = a4.w;
        *(float4*)&Bs[bRow][bCol] =
            *(const float4*)(Bptr + (size_t)(k0 + bRow) * N + bCol);
        __syncthreads();

        #pragma unroll
        for (int k = 0; k < BK; ++k) {
            float4 av0 = *(const float4*)&As[k][tRow * TM];
            float4 av1 = *(const float4*)&As[k][tRow * TM + 4];
            regA[0] = av0.x; regA[1] = av0.y; regA[2] = av0.z; regA[3] = av0.w;
            regA[4] = av1.x; regA[5] = av1.y; regA[6] = av1.z; regA[7] = av1.w;
            float4 bv0 = *(const float4*)&Bs[k][tCol * TN];
            float4 bv1 = *(const float4*)&Bs[k][tCol * TN + 4];
            regB[0] = bv0.x; regB[1] = bv0.y; regB[2] = bv0.z; regB[3] = bv0.w;
            regB[4] = bv1.x; regB[5] = bv1.y; regB[6] = bv1.z; regB[7] = bv1.w;
            #pragma unroll
            for (int i = 0; i < TM; ++i)
                #pragma unroll
                for (int j = 0; j < TN; ++j)
                    acc[i][j] = fmaf(regA[i], regB[j], acc[i][j]);
        }
        __syncthreads();
    }

    #pragma unroll
    for (int i = 0; i < TM; ++i) {
        const int m = cRow * BM + tRow * TM + i;
        #pragma unroll
        for (int j = 0; j < TN; ++j) {
            const int n = cCol * BN + tCol * TN + j;
            const size_t off = (size_t)m * N + n;
            float v = acc[i][j] + bias[n];
            if (EPI == 0) {
                C[off] = v;
            } else if (EPI == 1) {
                float sv, cv;
                sincosf(v, &sv, &cv);
                C[off]  = cv;
                C2[off] = sv;
            } else {
                C[off] = v + resid[off];
            }
        }
    }
}

// ---------------------------------------------------------------------------
// Fused chunked cumsum + retrieve:
//   br = value*kc, bi = value*ks (on the fly)
//   mem = within-chunk cumsum; retrieved = (mem_r*qc + mem_i*qs) / sqrt(S)
// chunk_size read from device (grid-stride over chunks for robustness).
// ---------------------------------------------------------------------------
__global__ __launch_bounds__(256)
void cumsum_retrieve(const float* __restrict__ value,
                     const float* __restrict__ kc, const float* __restrict__ ks,
                     const float* __restrict__ qc, const float* __restrict__ qs,
                     float* __restrict__ ret,
                     int Bb, int S, int D,
                     const int* __restrict__ cs_ptr, float inv_sqrt_S)
{
    const int cs = cs_ptr[0];
    const int nc = (S + cs - 1) / cs;
    const int total = Bb * nc;
    const int d = blockIdx.y * blockDim.x + threadIdx.x;
    if (d >= D) return;

    for (int t = blockIdx.x; t < total; t += gridDim.x) {
        const int b = t / nc;
        const int c = t % nc;
        const int s0 = c * cs;
        const int smax = min(cs, S - s0);
        size_t off = ((size_t)b * S + s0) * D + d;
        float r = 0.0f, im = 0.0f;
        for (int s = 0; s < smax; ++s, off += D) {
            const float v   = value[off];
            r  = fmaf(v, kc[off], r);
            im = fmaf(v, ks[off], im);
            ret[off] = (r * qc[off] + im * qs[off]) * inv_sqrt_S;
        }
    }
}

// ---------------------------------------------------------------------------
// In-place LayerNorm over last dim (one block per row, 256 threads)
// ---------------------------------------------------------------------------
__global__ __launch_bounds__(256)
void layernorm_inplace(float* __restrict__ ret,
                       const float* __restrict__ gamma,
                       const float* __restrict__ beta, int D)
{
    float* p = ret + (size_t)blockIdx.x * D;
    const int tid = threadIdx.x;
    const int per = D / 256;          // 4 for D=1024

    float vals[8];
    float sum = 0.0f, sq = 0.0f;
    for (int i = 0; i < per; ++i) {
        float v = p[tid + i * 256];
        vals[i] = v;
        sum += v;
        sq  += v * v;
    }

    __shared__ float s1[32], s2[32];
    const int lane = tid & 31, w = tid >> 5;
    #pragma unroll
    for (int o = 16; o; o >>= 1) {
        sum += __shfl_down_sync(0xffffffffu, sum, o);
        sq  += __shfl_down_sync(0xffffffffu, sq,  o);
    }
    if (lane == 0) { s1[w] = sum; s2[w] = sq; }
    __syncthreads();
    if (w == 0) {
        sum = (lane < 8) ? s1[lane] : 0.0f;
        sq  = (lane < 8) ? s2[lane] : 0.0f;
        #pragma unroll
        for (int o = 4; o; o >>= 1) {
            sum += __shfl_down_sync(0xffffffffu, sum, o);
            sq  += __shfl_down_sync(0xffffffffu, sq,  o);
        }
        if (lane == 0) {
            const float mean = sum / (float)D;
            const float var  = sq / (float)D - mean * mean;
            s1[0] = mean;
            s2[0] = rsqrtf(var + 1e-5f);
        }
    }
    __syncthreads();
    const float mean = s1[0], rstd = s2[0];
    for (int i = 0; i < per; ++i) {
        const int c = tid + i * 256;
        p[c] = (vals[i] - mean) * rstd * gamma[c] + beta[c];
    }
}

// ---------------------------------------------------------------------------
// Ortho loss: stage 1 — one block per (b,i,j), partial sums over D.
// ---------------------------------------------------------------------------
__global__ __launch_bounds__(256)
void ortho_partial(const float* __restrict__ kc, const float* __restrict__ ks,
                   const int* __restrict__ idx, int S, int D, int n)
{
    const int t = blockIdx.x;
    const int j = t % n;
    const int i = (t / n) % n;
    const int b = t / (n * n);

    if (i == j) {
        if (threadIdx.x == 0) g_ortho_part[t] = 0.0f;
        return;
    }
    const int si = idx[i], sj = idx[j];
    const float* ci = kc + ((size_t)b * S + si) * D;
    const float* cj = kc + ((size_t)b * S + sj) * D;
    const float* ni = ks + ((size_t)b * S + si) * D;
    const float* nj = ks + ((size_t)b * S + sj) * D;

    float acc = 0.0f;
    for (int d = threadIdx.x; d < D; d += blockDim.x) {
        const float v = ci[d] * cj[d] + ni[d] * nj[d];
        acc = fmaf(v, v, acc);
    }

    __shared__ float sh[32];
    const int lane = threadIdx.x & 31, w = threadIdx.x >> 5;
    #pragma unroll
    for (int o = 16; o; o >>= 1) acc += __shfl_down_sync(0xffffffffu, acc, o);
    if (lane == 0) sh[w] = acc;
    __syncthreads();
    if (w == 0) {
        acc = (lane < 8) ? sh[lane] : 0.0f;
        #pragma unroll
        for (int o = 4; o; o >>= 1) acc += __shfl_down_sync(0xffffffffu, acc, o);
        if (lane == 0) g_ortho_part[t] = acc;
    }
}

// Stage 2 — deterministic fixed-order reduction of partials.
__global__ __launch_bounds__(256)
void ortho_reduce(float* __restrict__ out_loc, int total, float denom)
{
    float acc = 0.0f;
    for (int t = threadIdx.x; t < total; t += 256) acc += g_ortho_part[t];

    __shared__ float sh[32];
    const int lane = threadIdx.x & 31, w = threadIdx.x >> 5;
    #pragma unroll
    for (int o = 16; o; o >>= 1) acc += __shfl_down_sync(0xffffffffu, acc, o);
    if (lane == 0) sh[w] = acc;
    __syncthreads();
    if (w == 0) {
        acc = (lane < 8) ? sh[lane] : 0.0f;
        #pragma unroll
        for (int o = 4; o; o >>= 1) acc += __shfl_down_sync(0xffffffffu, acc, o);
        if (lane == 0) *out_loc = acc / denom;
    }
}

// ---------------------------------------------------------------------------
// Launcher
// ---------------------------------------------------------------------------
extern "C" void kernel_launch(void* const* d_in, const int* in_sizes, int n_in,
                              void* d_out, int out_size)
{
    const float* x    = (const float*)d_in[0];
    const float* Wk   = (const float*)d_in[1];
    const float* bk   = (const float*)d_in[2];
    const float* Wv   = (const float*)d_in[3];
    const float* bv   = (const float*)d_in[4];
    const float* Wq   = (const float*)d_in[5];
    const float* bq   = (const float*)d_in[6];
    const float* Wkp  = (const float*)d_in[7];
    const float* bkp  = (const float*)d_in[8];
    const float* Wqp  = (const float*)d_in[9];
    const float* bqp  = (const float*)d_in[10];
    const float* ln_g = (const float*)d_in[11];
    const float* ln_b = (const float*)d_in[12];
    const float* Wo   = (const float*)d_in[13];
    const float* bo   = (const float*)d_in[14];
    const int*   idx  = (const int*)d_in[15];
    const int*   csp  = (const int*)d_in[16];

    const int D  = in_sizes[2];          // 1024 (size of bk)
    const int M  = in_sizes[0] / D;      // 16384
    const int Bb = 4;                    // batch (fixed by problem)
    const int S  = M / Bb;               // 4096
    const int n  = in_sizes[15];         // 32

    float *key, *val, *qry, *kc, *ks, *qc, *qs, *ret;
    cudaGetSymbolAddress((void**)&key, g_key);
    cudaGetSymbolAddress((void**)&val, g_val);
    cudaGetSymbolAddress((void**)&qry, g_qry);
    cudaGetSymbolAddress((void**)&kc,  g_kc);
    cudaGetSymbolAddress((void**)&ks,  g_ks);
    cudaGetSymbolAddress((void**)&qc,  g_qc);
    cudaGetSymbolAddress((void**)&qs,  g_qs);
    cudaGetSymbolAddress((void**)&ret, g_ret);

    float* out = (float*)d_out;

    const dim3 gBlk(256);
    const dim3 gGrid(D / BN, M / BM);

    // key / value / query projections
    sgemm_epi<0><<<gGrid, gBlk>>>(M, D, D, x, Wk, bk, key, nullptr, nullptr);
    sgemm_epi<0><<<gGrid, gBlk>>>(M, D, D, x, Wv, bv, val, nullptr, nullptr);
    sgemm_epi<0><<<gGrid, gBlk>>>(M, D, D, x, Wq, bq, qry, nullptr, nullptr);

    // phase projections, fused cos/sin epilogue
    sgemm_epi<1><<<gGrid, gBlk>>>(M, D, D, key, Wkp, bkp, kc, ks, nullptr);
    sgemm_epi<1><<<gGrid, gBlk>>>(M, D, D, qry, Wqp, bqp, qc, qs, nullptr);

    // chunked complex cumsum + retrieve (fused br/bi)
    const float inv_sqrt_S = 1.0f / sqrtf((float)S);
    cumsum_retrieve<<<dim3(256, D / 256), 256>>>(val, kc, ks, qc, qs, ret,
                                                 Bb, S, D, csp, inv_sqrt_S);

    // layernorm (in place)
    layernorm_inplace<<<M, 256>>>(ret, ln_g, ln_b, D);

    // output projection + residual, straight into d_out
    sgemm_epi<2><<<gGrid, gBlk>>>(M, D, D, ret, Wo, bo, out, nullptr, x);

    // ortho loss -> last output element
    ortho_partial<<<Bb * n * n, 256>>>(kc, ks, idx, S, D, n);
    const float denom = (float)(n * (n - 1)) * (float)D + 1e-6f;
    ortho_reduce<<<1, 256>>>(out + (out_size - 1), Bb * n * n, denom);
}

// round 3
// speedup vs baseline: 2.3295x; 2.3295x over previous
#include <cuda_runtime.h>
#include <cuda_bf16.h>
#include <math.h>
#include <cstdint>

// ---------------------------------------------------------------------------
// Problem constants (B=4, S=4096, D=1024)
// ---------------------------------------------------------------------------
#define MM    16384
#define DDIM  1024
#define NELEM ((size_t)MM * DDIM)

__device__ float g_val[NELEM];
__device__ float g_kc [NELEM];
__device__ float g_ks [NELEM];
__device__ float g_qc [NELEM];
__device__ float g_qs [NELEM];
__device__ float g_ret[NELEM];
__device__ __nv_bfloat16 g_xhi[NELEM], g_xlo[NELEM];
__device__ __nv_bfloat16 g_khi[NELEM], g_klo[NELEM];
__device__ __nv_bfloat16 g_qhi[NELEM], g_qlo[NELEM];
__device__ __nv_bfloat16 g_w[12][(size_t)DDIM * DDIM];   // 6 weights x (hi,lo), [N,K]
__device__ float g_ortho_part[8192];

// ---------------------------------------------------------------------------
// Warp-MMA helpers (baseline PTX: sm_80 features only)
// ---------------------------------------------------------------------------
__device__ __forceinline__ uint32_t smem_u32(const void* p) {
    return (uint32_t)__cvta_generic_to_shared(p);
}

__device__ __forceinline__ void ldsm_x4(uint32_t* r, uint32_t addr) {
    asm volatile("ldmatrix.sync.aligned.m8n8.x4.shared.b16 {%0,%1,%2,%3}, [%4];"
                 : "=r"(r[0]), "=r"(r[1]), "=r"(r[2]), "=r"(r[3]) : "r"(addr));
}

__device__ __forceinline__ void mma16816(float* d, const uint32_t* a, const uint32_t* b) {
    asm volatile(
        "mma.sync.aligned.m16n8k16.row.col.f32.bf16.bf16.f32 "
        "{%0,%1,%2,%3}, {%4,%5,%6,%7}, {%8,%9}, {%0,%1,%2,%3};"
        : "+f"(d[0]), "+f"(d[1]), "+f"(d[2]), "+f"(d[3])
        : "r"(a[0]), "r"(a[1]), "r"(a[2]), "r"(a[3]), "r"(b[0]), "r"(b[1]));
}

#define CP_ASYNC16(dst, src) \
    asm volatile("cp.async.cg.shared.global [%0], [%1], 16;" :: "r"(dst), "l"(src))
#define CP_COMMIT() asm volatile("cp.async.commit_group;" ::: "memory")
#define CP_WAIT2()  asm volatile("cp.async.wait_group 2;" ::: "memory")
#define CP_WAIT1()  asm volatile("cp.async.wait_group 1;" ::: "memory")
#define CP_WAIT0()  asm volatile("cp.async.wait_group 0;" ::: "memory")

// ---------------------------------------------------------------------------
// bf16-split HMMA GEMM: C[M,N] = (Ahi+Alo)[M,K] @ (Bhi+Blo)^T[N,K] + bias
//   3 MMA passes: Ah*Bh + Ah*Bl + Al*Bh, fp32 accumulate.
// Tile 128x128x32, 8 warps (warp tile 64x32), 3-stage cp.async pipeline.
// EPI: 0 = fp32 store, 1 = bf16 hi/lo re-split, 2 = sincos, 3 = +resid
// ---------------------------------------------------------------------------
#define GBM 128
#define GBN 128
#define GBK 32
#define ROWB 80                      // padded SMEM row stride (64B data + 16B pad)
#define TILEB (128 * ROWB)           // 10240 B
#define STAGEB (4 * TILEB)           // Ahi, Alo, Bhi, Blo
#define GSTAGES 3
#define GSMEM (GSTAGES * STAGEB)     // 122880 B

// load one 128x32 bf16 tile into padded SMEM (2 x 16B chunks per thread)
__device__ __forceinline__ void ld_tile(uint32_t sdst, const __nv_bfloat16* g,
                                        int K, int k0, int tid) {
    #pragma unroll
    for (int t = 0; t < 2; ++t) {
        const int c   = tid + t * 256;      // 0..511
        const int row = c >> 2;
        const int cc  = c & 3;
        CP_ASYNC16(sdst + row * ROWB + cc * 16,
                   g + (size_t)row * K + k0 + cc * 8);
    }
}

template <int EPI>
__global__ void __launch_bounds__(256, 1) mma_gemm(
    const __nv_bfloat16* __restrict__ Ahi, const __nv_bfloat16* __restrict__ Alo,
    const __nv_bfloat16* __restrict__ Bhi, const __nv_bfloat16* __restrict__ Blo,
    const float* __restrict__ bias,
    float* __restrict__ o0, float* __restrict__ o1,
    __nv_bfloat16* __restrict__ oh, __nv_bfloat16* __restrict__ ol,
    const float* __restrict__ resid,
    int M, int N, int K)
{
    extern __shared__ __align__(128) char smem[];
    const uint32_t sb = smem_u32(smem);
    const int tid  = threadIdx.x;
    const int wid  = tid >> 5, lane = tid & 31;
    const int wm   = (wid >> 2) * 64;        // warp M offset in tile
    const int wn   = (wid & 3) * 32;         // warp N offset in tile
    const int m0   = blockIdx.y * GBM, n0 = blockIdx.x * GBN;

    const __nv_bfloat16* A0 = Ahi + (size_t)m0 * K;
    const __nv_bfloat16* A1 = Alo + (size_t)m0 * K;
    const __nv_bfloat16* B0 = Bhi + (size_t)n0 * K;
    const __nv_bfloat16* B1 = Blo + (size_t)n0 * K;

    const int KT = K / GBK;                   // 32

    // prologue: stages 0,1
    #pragma unroll
    for (int p = 0; p < 2; ++p) {
        const uint32_t st = sb + p * STAGEB;
        ld_tile(st + 0 * TILEB, A0, K, p * GBK, tid);
        ld_tile(st + 1 * TILEB, A1, K, p * GBK, tid);
        ld_tile(st + 2 * TILEB, B0, K, p * GBK, tid);
        ld_tile(st + 3 * TILEB, B1, K, p * GBK, tid);
        CP_COMMIT();
    }

    float acc[4][4][4];
    #pragma unroll
    for (int i = 0; i < 4; ++i)
        #pragma unroll
        for (int j = 0; j < 4; ++j)
            #pragma unroll
            for (int e = 0; e < 4; ++e) acc[i][j][e] = 0.0f;

    // per-lane ldmatrix address components
    const int aRow = lane & 15;               // A: row within 16
    const int aCol = lane & 16;               // A: +16B for k+8 halves
    const int bRow = (lane & 7) + ((lane & 16) >> 1);   // B: n row within 16
    const int bCol = (lane & 8) * 2;                    // B: +16B for k+8

    for (int kt = 0; kt < KT; ++kt) {
        if (kt + 2 < KT) {
            const uint32_t st = sb + ((kt + 2) % GSTAGES) * STAGEB;
            const int k0 = (kt + 2) * GBK;
            ld_tile(st + 0 * TILEB, A0, K, k0, tid);
            ld_tile(st + 1 * TILEB, A1, K, k0, tid);
            ld_tile(st + 2 * TILEB, B0, K, k0, tid);
            ld_tile(st + 3 * TILEB, B1, K, k0, tid);
            CP_COMMIT();
        }
        if (kt + 2 < KT)      { CP_WAIT2(); }
        else if (kt + 1 < KT) { CP_WAIT1(); }
        else                  { CP_WAIT0(); }
        __syncthreads();

        const uint32_t st  = sb + (kt % GSTAGES) * STAGEB;
        const uint32_t sAh = st + 0 * TILEB;
        const uint32_t sAl = st + 1 * TILEB;
        const uint32_t sBh = st + 2 * TILEB;
        const uint32_t sBl = st + 3 * TILEB;

        #pragma unroll
        for (int h = 0; h < 2; ++h) {         // two k16 halves of GBK=32
            const int kb = h * 32;            // byte offset of k16 half

            uint32_t ah[4][4], al[4][4], bh[2][4], bl[2][4];
            #pragma unroll
            for (int mi = 0; mi < 4; ++mi) {
                const uint32_t off = (uint32_t)(wm + mi * 16 + aRow) * ROWB + kb + aCol;
                ldsm_x4(ah[mi], sAh + off);
                ldsm_x4(al[mi], sAl + off);
            }
            #pragma unroll
            for (int bi = 0; bi < 2; ++bi) {
                const uint32_t off = (uint32_t)(wn + bi * 16 + bRow) * ROWB + kb + bCol;
                ldsm_x4(bh[bi], sBh + off);
                ldsm_x4(bl[bi], sBl + off);
            }

            #pragma unroll
            for (int mi = 0; mi < 4; ++mi) {
                #pragma unroll
                for (int ni = 0; ni < 4; ++ni) {
                    const uint32_t* Bh2 = &bh[ni >> 1][(ni & 1) * 2];
                    const uint32_t* Bl2 = &bl[ni >> 1][(ni & 1) * 2];
                    mma16816(acc[mi][ni], ah[mi], Bh2);
                    mma16816(acc[mi][ni], ah[mi], Bl2);
                    mma16816(acc[mi][ni], al[mi], Bh2);
                }
            }
        }
        __syncthreads();
    }

    // epilogue: direct register -> global (float2 per row-group)
    #pragma unroll
    for (int mi = 0; mi < 4; ++mi) {
        #pragma unroll
        for (int ni = 0; ni < 4; ++ni) {
            const int col = n0 + wn + ni * 8 + (lane & 3) * 2;
            const float2 bv = *(const float2*)(bias + col);
            #pragma unroll
            for (int half = 0; half < 2; ++half) {
                const int row = m0 + wm + mi * 16 + (lane >> 2) + half * 8;
                const size_t off = (size_t)row * N + col;
                float v0 = acc[mi][ni][half * 2 + 0] + bv.x;
                float v1 = acc[mi][ni][half * 2 + 1] + bv.y;
                if (EPI == 0) {
                    *(float2*)(o0 + off) = make_float2(v0, v1);
                } else if (EPI == 1) {
                    __nv_bfloat16 h0 = __float2bfloat16(v0);
                    __nv_bfloat16 h1 = __float2bfloat16(v1);
                    *(__nv_bfloat162*)(oh + off) = __nv_bfloat162(h0, h1);
                    *(__nv_bfloat162*)(ol + off) = __nv_bfloat162(
                        __float2bfloat16(v0 - __bfloat162float(h0)),
                        __float2bfloat16(v1 - __bfloat162float(h1)));
                } else if (EPI == 2) {
                    float s0, c0, s1, c1;
                    sincosf(v0, &s0, &c0);
                    sincosf(v1, &s1, &c1);
                    *(float2*)(o0 + off) = make_float2(c0, c1);
                    *(float2*)(o1 + off) = make_float2(s0, s1);
                } else {
                    const float2 rv = *(const float2*)(resid + off);
                    *(float2*)(o0 + off) = make_float2(v0 + rv.x, v1 + rv.y);
                }
            }
        }
    }
}

// ---------------------------------------------------------------------------
// fp32 -> bf16 hi/lo split (vectorized)
// ---------------------------------------------------------------------------
__global__ __launch_bounds__(256)
void f32_to_hilo(const float* __restrict__ a, __nv_bfloat16* __restrict__ hi,
                 __nv_bfloat16* __restrict__ lo, int n4)
{
    const int i = blockIdx.x * 256 + threadIdx.x;
    if (i >= n4) return;
    const float4 v = ((const float4*)a)[i];
    __nv_bfloat16 h0 = __float2bfloat16(v.x);
    __nv_bfloat16 h1 = __float2bfloat16(v.y);
    __nv_bfloat16 h2 = __float2bfloat16(v.z);
    __nv_bfloat16 h3 = __float2bfloat16(v.w);
    __nv_bfloat162* H = (__nv_bfloat162*)hi;
    __nv_bfloat162* L = (__nv_bfloat162*)lo;
    H[2 * i]     = __nv_bfloat162(h0, h1);
    H[2 * i + 1] = __nv_bfloat162(h2, h3);
    L[2 * i]     = __nv_bfloat162(__float2bfloat16(v.x - __bfloat162float(h0)),
                                  __float2bfloat16(v.y - __bfloat162float(h1)));
    L[2 * i + 1] = __nv_bfloat162(__float2bfloat16(v.z - __bfloat162float(h2)),
                                  __float2bfloat16(v.w - __bfloat162float(h3)));
}

// Weight convert + transpose: W[K,N] fp32 -> th/tl[N,K] bf16
__global__ __launch_bounds__(1024)
void wtrans_hilo(const float* __restrict__ W, __nv_bfloat16* __restrict__ th,
                 __nv_bfloat16* __restrict__ tl, int Kd, int Nd)
{
    __shared__ float t[32][33];
    const int tx = threadIdx.x, ty = threadIdx.y;
    const int k0 = blockIdx.y * 32, n0 = blockIdx.x * 32;
    t[ty][tx] = W[(size_t)(k0 + ty) * Nd + n0 + tx];
    __syncthreads();
    const float v = t[tx][ty];                 // = W[k0+tx][n0+ty]
    const size_t o = (size_t)(n0 + ty) * Kd + k0 + tx;
    __nv_bfloat16 h = __float2bfloat16(v);
    th[o] = h;
    tl[o] = __float2bfloat16(v - __bfloat162float(h));
}

// ---------------------------------------------------------------------------
// Fused chunked cumsum + retrieve
// ---------------------------------------------------------------------------
__global__ __launch_bounds__(256)
void cumsum_retrieve(const float* __restrict__ value,
                     const float* __restrict__ kc, const float* __restrict__ ks,
                     const float* __restrict__ qc, const float* __restrict__ qs,
                     float* __restrict__ ret,
                     int Bb, int S, int D,
                     const int* __restrict__ cs_ptr, float inv_sqrt_S)
{
    const int cs = cs_ptr[0];
    const int nc = (S + cs - 1) / cs;
    const int total = Bb * nc;
    const int d = blockIdx.y * blockDim.x + threadIdx.x;
    if (d >= D) return;

    for (int t = blockIdx.x; t < total; t += gridDim.x) {
        const int b = t / nc;
        const int c = t % nc;
        const int s0 = c * cs;
        const int smax = min(cs, S - s0);
        size_t off = ((size_t)b * S + s0) * D + d;
        float r = 0.0f, im = 0.0f;
        for (int s = 0; s < smax; ++s, off += D) {
            const float v = value[off];
            r  = fmaf(v, kc[off], r);
            im = fmaf(v, ks[off], im);
            ret[off] = (r * qc[off] + im * qs[off]) * inv_sqrt_S;
        }
    }
}

// ---------------------------------------------------------------------------
// LayerNorm -> bf16 hi/lo outputs (for final GEMM)
// ---------------------------------------------------------------------------
__global__ __launch_bounds__(256)
void layernorm_hilo(const float* __restrict__ ret,
                    const float* __restrict__ gamma,
                    const float* __restrict__ beta,
                    __nv_bfloat16* __restrict__ oh, __nv_bfloat16* __restrict__ ol,
                    int D)
{
    const float* p = ret + (size_t)blockIdx.x * D;
    const int tid = threadIdx.x;
    const int per = D / 256;   // 4

    float vals[8];
    float sum = 0.0f, sq = 0.0f;
    for (int i = 0; i < per; ++i) {
        float v = p[tid + i * 256];
        vals[i] = v;
        sum += v;
        sq  += v * v;
    }

    __shared__ float s1[32], s2[32];
    const int lane = tid & 31, w = tid >> 5;
    #pragma unroll
    for (int o = 16; o; o >>= 1) {
        sum += __shfl_down_sync(0xffffffffu, sum, o);
        sq  += __shfl_down_sync(0xffffffffu, sq,  o);
    }
    if (lane == 0) { s1[w] = sum; s2[w] = sq; }
    __syncthreads();
    if (w == 0) {
        sum = (lane < 8) ? s1[lane] : 0.0f;
        sq  = (lane < 8) ? s2[lane] : 0.0f;
        #pragma unroll
        for (int o = 4; o; o >>= 1) {
            sum += __shfl_down_sync(0xffffffffu, sum, o);
            sq  += __shfl_down_sync(0xffffffffu, sq,  o);
        }
        if (lane == 0) {
            const float mean = sum / (float)D;
            const float var  = sq / (float)D - mean * mean;
            s1[0] = mean;
            s2[0] = rsqrtf(var + 1e-5f);
        }
    }
    __syncthreads();
    const float mean = s1[0], rstd = s2[0];
    const size_t base = (size_t)blockIdx.x * D;
    for (int i = 0; i < per; ++i) {
        const int c = tid + i * 256;
        const float v = (vals[i] - mean) * rstd * gamma[c] + beta[c];
        __nv_bfloat16 h = __float2bfloat16(v);
        oh[base + c] = h;
        ol[base + c] = __float2bfloat16(v - __bfloat162float(h));
    }
}

// ---------------------------------------------------------------------------
// Ortho loss
// ---------------------------------------------------------------------------
__global__ __launch_bounds__(256)
void ortho_partial(const float* __restrict__ kc, const float* __restrict__ ks,
                   const int* __restrict__ idx, int S, int D, int n)
{
    const int t = blockIdx.x;
    const int j = t % n;
    const int i = (t / n) % n;
    const int b = t / (n * n);

    if (i == j) {
        if (threadIdx.x == 0) g_ortho_part[t] = 0.0f;
        return;
    }
    const int si = idx[i], sj = idx[j];
    const float* ci = kc + ((size_t)b * S + si) * D;
    const float* cj = kc + ((size_t)b * S + sj) * D;
    const float* ni = ks + ((size_t)b * S + si) * D;
    const float* nj = ks + ((size_t)b * S + sj) * D;

    float acc = 0.0f;
    for (int d = threadIdx.x; d < D; d += blockDim.x) {
        const float v = ci[d] * cj[d] + ni[d] * nj[d];
        acc = fmaf(v, v, acc);
    }

    __shared__ float sh[32];
    const int lane = threadIdx.x & 31, w = threadIdx.x >> 5;
    #pragma unroll
    for (int o = 16; o; o >>= 1) acc += __shfl_down_sync(0xffffffffu, acc, o);
    if (lane == 0) sh[w] = acc;
    __syncthreads();
    if (w == 0) {
        acc = (lane < 8) ? sh[lane] : 0.0f;
        #pragma unroll
        for (int o = 4; o; o >>= 1) acc += __shfl_down_sync(0xffffffffu, acc, o);
        if (lane == 0) g_ortho_part[t] = acc;
    }
}

__global__ __launch_bounds__(256)
void ortho_reduce(float* __restrict__ out_loc, int total, float denom)
{
    float acc = 0.0f;
    for (int t = threadIdx.x; t < total; t += 256) acc += g_ortho_part[t];

    __shared__ float sh[32];
    const int lane = threadIdx.x & 31, w = threadIdx.x >> 5;
    #pragma unroll
    for (int o = 16; o; o >>= 1) acc += __shfl_down_sync(0xffffffffu, acc, o);
    if (lane == 0) sh[w] = acc;
    __syncthreads();
    if (w == 0) {
        acc = (lane < 8) ? sh[lane] : 0.0f;
        #pragma unroll
        for (int o = 4; o; o >>= 1) acc += __shfl_down_sync(0xffffffffu, acc, o);
        if (lane == 0) *out_loc = acc / denom;
    }
}

// ---------------------------------------------------------------------------
// Launcher
// ---------------------------------------------------------------------------
extern "C" void kernel_launch(void* const* d_in, const int* in_sizes, int n_in,
                              void* d_out, int out_size)
{
    const float* x    = (const float*)d_in[0];
    const float* Wk   = (const float*)d_in[1];
    const float* bk   = (const float*)d_in[2];
    const float* Wv   = (const float*)d_in[3];
    const float* bv   = (const float*)d_in[4];
    const float* Wq   = (const float*)d_in[5];
    const float* bq   = (const float*)d_in[6];
    const float* Wkp  = (const float*)d_in[7];
    const float* bkp  = (const float*)d_in[8];
    const float* Wqp  = (const float*)d_in[9];
    const float* bqp  = (const float*)d_in[10];
    const float* ln_g = (const float*)d_in[11];
    const float* ln_b = (const float*)d_in[12];
    const float* Wo   = (const float*)d_in[13];
    const float* bo   = (const float*)d_in[14];
    const int*   idx  = (const int*)d_in[15];
    const int*   csp  = (const int*)d_in[16];

    const int D  = in_sizes[2];        // 1024
    const int M  = in_sizes[0] / D;    // 16384
    const int Bb = 4;
    const int S  = M / Bb;             // 4096
    const int n  = in_sizes[15];       // 32

    float *val, *kc, *ks, *qc, *qs, *ret;
    __nv_bfloat16 *xhi, *xlo, *khi, *klo, *qhi, *qlo, *wbase;
    cudaGetSymbolAddress((void**)&val, g_val);
    cudaGetSymbolAddress((void**)&kc,  g_kc);
    cudaGetSymbolAddress((void**)&ks,  g_ks);
    cudaGetSymbolAddress((void**)&qc,  g_qc);
    cudaGetSymbolAddress((void**)&qs,  g_qs);
    cudaGetSymbolAddress((void**)&ret, g_ret);
    cudaGetSymbolAddress((void**)&xhi, g_xhi);
    cudaGetSymbolAddress((void**)&xlo, g_xlo);
    cudaGetSymbolAddress((void**)&khi, g_khi);
    cudaGetSymbolAddress((void**)&klo, g_klo);
    cudaGetSymbolAddress((void**)&qhi, g_qhi);
    cudaGetSymbolAddress((void**)&qlo, g_qlo);
    cudaGetSymbolAddress((void**)&wbase, g_w);
    const size_t WSZ = (size_t)D * D;
    #define WSLOT(i) (wbase + (size_t)(i) * WSZ)

    float* out = (float*)d_out;

    cudaFuncSetAttribute(mma_gemm<0>, cudaFuncAttributeMaxDynamicSharedMemorySize, GSMEM);
    cudaFuncSetAttribute(mma_gemm<1>, cudaFuncAttributeMaxDynamicSharedMemorySize, GSMEM);
    cudaFuncSetAttribute(mma_gemm<2>, cudaFuncAttributeMaxDynamicSharedMemorySize, GSMEM);
    cudaFuncSetAttribute(mma_gemm<3>, cudaFuncAttributeMaxDynamicSharedMemorySize, GSMEM);

    // weight conversion + transpose
    const dim3 wb(32, 32), wg(D / 32, D / 32);
    wtrans_hilo<<<wg, wb>>>(Wk,  WSLOT(0),  WSLOT(1),  D, D);
    wtrans_hilo<<<wg, wb>>>(Wv,  WSLOT(2),  WSLOT(3),  D, D);
    wtrans_hilo<<<wg, wb>>>(Wq,  WSLOT(4),  WSLOT(5),  D, D);
    wtrans_hilo<<<wg, wb>>>(Wkp, WSLOT(6),  WSLOT(7),  D, D);
    wtrans_hilo<<<wg, wb>>>(Wqp, WSLOT(8),  WSLOT(9),  D, D);
    wtrans_hilo<<<wg, wb>>>(Wo,  WSLOT(10), WSLOT(11), D, D);

    // x -> hi/lo
    const int n4 = (int)(NELEM / 4);
    f32_to_hilo<<<(n4 + 255) / 256, 256>>>(x, xhi, xlo, n4);

    const dim3 gg(D / GBN, M / GBM);

    // key / value / query projections
    mma_gemm<1><<<gg, 256, GSMEM>>>(xhi, xlo, WSLOT(0), WSLOT(1), bk,
                                    nullptr, nullptr, khi, klo, nullptr, M, D, D);
    mma_gemm<0><<<gg, 256, GSMEM>>>(xhi, xlo, WSLOT(2), WSLOT(3), bv,
                                    val, nullptr, nullptr, nullptr, nullptr, M, D, D);
    mma_gemm<1><<<gg, 256, GSMEM>>>(xhi, xlo, WSLOT(4), WSLOT(5), bq,
                                    nullptr, nullptr, qhi, qlo, nullptr, M, D, D);

    // phase projections with fused cos/sin
    mma_gemm<2><<<gg, 256, GSMEM>>>(khi, klo, WSLOT(6), WSLOT(7), bkp,
                                    kc, ks, nullptr, nullptr, nullptr, M, D, D);
    mma_gemm<2><<<gg, 256, GSMEM>>>(qhi, qlo, WSLOT(8), WSLOT(9), bqp,
                                    qc, qs, nullptr, nullptr, nullptr, M, D, D);

    // chunked complex cumsum + retrieve
    const float inv_sqrt_S = 1.0f / sqrtf((float)S);
    cumsum_retrieve<<<dim3(256, D / 256), 256>>>(val, kc, ks, qc, qs, ret,
                                                 Bb, S, D, csp, inv_sqrt_S);

    // layernorm -> bf16 hi/lo (reuse khi/klo, dead after phase GEMM)
    layernorm_hilo<<<M, 256>>>(ret, ln_g, ln_b, khi, klo, D);

    // output projection + residual, straight into d_out
    mma_gemm<3><<<gg, 256, GSMEM>>>(khi, klo, WSLOT(10), WSLOT(11), bo,
                                    out, nullptr, nullptr, nullptr, x, M, D, D);

    // ortho loss -> last output element
    ortho_partial<<<Bb * n * n, 256>>>(kc, ks, idx, S, D, n);
    const float denom = (float)(n * (n - 1)) * (float)D + 1e-6f;
    ortho_reduce<<<1, 256>>>(out + (out_size - 1), Bb * n * n, denom);
}

// round 4
// speedup vs baseline: 3.8505x; 1.6529x over previous
#include <cuda_runtime.h>
#include <cuda_fp16.h>
#include <math.h>
#include <cstdint>

// ---------------------------------------------------------------------------
// Problem constants (B=4, S=4096, D=1024)
// ---------------------------------------------------------------------------
#define MM    16384
#define DDIM  1024
#define NELEM ((size_t)MM * DDIM)

#define WSCALE     64.0f
#define INV_WSCALE (1.0f / 64.0f)

__device__ float g_val[NELEM];
__device__ float g_kc [NELEM];
__device__ float g_ks [NELEM];
__device__ float g_qc [NELEM];
__device__ float g_qs [NELEM];
__device__ float g_ret[NELEM];
__device__ __half g_xh[NELEM];
__device__ __half g_kh[NELEM];
__device__ __half g_qh[NELEM];
__device__ __half g_w[12][(size_t)DDIM * DDIM];   // 6 weights x (hi,lo), [N,K], pre-scaled x64
__device__ float g_ortho_part[8192];

// ---------------------------------------------------------------------------
// Warp-MMA helpers (baseline PTX: sm_80 features only)
// ---------------------------------------------------------------------------
__device__ __forceinline__ uint32_t smem_u32(const void* p) {
    return (uint32_t)__cvta_generic_to_shared(p);
}

__device__ __forceinline__ void ldsm_x4(uint32_t* r, uint32_t addr) {
    asm volatile("ldmatrix.sync.aligned.m8n8.x4.shared.b16 {%0,%1,%2,%3}, [%4];"
                 : "=r"(r[0]), "=r"(r[1]), "=r"(r[2]), "=r"(r[3]) : "r"(addr));
}

__device__ __forceinline__ void mma16816(float* d, const uint32_t* a, const uint32_t* b) {
    asm volatile(
        "mma.sync.aligned.m16n8k16.row.col.f32.f16.f16.f32 "
        "{%0,%1,%2,%3}, {%4,%5,%6,%7}, {%8,%9}, {%0,%1,%2,%3};"
        : "+f"(d[0]), "+f"(d[1]), "+f"(d[2]), "+f"(d[3])
        : "r"(a[0]), "r"(a[1]), "r"(a[2]), "r"(a[3]), "r"(b[0]), "r"(b[1]));
}

#define CP_ASYNC16(dst, src) \
    asm volatile("cp.async.cg.shared.global [%0], [%1], 16;" :: "r"(dst), "l"(src))
#define CP_COMMIT() asm volatile("cp.async.commit_group;" ::: "memory")
#define CP_WAIT2()  asm volatile("cp.async.wait_group 2;" ::: "memory")
#define CP_WAIT1()  asm volatile("cp.async.wait_group 1;" ::: "memory")
#define CP_WAIT0()  asm volatile("cp.async.wait_group 0;" ::: "memory")

// ---------------------------------------------------------------------------
// fp16 2-pass GEMM: C[M,N] = (1/64) * A[M,K] @ (Wh+Wl)^T[N,K] + bias
// Tile 128x128x32, 8 warps (warp tile 64x32), 3-stage cp.async, 2 CTAs/SM.
// EPI: 0 = fp32 store, 1 = fp16 store, 2 = sincos, 3 = +resid
// ---------------------------------------------------------------------------
#define GBM 128
#define GBN 128
#define GBK 32
#define ROWB 80                      // padded SMEM row stride (64B data + 16B pad)
#define TILEB (128 * ROWB)           // 10240 B
#define STAGEB (3 * TILEB)           // A, Wh, Wl
#define GSTAGES 3
#define GSMEM (GSTAGES * STAGEB)     // 92160 B

// load one 128x32 fp16 tile into padded SMEM (2 x 16B chunks per thread)
__device__ __forceinline__ void ld_tile(uint32_t sdst, const __half* g,
                                        int K, int k0, int tid) {
    #pragma unroll
    for (int t = 0; t < 2; ++t) {
        const int c   = tid + t * 256;      // 0..511
        const int row = c >> 2;
        const int cc  = c & 3;
        CP_ASYNC16(sdst + row * ROWB + cc * 16,
                   g + (size_t)row * K + k0 + cc * 8);
    }
}

template <int EPI>
__global__ void __launch_bounds__(256, 2) mma_gemm(
    const __half* __restrict__ A,
    const __half* __restrict__ Wh, const __half* __restrict__ Wl,
    const float* __restrict__ bias,
    float* __restrict__ o0, float* __restrict__ o1,
    __half* __restrict__ oh,
    const float* __restrict__ resid,
    int M, int N, int K)
{
    extern __shared__ __align__(128) char smem[];
    const uint32_t sb = smem_u32(smem);
    const int tid  = threadIdx.x;
    const int wid  = tid >> 5, lane = tid & 31;
    const int wm   = (wid >> 2) * 64;        // warp M offset in tile
    const int wn   = (wid & 3) * 32;         // warp N offset in tile
    const int m0   = blockIdx.y * GBM, n0 = blockIdx.x * GBN;

    const __half* A0 = A  + (size_t)m0 * K;
    const __half* B0 = Wh + (size_t)n0 * K;
    const __half* B1 = Wl + (size_t)n0 * K;

    const int KT = K / GBK;                   // 32

    // prologue: stages 0,1
    #pragma unroll
    for (int p = 0; p < 2; ++p) {
        const uint32_t st = sb + p * STAGEB;
        ld_tile(st + 0 * TILEB, A0, K, p * GBK, tid);
        ld_tile(st + 1 * TILEB, B0, K, p * GBK, tid);
        ld_tile(st + 2 * TILEB, B1, K, p * GBK, tid);
        CP_COMMIT();
    }

    float acc[4][4][4];
    #pragma unroll
    for (int i = 0; i < 4; ++i)
        #pragma unroll
        for (int j = 0; j < 4; ++j)
            #pragma unroll
            for (int e = 0; e < 4; ++e) acc[i][j][e] = 0.0f;

    // per-lane ldmatrix address components
    const int aRow = lane & 15;               // A: row within 16
    const int aCol = lane & 16;               // A: +16B for k+8 halves
    const int bRow = (lane & 7) + ((lane & 16) >> 1);   // B: n row within 16
    const int bCol = (lane & 8) * 2;                    // B: +16B for k+8

    for (int kt = 0; kt < KT; ++kt) {
        if (kt + 2 < KT) {
            const uint32_t st = sb + ((kt + 2) % GSTAGES) * STAGEB;
            const int k0 = (kt + 2) * GBK;
            ld_tile(st + 0 * TILEB, A0, K, k0, tid);
            ld_tile(st + 1 * TILEB, B0, K, k0, tid);
            ld_tile(st + 2 * TILEB, B1, K, k0, tid);
            CP_COMMIT();
        }
        if (kt + 2 < KT)      { CP_WAIT2(); }
        else if (kt + 1 < KT) { CP_WAIT1(); }
        else                  { CP_WAIT0(); }
        __syncthreads();

        const uint32_t st  = sb + (kt % GSTAGES) * STAGEB;
        const uint32_t sA  = st + 0 * TILEB;
        const uint32_t sBh = st + 1 * TILEB;
        const uint32_t sBl = st + 2 * TILEB;

        #pragma unroll
        for (int h = 0; h < 2; ++h) {         // two k16 halves of GBK=32
            const int kb = h * 32;            // byte offset of k16 half

            uint32_t a[4][4], bh[2][4], bl[2][4];
            #pragma unroll
            for (int mi = 0; mi < 4; ++mi) {
                const uint32_t off = (uint32_t)(wm + mi * 16 + aRow) * ROWB + kb + aCol;
                ldsm_x4(a[mi], sA + off);
            }
            #pragma unroll
            for (int bi = 0; bi < 2; ++bi) {
                const uint32_t off = (uint32_t)(wn + bi * 16 + bRow) * ROWB + kb + bCol;
                ldsm_x4(bh[bi], sBh + off);
                ldsm_x4(bl[bi], sBl + off);
            }

            #pragma unroll
            for (int mi = 0; mi < 4; ++mi) {
                #pragma unroll
                for (int ni = 0; ni < 4; ++ni) {
                    const uint32_t* Bh2 = &bh[ni >> 1][(ni & 1) * 2];
                    const uint32_t* Bl2 = &bl[ni >> 1][(ni & 1) * 2];
                    mma16816(acc[mi][ni], a[mi], Bh2);
                    mma16816(acc[mi][ni], a[mi], Bl2);
                }
            }
        }
        __syncthreads();
    }

    // epilogue: direct register -> global (float2/half2 per row-group)
    #pragma unroll
    for (int mi = 0; mi < 4; ++mi) {
        #pragma unroll
        for (int ni = 0; ni < 4; ++ni) {
            const int col = n0 + wn + ni * 8 + (lane & 3) * 2;
            const float2 bv = *(const float2*)(bias + col);
            #pragma unroll
            for (int half_ = 0; half_ < 2; ++half_) {
                const int row = m0 + wm + mi * 16 + (lane >> 2) + half_ * 8;
                const size_t off = (size_t)row * N + col;
                float v0 = acc[mi][ni][half_ * 2 + 0] * INV_WSCALE + bv.x;
                float v1 = acc[mi][ni][half_ * 2 + 1] * INV_WSCALE + bv.y;
                if (EPI == 0) {
                    *(float2*)(o0 + off) = make_float2(v0, v1);
                } else if (EPI == 1) {
                    *(__half2*)(oh + off) = __floats2half2_rn(v0, v1);
                } else if (EPI == 2) {
                    float s0, c0, s1, c1;
                    __sincosf(v0, &s0, &c0);
                    __sincosf(v1, &s1, &c1);
                    *(float2*)(o0 + off) = make_float2(c0, c1);
                    *(float2*)(o1 + off) = make_float2(s0, s1);
                } else {
                    const float2 rv = *(const float2*)(resid + off);
                    *(float2*)(o0 + off) = make_float2(v0 + rv.x, v1 + rv.y);
                }
            }
        }
    }
}

// ---------------------------------------------------------------------------
// fp32 -> fp16 (vectorized)
// ---------------------------------------------------------------------------
__global__ __launch_bounds__(256)
void f32_to_f16(const float* __restrict__ a, __half* __restrict__ h, int n4)
{
    const int i = blockIdx.x * 256 + threadIdx.x;
    if (i >= n4) return;
    const float4 v = ((const float4*)a)[i];
    __half2* H = (__half2*)h;
    H[2 * i]     = __floats2half2_rn(v.x, v.y);
    H[2 * i + 1] = __floats2half2_rn(v.z, v.w);
}

// Weight convert + transpose + scale: W[K,N] fp32 -> (64W) hi/lo [N,K] fp16
__global__ __launch_bounds__(1024)
void wtrans_f16(const float* __restrict__ W, __half* __restrict__ th,
                __half* __restrict__ tl, int Kd, int Nd)
{
    __shared__ float t[32][33];
    const int tx = threadIdx.x, ty = threadIdx.y;
    const int k0 = blockIdx.y * 32, n0 = blockIdx.x * 32;
    t[ty][tx] = W[(size_t)(k0 + ty) * Nd + n0 + tx];
    __syncthreads();
    const float v = t[tx][ty] * WSCALE;        // = 64 * W[k0+tx][n0+ty]
    const size_t o = (size_t)(n0 + ty) * Kd + k0 + tx;
    __half h = __float2half(v);
    th[o] = h;
    tl[o] = __float2half(v - __half2float(h));
}

// ---------------------------------------------------------------------------
// Fused chunked cumsum + retrieve
// ---------------------------------------------------------------------------
__global__ __launch_bounds__(256)
void cumsum_retrieve(const float* __restrict__ value,
                     const float* __restrict__ kc, const float* __restrict__ ks,
                     const float* __restrict__ qc, const float* __restrict__ qs,
                     float* __restrict__ ret,
                     int Bb, int S, int D,
                     const int* __restrict__ cs_ptr, float inv_sqrt_S)
{
    const int cs = cs_ptr[0];
    const int nc = (S + cs - 1) / cs;
    const int total = Bb * nc;
    const int d = blockIdx.y * blockDim.x + threadIdx.x;
    if (d >= D) return;

    for (int t = blockIdx.x; t < total; t += gridDim.x) {
        const int b = t / nc;
        const int c = t % nc;
        const int s0 = c * cs;
        const int smax = min(cs, S - s0);
        size_t off = ((size_t)b * S + s0) * D + d;
        float r = 0.0f, im = 0.0f;
        for (int s = 0; s < smax; ++s, off += D) {
            const float v = value[off];
            r  = fmaf(v, kc[off], r);
            im = fmaf(v, ks[off], im);
            ret[off] = (r * qc[off] + im * qs[off]) * inv_sqrt_S;
        }
    }
}

// ---------------------------------------------------------------------------
// LayerNorm -> fp16 output (for final GEMM)
// ---------------------------------------------------------------------------
__global__ __launch_bounds__(256)
void layernorm_f16(const float* __restrict__ ret,
                   const float* __restrict__ gamma,
                   const float* __restrict__ beta,
                   __half* __restrict__ oh, int D)
{
    const float* p = ret + (size_t)blockIdx.x * D;
    const int tid = threadIdx.x;
    const int per = D / 256;   // 4

    float vals[8];
    float sum = 0.0f, sq = 0.0f;
    for (int i = 0; i < per; ++i) {
        float v = p[tid + i * 256];
        vals[i] = v;
        sum += v;
        sq  += v * v;
    }

    __shared__ float s1[32], s2[32];
    const int lane = tid & 31, w = tid >> 5;
    #pragma unroll
    for (int o = 16; o; o >>= 1) {
        sum += __shfl_down_sync(0xffffffffu, sum, o);
        sq  += __shfl_down_sync(0xffffffffu, sq,  o);
    }
    if (lane == 0) { s1[w] = sum; s2[w] = sq; }
    __syncthreads();
    if (w == 0) {
        sum = (lane < 8) ? s1[lane] : 0.0f;
        sq  = (lane < 8) ? s2[lane] : 0.0f;
        #pragma unroll
        for (int o = 4; o; o >>= 1) {
            sum += __shfl_down_sync(0xffffffffu, sum, o);
            sq  += __shfl_down_sync(0xffffffffu, sq,  o);
        }
        if (lane == 0) {
            const float mean = sum / (float)D;
            const float var  = sq / (float)D - mean * mean;
            s1[0] = mean;
            s2[0] = rsqrtf(var + 1e-5f);
        }
    }
    __syncthreads();
    const float mean = s1[0], rstd = s2[0];
    const size_t base = (size_t)blockIdx.x * D;
    for (int i = 0; i < per; ++i) {
        const int c = tid + i * 256;
        const float v = (vals[i] - mean) * rstd * gamma[c] + beta[c];
        oh[base + c] = __float2half(v);
    }
}

// ---------------------------------------------------------------------------
// Ortho loss
// ---------------------------------------------------------------------------
__global__ __launch_bounds__(256)
void ortho_partial(const float* __restrict__ kc, const float* __restrict__ ks,
                   const int* __restrict__ idx, int S, int D, int n)
{
    const int t = blockIdx.x;
    const int j = t % n;
    const int i = (t / n) % n;
    const int b = t / (n * n);

    if (i == j) {
        if (threadIdx.x == 0) g_ortho_part[t] = 0.0f;
        return;
    }
    const int si = idx[i], sj = idx[j];
    const float* ci = kc + ((size_t)b * S + si) * D;
    const float* cj = kc + ((size_t)b * S + sj) * D;
    const float* ni = ks + ((size_t)b * S + si) * D;
    const float* nj = ks + ((size_t)b * S + sj) * D;

    float acc = 0.0f;
    for (int d = threadIdx.x; d < D; d += blockDim.x) {
        const float v = ci[d] * cj[d] + ni[d] * nj[d];
        acc = fmaf(v, v, acc);
    }

    __shared__ float sh[32];
    const int lane = threadIdx.x & 31, w = threadIdx.x >> 5;
    #pragma unroll
    for (int o = 16; o; o >>= 1) acc += __shfl_down_sync(0xffffffffu, acc, o);
    if (lane == 0) sh[w] = acc;
    __syncthreads();
    if (w == 0) {
        acc = (lane < 8) ? sh[lane] : 0.0f;
        #pragma unroll
        for (int o = 4; o; o >>= 1) acc += __shfl_down_sync(0xffffffffu, acc, o);
        if (lane == 0) g_ortho_part[t] = acc;
    }
}

__global__ __launch_bounds__(256)
void ortho_reduce(float* __restrict__ out_loc, int total, float denom)
{
    float acc = 0.0f;
    for (int t = threadIdx.x; t < total; t += 256) acc += g_ortho_part[t];

    __shared__ float sh[32];
    const int lane = threadIdx.x & 31, w = threadIdx.x >> 5;
    #pragma unroll
    for (int o = 16; o; o >>= 1) acc += __shfl_down_sync(0xffffffffu, acc, o);
    if (lane == 0) sh[w] = acc;
    __syncthreads();
    if (w == 0) {
        acc = (lane < 8) ? sh[lane] : 0.0f;
        #pragma unroll
        for (int o = 4; o; o >>= 1) acc += __shfl_down_sync(0xffffffffu, acc, o);
        if (lane == 0) *out_loc = acc / denom;
    }
}

// ---------------------------------------------------------------------------
// Launcher
// ---------------------------------------------------------------------------
extern "C" void kernel_launch(void* const* d_in, const int* in_sizes, int n_in,
                              void* d_out, int out_size)
{
    const float* x    = (const float*)d_in[0];
    const float* Wk   = (const float*)d_in[1];
    const float* bk   = (const float*)d_in[2];
    const float* Wv   = (const float*)d_in[3];
    const float* bv   = (const float*)d_in[4];
    const float* Wq   = (const float*)d_in[5];
    const float* bq   = (const float*)d_in[6];
    const float* Wkp  = (const float*)d_in[7];
    const float* bkp  = (const float*)d_in[8];
    const float* Wqp  = (const float*)d_in[9];
    const float* bqp  = (const float*)d_in[10];
    const float* ln_g = (const float*)d_in[11];
    const float* ln_b = (const float*)d_in[12];
    const float* Wo   = (const float*)d_in[13];
    const float* bo   = (const float*)d_in[14];
    const int*   idx  = (const int*)d_in[15];
    const int*   csp  = (const int*)d_in[16];

    const int D  = in_sizes[2];        // 1024
    const int M  = in_sizes[0] / D;    // 16384
    const int Bb = 4;
    const int S  = M / Bb;             // 4096
    const int n  = in_sizes[15];       // 32

    float *val, *kc, *ks, *qc, *qs, *ret;
    __half *xh, *kh, *qh, *wbase;
    cudaGetSymbolAddress((void**)&val, g_val);
    cudaGetSymbolAddress((void**)&kc,  g_kc);
    cudaGetSymbolAddress((void**)&ks,  g_ks);
    cudaGetSymbolAddress((void**)&qc,  g_qc);
    cudaGetSymbolAddress((void**)&qs,  g_qs);
    cudaGetSymbolAddress((void**)&ret, g_ret);
    cudaGetSymbolAddress((void**)&xh,  g_xh);
    cudaGetSymbolAddress((void**)&kh,  g_kh);
    cudaGetSymbolAddress((void**)&qh,  g_qh);
    cudaGetSymbolAddress((void**)&wbase, g_w);
    const size_t WSZ = (size_t)D * D;
    #define WSLOT(i) (wbase + (size_t)(i) * WSZ)

    float* out = (float*)d_out;

    cudaFuncSetAttribute(mma_gemm<0>, cudaFuncAttributeMaxDynamicSharedMemorySize, GSMEM);
    cudaFuncSetAttribute(mma_gemm<1>, cudaFuncAttributeMaxDynamicSharedMemorySize, GSMEM);
    cudaFuncSetAttribute(mma_gemm<2>, cudaFuncAttributeMaxDynamicSharedMemorySize, GSMEM);
    cudaFuncSetAttribute(mma_gemm<3>, cudaFuncAttributeMaxDynamicSharedMemorySize, GSMEM);

    // weight conversion + transpose + x64 scale
    const dim3 wb(32, 32), wg(D / 32, D / 32);
    wtrans_f16<<<wg, wb>>>(Wk,  WSLOT(0),  WSLOT(1),  D, D);
    wtrans_f16<<<wg, wb>>>(Wv,  WSLOT(2),  WSLOT(3),  D, D);
    wtrans_f16<<<wg, wb>>>(Wq,  WSLOT(4),  WSLOT(5),  D, D);
    wtrans_f16<<<wg, wb>>>(Wkp, WSLOT(6),  WSLOT(7),  D, D);
    wtrans_f16<<<wg, wb>>>(Wqp, WSLOT(8),  WSLOT(9),  D, D);
    wtrans_f16<<<wg, wb>>>(Wo,  WSLOT(10), WSLOT(11), D, D);

    // x -> fp16
    const int n4 = (int)(NELEM / 4);
    f32_to_f16<<<(n4 + 255) / 256, 256>>>(x, xh, n4);

    const dim3 gg(D / GBN, M / GBM);

    // key / value / query projections
    mma_gemm<1><<<gg, 256, GSMEM>>>(xh, WSLOT(0), WSLOT(1), bk,
                                    nullptr, nullptr, kh, nullptr, M, D, D);
    mma_gemm<0><<<gg, 256, GSMEM>>>(xh, WSLOT(2), WSLOT(3), bv,
                                    val, nullptr, nullptr, nullptr, M, D, D);
    mma_gemm<1><<<gg, 256, GSMEM>>>(xh, WSLOT(4), WSLOT(5), bq,
                                    nullptr, nullptr, qh, nullptr, M, D, D);

    // phase projections with fused cos/sin
    mma_gemm<2><<<gg, 256, GSMEM>>>(kh, WSLOT(6), WSLOT(7), bkp,
                                    kc, ks, nullptr, nullptr, M, D, D);
    mma_gemm<2><<<gg, 256, GSMEM>>>(qh, WSLOT(8), WSLOT(9), bqp,
                                    qc, qs, nullptr, nullptr, M, D, D);

    // chunked complex cumsum + retrieve
    const float inv_sqrt_S = 1.0f / sqrtf((float)S);
    cumsum_retrieve<<<dim3(256, D / 256), 256>>>(val, kc, ks, qc, qs, ret,
                                                 Bb, S, D, csp, inv_sqrt_S);

    // layernorm -> fp16 (reuse kh, dead after phase GEMM)
    layernorm_f16<<<M, 256>>>(ret, ln_g, ln_b, kh, D);

    // output projection + residual, straight into d_out
    mma_gemm<3><<<gg, 256, GSMEM>>>(kh, WSLOT(10), WSLOT(11), bo,
                                    out, nullptr, nullptr, x, M, D, D);

    // ortho loss -> last output element
    ortho_partial<<<Bb * n * n, 256>>>(kc, ks, idx, S, D, n);
    const float denom = (float)(n * (n - 1)) * (float)D + 1e-6f;
    ortho_reduce<<<1, 256>>>(out + (out_size - 1), Bb * n * n, denom);
}

// round 5
// speedup vs baseline: 4.1075x; 1.0667x over previous
#include <cuda_runtime.h>
#include <cuda_fp16.h>
#include <math.h>
#include <cstdint>

// ---------------------------------------------------------------------------
// Problem constants (B=4, S=4096, D=1024)
// ---------------------------------------------------------------------------
#define MM    16384
#define DDIM  1024
#define NELEM ((size_t)MM * DDIM)

#define WSCALE     64.0f
#define INV_WSCALE (1.0f / 64.0f)

__device__ float g_val[NELEM];
__device__ float g_kc [NELEM];
__device__ float g_ks [NELEM];
__device__ float g_qc [NELEM];
__device__ float g_qs [NELEM];
__device__ float g_ret[NELEM];
__device__ __half g_xh[NELEM];
__device__ __half g_kh[NELEM];
__device__ __half g_qh[NELEM];
// weight pool: [0..3M) QKV_hi (rows: Wk,Wv,Wq), [3M..6M) QKV_lo,
//              slots 6..11: Wkp hi/lo, Wqp hi/lo, Wo hi/lo (1M each)
__device__ __half g_w[12][(size_t)DDIM * DDIM];
__device__ float g_ortho_part[8192];

// ---------------------------------------------------------------------------
// Warp-MMA helpers (baseline PTX: sm_80 features only)
// ---------------------------------------------------------------------------
__device__ __forceinline__ uint32_t smem_u32(const void* p) {
    return (uint32_t)__cvta_generic_to_shared(p);
}

__device__ __forceinline__ void ldsm_x4(uint32_t* r, uint32_t addr) {
    asm volatile("ldmatrix.sync.aligned.m8n8.x4.shared.b16 {%0,%1,%2,%3}, [%4];"
                 : "=r"(r[0]), "=r"(r[1]), "=r"(r[2]), "=r"(r[3]) : "r"(addr));
}

__device__ __forceinline__ void mma16816(float* d, const uint32_t* a, const uint32_t* b) {
    asm volatile(
        "mma.sync.aligned.m16n8k16.row.col.f32.f16.f16.f32 "
        "{%0,%1,%2,%3}, {%4,%5,%6,%7}, {%8,%9}, {%0,%1,%2,%3};"
        : "+f"(d[0]), "+f"(d[1]), "+f"(d[2]), "+f"(d[3])
        : "r"(a[0]), "r"(a[1]), "r"(a[2]), "r"(a[3]), "r"(b[0]), "r"(b[1]));
}

#define CP_ASYNC16(dst, src) \
    asm volatile("cp.async.cg.shared.global [%0], [%1], 16;" :: "r"(dst), "l"(src))
#define CP_COMMIT() asm volatile("cp.async.commit_group;" ::: "memory")
#define CP_WAIT0()  asm volatile("cp.async.wait_group 0;" ::: "memory")

// ---------------------------------------------------------------------------
// fp16 2-pass GEMM: C[M,N] = (1/64) * A[M,K] @ (Wh+Wl)^T[N,K] + bias
// Tile 128x128x64, 8 warps (warp tile 64x32), 2-stage cp.async, 2 CTAs/SM,
// single __syncthreads per k-iteration (prefetch issued after the barrier).
// EPI: 2 = sincos, 3 = +resid, 4 = fused QKV (kh fp16 / val fp32 / qh fp16)
// ---------------------------------------------------------------------------
#define GBM 128
#define GBN 128
#define GBK 64
#define ROWB 144                     // 128B data + 16B pad
#define TILEB (128 * ROWB)           // 18432 B
#define STAGEB (3 * TILEB)           // A, Wh, Wl = 55296 B
#define GSTAGES 2
#define GSMEM (GSTAGES * STAGEB)     // 110592 B

// load one 128x64 fp16 tile into padded SMEM (4 x 16B chunks per thread)
__device__ __forceinline__ void ld_tile(uint32_t sdst, const __half* g,
                                        int K, int k0, int tid) {
    #pragma unroll
    for (int t = 0; t < 4; ++t) {
        const int c   = tid + t * 256;      // 0..1023
        const int row = c >> 3;
        const int cc  = c & 7;
        CP_ASYNC16(sdst + row * ROWB + cc * 16,
                   g + (size_t)row * K + k0 + cc * 8);
    }
}

template <int EPI>
__global__ void __launch_bounds__(256, 2) mma_gemm(
    const __half* __restrict__ A,
    const __half* __restrict__ Wh, const __half* __restrict__ Wl,
    const float* __restrict__ b0, const float* __restrict__ b1,
    const float* __restrict__ b2,
    float* __restrict__ of0, float* __restrict__ of1,
    __half* __restrict__ oh0, __half* __restrict__ oh1,
    const float* __restrict__ resid,
    int M, int N, int K)
{
    extern __shared__ __align__(128) char smem[];
    const uint32_t sb = smem_u32(smem);
    const int tid  = threadIdx.x;
    const int wid  = tid >> 5, lane = tid & 31;
    const int wm   = (wid >> 2) * 64;        // warp M offset in tile
    const int wn   = (wid & 3) * 32;         // warp N offset in tile
    const int m0   = blockIdx.y * GBM, n0 = blockIdx.x * GBN;

    const __half* A0 = A  + (size_t)m0 * K;
    const __half* B0 = Wh + (size_t)n0 * K;
    const __half* B1 = Wl + (size_t)n0 * K;

    const int KT = K / GBK;                   // 16

    // prologue: stage 0
    {
        const uint32_t st = sb;
        ld_tile(st + 0 * TILEB, A0, K, 0, tid);
        ld_tile(st + 1 * TILEB, B0, K, 0, tid);
        ld_tile(st + 2 * TILEB, B1, K, 0, tid);
        CP_COMMIT();
    }

    float acc[4][4][4];
    #pragma unroll
    for (int i = 0; i < 4; ++i)
        #pragma unroll
        for (int j = 0; j < 4; ++j)
            #pragma unroll
            for (int e = 0; e < 4; ++e) acc[i][j][e] = 0.0f;

    // per-lane ldmatrix address components
    const int aRow = lane & 15;
    const int aCol = lane & 16;                           // +16B for k+8 half
    const int bRow = (lane & 7) + ((lane & 16) >> 1);
    const int bCol = (lane & 8) * 2;

    for (int kt = 0; kt < KT; ++kt) {
        CP_WAIT0();            // stage kt ready (group issued at kt-1 / prologue)
        __syncthreads();       // all warps done reading stage kt-1 (== kt+1 mod 2)

        if (kt + 1 < KT) {     // prefetch next stage (safe after barrier)
            const uint32_t st = sb + ((kt + 1) & 1) * STAGEB;
            const int k0 = (kt + 1) * GBK;
            ld_tile(st + 0 * TILEB, A0, K, k0, tid);
            ld_tile(st + 1 * TILEB, B0, K, k0, tid);
            ld_tile(st + 2 * TILEB, B1, K, k0, tid);
            CP_COMMIT();
        }

        const uint32_t st  = sb + (kt & 1) * STAGEB;
        const uint32_t sA  = st + 0 * TILEB;
        const uint32_t sBh = st + 1 * TILEB;
        const uint32_t sBl = st + 2 * TILEB;

        #pragma unroll
        for (int h = 0; h < 4; ++h) {         // four k16 slices of GBK=64
            const int kb = h * 32;            // byte offset of k16 slice

            uint32_t a[4][4], bh[2][4], bl[2][4];
            #pragma unroll
            for (int mi = 0; mi < 4; ++mi) {
                const uint32_t off = (uint32_t)(wm + mi * 16 + aRow) * ROWB + kb + aCol;
                ldsm_x4(a[mi], sA + off);
            }
            #pragma unroll
            for (int bi = 0; bi < 2; ++bi) {
                const uint32_t off = (uint32_t)(wn + bi * 16 + bRow) * ROWB + kb + bCol;
                ldsm_x4(bh[bi], sBh + off);
                ldsm_x4(bl[bi], sBl + off);
            }

            #pragma unroll
            for (int mi = 0; mi < 4; ++mi) {
                #pragma unroll
                for (int ni = 0; ni < 4; ++ni) {
                    const uint32_t* Bh2 = &bh[ni >> 1][(ni & 1) * 2];
                    const uint32_t* Bl2 = &bl[ni >> 1][(ni & 1) * 2];
                    mma16816(acc[mi][ni], a[mi], Bh2);
                    mma16816(acc[mi][ni], a[mi], Bl2);
                }
            }
        }
    }

    // epilogue: direct register -> global
    #pragma unroll
    for (int mi = 0; mi < 4; ++mi) {
        #pragma unroll
        for (int ni = 0; ni < 4; ++ni) {
            const int nn = n0 + wn + ni * 8 + (lane & 3) * 2;
            #pragma unroll
            for (int half_ = 0; half_ < 2; ++half_) {
                const int row = m0 + wm + mi * 16 + (lane >> 2) + half_ * 8;
                float v0 = acc[mi][ni][half_ * 2 + 0] * INV_WSCALE;
                float v1 = acc[mi][ni][half_ * 2 + 1] * INV_WSCALE;
                if (EPI == 4) {
                    // fused QKV: column block selects destination (uniform per CTA)
                    const int sel  = nn >> 10;
                    const int cold = nn & 1023;
                    const float* bp = (sel == 0) ? b0 : (sel == 1) ? b1 : b2;
                    const float2 bv = *(const float2*)(bp + cold);
                    v0 += bv.x; v1 += bv.y;
                    const size_t off = (size_t)row * DDIM + cold;
                    if (sel == 0)      *(__half2*)(oh0 + off) = __floats2half2_rn(v0, v1);
                    else if (sel == 1) *(float2*)(of0 + off)  = make_float2(v0, v1);
                    else               *(__half2*)(oh1 + off) = __floats2half2_rn(v0, v1);
                } else {
                    const float2 bv = *(const float2*)(b0 + nn);
                    v0 += bv.x; v1 += bv.y;
                    const size_t off = (size_t)row * N + nn;
                    if (EPI == 2) {
                        float s0, c0, s1, c1;
                        __sincosf(v0, &s0, &c0);
                        __sincosf(v1, &s1, &c1);
                        *(float2*)(of0 + off) = make_float2(c0, c1);
                        *(float2*)(of1 + off) = make_float2(s0, s1);
                    } else {   // EPI 3: +resid
                        const float2 rv = *(const float2*)(resid + off);
                        *(float2*)(of0 + off) = make_float2(v0 + rv.x, v1 + rv.y);
                    }
                }
            }
        }
    }
}

// ---------------------------------------------------------------------------
// fp32 -> fp16 (vectorized)
// ---------------------------------------------------------------------------
__global__ __launch_bounds__(256)
void f32_to_f16(const float* __restrict__ a, __half* __restrict__ h, int n4)
{
    const int i = blockIdx.x * 256 + threadIdx.x;
    if (i >= n4) return;
    const float4 v = ((const float4*)a)[i];
    __half2* H = (__half2*)h;
    H[2 * i]     = __floats2half2_rn(v.x, v.y);
    H[2 * i + 1] = __floats2half2_rn(v.z, v.w);
}

// Weight convert + transpose + scale: W[K,N] fp32 -> (64W) hi/lo [N,K] fp16
__global__ __launch_bounds__(1024)
void wtrans_f16(const float* __restrict__ W, __half* __restrict__ th,
                __half* __restrict__ tl, int Kd, int Nd)
{
    __shared__ float t[32][33];
    const int tx = threadIdx.x, ty = threadIdx.y;
    const int k0 = blockIdx.y * 32, n0 = blockIdx.x * 32;
    t[ty][tx] = W[(size_t)(k0 + ty) * Nd + n0 + tx];
    __syncthreads();
    const float v = t[tx][ty] * WSCALE;        // = 64 * W[k0+tx][n0+ty]
    const size_t o = (size_t)(n0 + ty) * Kd + k0 + tx;
    __half h = __float2half(v);
    th[o] = h;
    tl[o] = __float2half(v - __half2float(h));
}

// ---------------------------------------------------------------------------
// Fused chunked cumsum + retrieve
// ---------------------------------------------------------------------------
__global__ __launch_bounds__(256)
void cumsum_retrieve(const float* __restrict__ value,
                     const float* __restrict__ kc, const float* __restrict__ ks,
                     const float* __restrict__ qc, const float* __restrict__ qs,
                     float* __restrict__ ret,
                     int Bb, int S, int D,
                     const int* __restrict__ cs_ptr, float inv_sqrt_S)
{
    const int cs = cs_ptr[0];
    const int nc = (S + cs - 1) / cs;
    const int total = Bb * nc;
    const int d = blockIdx.y * blockDim.x + threadIdx.x;
    if (d >= D) return;

    for (int t = blockIdx.x; t < total; t += gridDim.x) {
        const int b = t / nc;
        const int c = t % nc;
        const int s0 = c * cs;
        const int smax = min(cs, S - s0);
        size_t off = ((size_t)b * S + s0) * D + d;
        float r = 0.0f, im = 0.0f;
        for (int s = 0; s < smax; ++s, off += D) {
            const float v = value[off];
            r  = fmaf(v, kc[off], r);
            im = fmaf(v, ks[off], im);
            ret[off] = (r * qc[off] + im * qs[off]) * inv_sqrt_S;
        }
    }
}

// ---------------------------------------------------------------------------
// LayerNorm -> fp16 output (for final GEMM)
// ---------------------------------------------------------------------------
__global__ __launch_bounds__(256)
void layernorm_f16(const float* __restrict__ ret,
                   const float* __restrict__ gamma,
                   const float* __restrict__ beta,
                   __half* __restrict__ oh, int D)
{
    const float* p = ret + (size_t)blockIdx.x * D;
    const int tid = threadIdx.x;
    const int per = D / 256;   // 4

    float vals[8];
    float sum = 0.0f, sq = 0.0f;
    for (int i = 0; i < per; ++i) {
        float v = p[tid + i * 256];
        vals[i] = v;
        sum += v;
        sq  += v * v;
    }

    __shared__ float s1[32], s2[32];
    const int lane = tid & 31, w = tid >> 5;
    #pragma unroll
    for (int o = 16; o; o >>= 1) {
        sum += __shfl_down_sync(0xffffffffu, sum, o);
        sq  += __shfl_down_sync(0xffffffffu, sq,  o);
    }
    if (lane == 0) { s1[w] = sum; s2[w] = sq; }
    __syncthreads();
    if (w == 0) {
        sum = (lane < 8) ? s1[lane] : 0.0f;
        sq  = (lane < 8) ? s2[lane] : 0.0f;
        #pragma unroll
        for (int o = 4; o; o >>= 1) {
            sum += __shfl_down_sync(0xffffffffu, sum, o);
            sq  += __shfl_down_sync(0xffffffffu, sq,  o);
        }
        if (lane == 0) {
            const float mean = sum / (float)D;
            const float var  = sq / (float)D - mean * mean;
            s1[0] = mean;
            s2[0] = rsqrtf(var + 1e-5f);
        }
    }
    __syncthreads();
    const float mean = s1[0], rstd = s2[0];
    const size_t base = (size_t)blockIdx.x * D;
    for (int i = 0; i < per; ++i) {
        const int c = tid + i * 256;
        const float v = (vals[i] - mean) * rstd * gamma[c] + beta[c];
        oh[base + c] = __float2half(v);
    }
}

// ---------------------------------------------------------------------------
// Ortho loss
// ---------------------------------------------------------------------------
__global__ __launch_bounds__(256)
void ortho_partial(const float* __restrict__ kc, const float* __restrict__ ks,
                   const int* __restrict__ idx, int S, int D, int n)
{
    const int t = blockIdx.x;
    const int j = t % n;
    const int i = (t / n) % n;
    const int b = t / (n * n);

    if (i == j) {
        if (threadIdx.x == 0) g_ortho_part[t] = 0.0f;
        return;
    }
    const int si = idx[i], sj = idx[j];
    const float* ci = kc + ((size_t)b * S + si) * D;
    const float* cj = kc + ((size_t)b * S + sj) * D;
    const float* ni = ks + ((size_t)b * S + si) * D;
    const float* nj = ks + ((size_t)b * S + sj) * D;

    float acc = 0.0f;
    for (int d = threadIdx.x; d < D; d += blockDim.x) {
        const float v = ci[d] * cj[d] + ni[d] * nj[d];
        acc = fmaf(v, v, acc);
    }

    __shared__ float sh[32];
    const int lane = threadIdx.x & 31, w = threadIdx.x >> 5;
    #pragma unroll
    for (int o = 16; o; o >>= 1) acc += __shfl_down_sync(0xffffffffu, acc, o);
    if (lane == 0) sh[w] = acc;
    __syncthreads();
    if (w == 0) {
        acc = (lane < 8) ? sh[lane] : 0.0f;
        #pragma unroll
        for (int o = 4; o; o >>= 1) acc += __shfl_down_sync(0xffffffffu, acc, o);
        if (lane == 0) g_ortho_part[t] = acc;
    }
}

__global__ __launch_bounds__(256)
void ortho_reduce(float* __restrict__ out_loc, int total, float denom)
{
    float acc = 0.0f;
    for (int t = threadIdx.x; t < total; t += 256) acc += g_ortho_part[t];

    __shared__ float sh[32];
    const int lane = threadIdx.x & 31, w = threadIdx.x >> 5;
    #pragma unroll
    for (int o = 16; o; o >>= 1) acc += __shfl_down_sync(0xffffffffu, acc, o);
    if (lane == 0) sh[w] = acc;
    __syncthreads();
    if (w == 0) {
        acc = (lane < 8) ? sh[lane] : 0.0f;
        #pragma unroll
        for (int o = 4; o; o >>= 1) acc += __shfl_down_sync(0xffffffffu, acc, o);
        if (lane == 0) *out_loc = acc / denom;
    }
}

// ---------------------------------------------------------------------------
// Launcher
// ---------------------------------------------------------------------------
extern "C" void kernel_launch(void* const* d_in, const int* in_sizes, int n_in,
                              void* d_out, int out_size)
{
    const float* x    = (const float*)d_in[0];
    const float* Wk   = (const float*)d_in[1];
    const float* bk   = (const float*)d_in[2];
    const float* Wv   = (const float*)d_in[3];
    const float* bv   = (const float*)d_in[4];
    const float* Wq   = (const float*)d_in[5];
    const float* bq   = (const float*)d_in[6];
    const float* Wkp  = (const float*)d_in[7];
    const float* bkp  = (const float*)d_in[8];
    const float* Wqp  = (const float*)d_in[9];
    const float* bqp  = (const float*)d_in[10];
    const float* ln_g = (const float*)d_in[11];
    const float* ln_b = (const float*)d_in[12];
    const float* Wo   = (const float*)d_in[13];
    const float* bo   = (const float*)d_in[14];
    const int*   idx  = (const int*)d_in[15];
    const int*   csp  = (const int*)d_in[16];

    const int D  = in_sizes[2];        // 1024
    const int M  = in_sizes[0] / D;    // 16384
    const int Bb = 4;
    const int S  = M / Bb;             // 4096
    const int n  = in_sizes[15];       // 32

    float *val, *kc, *ks, *qc, *qs, *ret;
    __half *xh, *kh, *qh, *wbase;
    cudaGetSymbolAddress((void**)&val, g_val);
    cudaGetSymbolAddress((void**)&kc,  g_kc);
    cudaGetSymbolAddress((void**)&ks,  g_ks);
    cudaGetSymbolAddress((void**)&qc,  g_qc);
    cudaGetSymbolAddress((void**)&qs,  g_qs);
    cudaGetSymbolAddress((void**)&ret, g_ret);
    cudaGetSymbolAddress((void**)&xh,  g_xh);
    cudaGetSymbolAddress((void**)&kh,  g_kh);
    cudaGetSymbolAddress((void**)&qh,  g_qh);
    cudaGetSymbolAddress((void**)&wbase, g_w);
    const size_t WSZ = (size_t)D * D;
    #define WSLOT(i) (wbase + (size_t)(i) * WSZ)

    // fused QKV weight layout: hi rows [Wk|Wv|Wq] at slots 0..2, lo at 3..5
    __half* qkv_hi = WSLOT(0);
    __half* qkv_lo = WSLOT(3);

    float* out = (float*)d_out;

    cudaFuncSetAttribute(mma_gemm<2>, cudaFuncAttributeMaxDynamicSharedMemorySize, GSMEM);
    cudaFuncSetAttribute(mma_gemm<3>, cudaFuncAttributeMaxDynamicSharedMemorySize, GSMEM);
    cudaFuncSetAttribute(mma_gemm<4>, cudaFuncAttributeMaxDynamicSharedMemorySize, GSMEM);

    const dim3 wb(32, 32), wg(D / 32, D / 32);

    // launches 1-5: QKV weight blocks, Wkp, x->fp16  (ncu -s 5 skips these)
    wtrans_f16<<<wg, wb>>>(Wk,  qkv_hi + 0 * WSZ, qkv_lo + 0 * WSZ, D, D);
    wtrans_f16<<<wg, wb>>>(Wv,  qkv_hi + 1 * WSZ, qkv_lo + 1 * WSZ, D, D);
    wtrans_f16<<<wg, wb>>>(Wq,  qkv_hi + 2 * WSZ, qkv_lo + 2 * WSZ, D, D);
    wtrans_f16<<<wg, wb>>>(Wkp, WSLOT(6), WSLOT(7), D, D);
    const int n4 = (int)(NELEM / 4);
    f32_to_f16<<<(n4 + 255) / 256, 256>>>(x, xh, n4);

    // launch 6 (ncu profiles this): fused QKV projection, N = 3*D
    mma_gemm<4><<<dim3(3 * D / GBN, M / GBM), 256, GSMEM>>>(
        xh, qkv_hi, qkv_lo, bk, bv, bq,
        val, nullptr, kh, qh, nullptr, M, 3 * D, D);

    // remaining weight conversions
    wtrans_f16<<<wg, wb>>>(Wqp, WSLOT(8),  WSLOT(9),  D, D);
    wtrans_f16<<<wg, wb>>>(Wo,  WSLOT(10), WSLOT(11), D, D);

    const dim3 gg(D / GBN, M / GBM);

    // phase projections with fused cos/sin
    mma_gemm<2><<<gg, 256, GSMEM>>>(kh, WSLOT(6), WSLOT(7), bkp, nullptr, nullptr,
                                    kc, ks, nullptr, nullptr, nullptr, M, D, D);
    mma_gemm<2><<<gg, 256, GSMEM>>>(qh, WSLOT(8), WSLOT(9), bqp, nullptr, nullptr,
                                    qc, qs, nullptr, nullptr, nullptr, M, D, D);

    // chunked complex cumsum + retrieve
    const float inv_sqrt_S = 1.0f / sqrtf((float)S);
    cumsum_retrieve<<<dim3(256, D / 256), 256>>>(val, kc, ks, qc, qs, ret,
                                                 Bb, S, D, csp, inv_sqrt_S);

    // layernorm -> fp16 (reuse kh, dead after phase GEMM)
    layernorm_f16<<<M, 256>>>(ret, ln_g, ln_b, kh, D);

    // output projection + residual, straight into d_out
    mma_gemm<3><<<gg, 256, GSMEM>>>(kh, WSLOT(10), WSLOT(11), bo, nullptr, nullptr,
                                    out, nullptr, nullptr, nullptr, x, M, D, D);

    // ortho loss -> last output element
    ortho_partial<<<Bb * n * n, 256>>>(kc, ks, idx, S, D, n);
    const float denom = (float)(n * (n - 1)) * (float)D + 1e-6f;
    ortho_reduce<<<1, 256>>>(out + (out_size - 1), Bb * n * n, denom);
}

// round 7
// speedup vs baseline: 5.4269x; 1.3212x over previous
#include <cuda_runtime.h>
#include <cuda_fp16.h>
#include <math.h>
#include <cstdint>

// ---------------------------------------------------------------------------
// Problem constants (B=4, S=4096, D=1024)
// ---------------------------------------------------------------------------
#define MM    16384
#define DDIM  1024
#define NELEM ((size_t)MM * DDIM)

#define WSCALE     64.0f
#define INV_WSCALE (1.0f / 64.0f)

__device__ float g_val[NELEM];
__device__ float g_kc [NELEM];
__device__ float g_ks [NELEM];
__device__ float g_qc [NELEM];
__device__ float g_qs [NELEM];
__device__ float g_ret[NELEM];
__device__ __half g_xh[NELEM];
__device__ __half g_kh[NELEM];
__device__ __half g_qh[NELEM];
// slots: 0..2 = QKV rows [Wk|Wv|Wq], 3 = Wkp, 4 = Wqp, 5 = Wo  ([N,K], x64)
__device__ __half g_w[6][(size_t)DDIM * DDIM];
__device__ float g_ortho_part[8192];

// ---------------------------------------------------------------------------
// Warp-MMA helpers (baseline PTX: sm_80 features only)
// ---------------------------------------------------------------------------
__device__ __forceinline__ uint32_t smem_u32(const void* p) {
    return (uint32_t)__cvta_generic_to_shared(p);
}

__device__ __forceinline__ void ldsm_x4(uint32_t* r, uint32_t addr) {
    asm volatile("ldmatrix.sync.aligned.m8n8.x4.shared.b16 {%0,%1,%2,%3}, [%4];"
                 : "=r"(r[0]), "=r"(r[1]), "=r"(r[2]), "=r"(r[3]) : "r"(addr));
}

__device__ __forceinline__ void mma16816(float* d, const uint32_t* a, const uint32_t* b) {
    asm volatile(
        "mma.sync.aligned.m16n8k16.row.col.f32.f16.f16.f32 "
        "{%0,%1,%2,%3}, {%4,%5,%6,%7}, {%8,%9}, {%0,%1,%2,%3};"
        : "+f"(d[0]), "+f"(d[1]), "+f"(d[2]), "+f"(d[3])
        : "r"(a[0]), "r"(a[1]), "r"(a[2]), "r"(a[3]), "r"(b[0]), "r"(b[1]));
}

#define CP_ASYNC16(dst, src) \
    asm volatile("cp.async.cg.shared.global [%0], [%1], 16;" :: "r"(dst), "l"(src))
#define CP_COMMIT() asm volatile("cp.async.commit_group;" ::: "memory")
#define CP_WAIT1()  asm volatile("cp.async.wait_group 1;" ::: "memory")
#define CP_WAIT0()  asm volatile("cp.async.wait_group 0;" ::: "memory")

// ---------------------------------------------------------------------------
// fp16 single-pass GEMM: C[M,N] = (1/64) * A[M,K] @ W^T[N,K] + bias
// CTA tile 256x128x64, 8 warps (warp tile 64x64), 3-stage cp.async, 1 CTA/SM.
// Pipeline order per iteration (correct cp.async visibility):
//   wait_group -> __syncthreads -> prefetch(kt+2) -> compute(kt)
// EPI: 2 = sincos (batched via blockIdx.z), 3 = +resid, 4 = fused QKV
// ---------------------------------------------------------------------------
#define GBM 256
#define GBN 128
#define GBK 64
#define ROWB 144                       // 128B data + 16B pad
#define A_TILEB (GBM * ROWB)           // 36864 B
#define B_TILEB (GBN * ROWB)           // 18432 B
#define STAGEB (A_TILEB + B_TILEB)     // 55296 B
#define GSTAGES 3
#define GSMEM (GSTAGES * STAGEB)       // 165888 B

// load one ROWSx64 fp16 tile into padded SMEM (16B chunks)
template <int ROWS>
__device__ __forceinline__ void ld_tile(uint32_t sdst, const __half* g,
                                        int K, int k0, int tid) {
    #pragma unroll
    for (int t = 0; t < ROWS * 8 / 256; ++t) {
        const int c   = tid + t * 256;
        const int row = c >> 3;
        const int cc  = c & 7;
        CP_ASYNC16(sdst + row * ROWB + cc * 16,
                   g + (size_t)row * K + k0 + cc * 8);
    }
}

template <int EPI>
__global__ void __launch_bounds__(256, 1) mma_gemm(
    const __half* __restrict__ A,  const __half* __restrict__ A2,
    const __half* __restrict__ W,  const __half* __restrict__ W2,
    const float* __restrict__ b0, const float* __restrict__ b1,
    const float* __restrict__ b2,
    float* __restrict__ of0, float* __restrict__ of1,
    float* __restrict__ of2, float* __restrict__ of3,
    __half* __restrict__ oh0, __half* __restrict__ oh1,
    const float* __restrict__ resid,
    int M, int N, int K)
{
    extern __shared__ __align__(128) char smem[];
    const uint32_t sb = smem_u32(smem);
    const int tid  = threadIdx.x;
    const int wid  = tid >> 5, lane = tid & 31;
    const int wm   = (wid >> 1) * 64;          // warp M offset (4 row-warps)
    const int wn   = (wid & 1) * 64;           // warp N offset (2 col-warps)
    const int m0   = blockIdx.y * GBM, n0 = blockIdx.x * GBN;
    const int z    = (EPI == 2) ? (int)blockIdx.z : 0;

    const __half* Ap = (EPI == 2 && z) ? A2 : A;
    const __half* Wp = (EPI == 2 && z) ? W2 : W;

    const __half* A0 = Ap + (size_t)m0 * K;
    const __half* B0 = Wp + (size_t)n0 * K;

    const int KT = K / GBK;                    // 16

    // prologue: stages 0,1
    #pragma unroll
    for (int p = 0; p < 2; ++p) {
        const uint32_t st = sb + p * STAGEB;
        ld_tile<GBM>(st, A0, K, p * GBK, tid);
        ld_tile<GBN>(st + A_TILEB, B0, K, p * GBK, tid);
        CP_COMMIT();
    }

    float acc[4][8][4];
    #pragma unroll
    for (int i = 0; i < 4; ++i)
        #pragma unroll
        for (int j = 0; j < 8; ++j)
            #pragma unroll
            for (int e = 0; e < 4; ++e) acc[i][j][e] = 0.0f;

    // per-lane ldmatrix address components
    const int aRow = lane & 15;
    const int aCol = lane & 16;                          // +16B selects k+8
    const int bRow = (lane & 7) + ((lane & 16) >> 1);
    const int bCol = (lane & 8) * 2;

    for (int kt = 0; kt < KT; ++kt) {
        // stage kt complete for ALL threads after the barrier below
        if (kt + 1 < KT) { CP_WAIT1(); } else { CP_WAIT0(); }
        __syncthreads();

        // prefetch stage kt+2 (overwrites stage kt-1; all warps are past it)
        if (kt + 2 < KT) {
            const uint32_t st = sb + ((kt + 2) % GSTAGES) * STAGEB;
            const int k0 = (kt + 2) * GBK;
            ld_tile<GBM>(st, A0, K, k0, tid);
            ld_tile<GBN>(st + A_TILEB, B0, K, k0, tid);
            CP_COMMIT();
        }

        const uint32_t st = sb + (kt % GSTAGES) * STAGEB;
        const uint32_t sA = st;
        const uint32_t sB = st + A_TILEB;

        #pragma unroll
        for (int h = 0; h < 4; ++h) {          // four k16 slices of GBK=64
            const int kb = h * 32;

            uint32_t a[4][4], b[4][4];
            #pragma unroll
            for (int mi = 0; mi < 4; ++mi) {
                const uint32_t off = (uint32_t)(wm + mi * 16 + aRow) * ROWB + kb + aCol;
                ldsm_x4(a[mi], sA + off);
            }
            #pragma unroll
            for (int bi = 0; bi < 4; ++bi) {
                const uint32_t off = (uint32_t)(wn + bi * 16 + bRow) * ROWB + kb + bCol;
                ldsm_x4(b[bi], sB + off);
            }

            #pragma unroll
            for (int mi = 0; mi < 4; ++mi) {
                #pragma unroll
                for (int ni = 0; ni < 8; ++ni) {
                    mma16816(acc[mi][ni], a[mi], &b[ni >> 1][(ni & 1) * 2]);
                }
            }
        }
    }

    // epilogue: registers -> global
    #pragma unroll
    for (int mi = 0; mi < 4; ++mi) {
        #pragma unroll
        for (int ni = 0; ni < 8; ++ni) {
            const int nn = n0 + wn + ni * 8 + (lane & 3) * 2;
            #pragma unroll
            for (int half_ = 0; half_ < 2; ++half_) {
                const int row = m0 + wm + mi * 16 + (lane >> 2) + half_ * 8;
                float v0 = acc[mi][ni][half_ * 2 + 0] * INV_WSCALE;
                float v1 = acc[mi][ni][half_ * 2 + 1] * INV_WSCALE;
                if (EPI == 4) {
                    // fused QKV: column block selects destination
                    const int sel  = nn >> 10;
                    const int cold = nn & 1023;
                    const float* bp = (sel == 0) ? b0 : (sel == 1) ? b1 : b2;
                    const float2 bv = *(const float2*)(bp + cold);
                    v0 += bv.x; v1 += bv.y;
                    const size_t off = (size_t)row * DDIM + cold;
                    if (sel == 0)      *(__half2*)(oh0 + off) = __floats2half2_rn(v0, v1);
                    else if (sel == 1) *(float2*)(of0 + off)  = make_float2(v0, v1);
                    else               *(__half2*)(oh1 + off) = __floats2half2_rn(v0, v1);
                } else if (EPI == 2) {
                    const float* bp = z ? b1 : b0;
                    float* oc = z ? of2 : of0;
                    float* os = z ? of3 : of1;
                    const float2 bv = *(const float2*)(bp + nn);
                    v0 += bv.x; v1 += bv.y;
                    const size_t off = (size_t)row * N + nn;
                    float s0, c0, s1, c1;
                    __sincosf(v0, &s0, &c0);
                    __sincosf(v1, &s1, &c1);
                    *(float2*)(oc + off) = make_float2(c0, c1);
                    *(float2*)(os + off) = make_float2(s0, s1);
                } else {   // EPI 3: +resid
                    const float2 bv = *(const float2*)(b0 + nn);
                    const size_t off = (size_t)row * N + nn;
                    const float2 rv = *(const float2*)(resid + off);
                    *(float2*)(of0 + off) = make_float2(v0 + bv.x + rv.x,
                                                        v1 + bv.y + rv.y);
                }
            }
        }
    }
}

// ---------------------------------------------------------------------------
// fp32 -> fp16 (vectorized)
// ---------------------------------------------------------------------------
__global__ __launch_bounds__(256)
void f32_to_f16(const float* __restrict__ a, __half* __restrict__ h, int n4)
{
    const int i = blockIdx.x * 256 + threadIdx.x;
    if (i >= n4) return;
    const float4 v = ((const float4*)a)[i];
    __half2* H = (__half2*)h;
    H[2 * i]     = __floats2half2_rn(v.x, v.y);
    H[2 * i + 1] = __floats2half2_rn(v.z, v.w);
}

// All-6 weight convert + transpose + scale in one launch:
// W[K,N] fp32 -> (64W)[N,K] fp16, blockIdx.z selects the weight.
struct W6 { const float* p[6]; };
__global__ __launch_bounds__(1024)
void wtrans6(W6 ws, __half* __restrict__ outbase, int Kd, int Nd)
{
    __shared__ float t[32][33];
    const float* W = ws.p[blockIdx.z];
    __half* th = outbase + (size_t)blockIdx.z * Kd * Nd;
    const int tx = threadIdx.x, ty = threadIdx.y;
    const int k0 = blockIdx.y * 32, n0 = blockIdx.x * 32;
    t[ty][tx] = W[(size_t)(k0 + ty) * Nd + n0 + tx];
    __syncthreads();
    const float v = t[tx][ty] * WSCALE;        // = 64 * W[k0+tx][n0+ty]
    th[(size_t)(n0 + ty) * Kd + k0 + tx] = __float2half(v);
}

// ---------------------------------------------------------------------------
// Fused chunked cumsum + retrieve
// ---------------------------------------------------------------------------
__global__ __launch_bounds__(256)
void cumsum_retrieve(const float* __restrict__ value,
                     const float* __restrict__ kc, const float* __restrict__ ks,
                     const float* __restrict__ qc, const float* __restrict__ qs,
                     float* __restrict__ ret,
                     int Bb, int S, int D,
                     const int* __restrict__ cs_ptr, float inv_sqrt_S)
{
    const int cs = cs_ptr[0];
    const int nc = (S + cs - 1) / cs;
    const int total = Bb * nc;
    const int d = blockIdx.y * blockDim.x + threadIdx.x;
    if (d >= D) return;

    for (int t = blockIdx.x; t < total; t += gridDim.x) {
        const int b = t / nc;
        const int c = t % nc;
        const int s0 = c * cs;
        const int smax = min(cs, S - s0);
        size_t off = ((size_t)b * S + s0) * D + d;
        float r = 0.0f, im = 0.0f;
        for (int s = 0; s < smax; ++s, off += D) {
            const float v = value[off];
            r  = fmaf(v, kc[off], r);
            im = fmaf(v, ks[off], im);
            ret[off] = (r * qc[off] + im * qs[off]) * inv_sqrt_S;
        }
    }
}

// ---------------------------------------------------------------------------
// LayerNorm -> fp16 output (for final GEMM)
// ---------------------------------------------------------------------------
__global__ __launch_bounds__(256)
void layernorm_f16(const float* __restrict__ ret,
                   const float* __restrict__ gamma,
                   const float* __restrict__ beta,
                   __half* __restrict__ oh, int D)
{
    const float* p = ret + (size_t)blockIdx.x * D;
    const int tid = threadIdx.x;
    const int per = D / 256;   // 4

    float vals[8];
    float sum = 0.0f, sq = 0.0f;
    for (int i = 0; i < per; ++i) {
        float v = p[tid + i * 256];
        vals[i] = v;
        sum += v;
        sq  += v * v;
    }

    __shared__ float s1[32], s2[32];
    const int lane = tid & 31, w = tid >> 5;
    #pragma unroll
    for (int o = 16; o; o >>= 1) {
        sum += __shfl_down_sync(0xffffffffu, sum, o);
        sq  += __shfl_down_sync(0xffffffffu, sq,  o);
    }
    if (lane == 0) { s1[w] = sum; s2[w] = sq; }
    __syncthreads();
    if (w == 0) {
        sum = (lane < 8) ? s1[lane] : 0.0f;
        sq  = (lane < 8) ? s2[lane] : 0.0f;
        #pragma unroll
        for (int o = 4; o; o >>= 1) {
            sum += __shfl_down_sync(0xffffffffu, sum, o);
            sq  += __shfl_down_sync(0xffffffffu, sq,  o);
        }
        if (lane == 0) {
            const float mean = sum / (float)D;
            const float var  = sq / (float)D - mean * mean;
            s1[0] = mean;
            s2[0] = rsqrtf(var + 1e-5f);
        }
    }
    __syncthreads();
    const float mean = s1[0], rstd = s2[0];
    const size_t base = (size_t)blockIdx.x * D;
    for (int i = 0; i < per; ++i) {
        const int c = tid + i * 256;
        const float v = (vals[i] - mean) * rstd * gamma[c] + beta[c];
        oh[base + c] = __float2half(v);
    }
}

// ---------------------------------------------------------------------------
// Ortho loss
// ---------------------------------------------------------------------------
__global__ __launch_bounds__(256)
void ortho_partial(const float* __restrict__ kc, const float* __restrict__ ks,
                   const int* __restrict__ idx, int S, int D, int n)
{
    const int t = blockIdx.x;
    const int j = t % n;
    const int i = (t / n) % n;
    const int b = t / (n * n);

    if (i == j) {
        if (threadIdx.x == 0) g_ortho_part[t] = 0.0f;
        return;
    }
    const int si = idx[i], sj = idx[j];
    const float* ci = kc + ((size_t)b * S + si) * D;
    const float* cj = kc + ((size_t)b * S + sj) * D;
    const float* ni = ks + ((size_t)b * S + si) * D;
    const float* nj = ks + ((size_t)b * S + sj) * D;

    float acc = 0.0f;
    for (int d = threadIdx.x; d < D; d += blockDim.x) {
        const float v = ci[d] * cj[d] + ni[d] * nj[d];
        acc = fmaf(v, v, acc);
    }

    __shared__ float sh[32];
    const int lane = threadIdx.x & 31, w = threadIdx.x >> 5;
    #pragma unroll
    for (int o = 16; o; o >>= 1) acc += __shfl_down_sync(0xffffffffu, acc, o);
    if (lane == 0) sh[w] = acc;
    __syncthreads();
    if (w == 0) {
        acc = (lane < 8) ? sh[lane] : 0.0f;
        #pragma unroll
        for (int o = 4; o; o >>= 1) acc += __shfl_down_sync(0xffffffffu, acc, o);
        if (lane == 0) g_ortho_part[t] = acc;
    }
}

__global__ __launch_bounds__(256)
void ortho_reduce(float* __restrict__ out_loc, int total, float denom)
{
    float acc = 0.0f;
    for (int t = threadIdx.x; t < total; t += 256) acc += g_ortho_part[t];

    __shared__ float sh[32];
    const int lane = threadIdx.x & 31, w = threadIdx.x >> 5;
    #pragma unroll
    for (int o = 16; o; o >>= 1) acc += __shfl_down_sync(0xffffffffu, acc, o);
    if (lane == 0) sh[w] = acc;
    __syncthreads();
    if (w == 0) {
        acc = (lane < 8) ? sh[lane] : 0.0f;
        #pragma unroll
        for (int o = 4; o; o >>= 1) acc += __shfl_down_sync(0xffffffffu, acc, o);
        if (lane == 0) *out_loc = acc / denom;
    }
}

// ---------------------------------------------------------------------------
// Launcher
// ---------------------------------------------------------------------------
extern "C" void kernel_launch(void* const* d_in, const int* in_sizes, int n_in,
                              void* d_out, int out_size)
{
    const float* x    = (const float*)d_in[0];
    const float* Wk   = (const float*)d_in[1];
    const float* bk   = (const float*)d_in[2];
    const float* Wv   = (const float*)d_in[3];
    const float* bv   = (const float*)d_in[4];
    const float* Wq   = (const float*)d_in[5];
    const float* bq   = (const float*)d_in[6];
    const float* Wkp  = (const float*)d_in[7];
    const float* bkp  = (const float*)d_in[8];
    const float* Wqp  = (const float*)d_in[9];
    const float* bqp  = (const float*)d_in[10];
    const float* ln_g = (const float*)d_in[11];
    const float* ln_b = (const float*)d_in[12];
    const float* Wo   = (const float*)d_in[13];
    const float* bo   = (const float*)d_in[14];
    const int*   idx  = (const int*)d_in[15];
    const int*   csp  = (const int*)d_in[16];

    const int D  = in_sizes[2];        // 1024
    const int M  = in_sizes[0] / D;    // 16384
    const int Bb = 4;
    const int S  = M / Bb;             // 4096
    const int n  = in_sizes[15];       // 32

    float *val, *kc, *ks, *qc, *qs, *ret;
    __half *xh, *kh, *qh, *wbase;
    cudaGetSymbolAddress((void**)&val, g_val);
    cudaGetSymbolAddress((void**)&kc,  g_kc);
    cudaGetSymbolAddress((void**)&ks,  g_ks);
    cudaGetSymbolAddress((void**)&qc,  g_qc);
    cudaGetSymbolAddress((void**)&qs,  g_qs);
    cudaGetSymbolAddress((void**)&ret, g_ret);
    cudaGetSymbolAddress((void**)&xh,  g_xh);
    cudaGetSymbolAddress((void**)&kh,  g_kh);
    cudaGetSymbolAddress((void**)&qh,  g_qh);
    cudaGetSymbolAddress((void**)&wbase, g_w);
    const size_t WSZ = (size_t)D * D;
    #define WSLOT(i) (wbase + (size_t)(i) * WSZ)

    float* out = (float*)d_out;

    cudaFuncSetAttribute(mma_gemm<2>, cudaFuncAttributeMaxDynamicSharedMemorySize, GSMEM);
    cudaFuncSetAttribute(mma_gemm<3>, cudaFuncAttributeMaxDynamicSharedMemorySize, GSMEM);
    cudaFuncSetAttribute(mma_gemm<4>, cudaFuncAttributeMaxDynamicSharedMemorySize, GSMEM);

    // 1) all six weight conversions in one launch (z selects weight)
    W6 ws;
    ws.p[0] = Wk; ws.p[1] = Wv; ws.p[2] = Wq;
    ws.p[3] = Wkp; ws.p[4] = Wqp; ws.p[5] = Wo;
    wtrans6<<<dim3(D / 32, D / 32, 6), dim3(32, 32)>>>(ws, wbase, D, D);

    // 2) x -> fp16
    const int n4 = (int)(NELEM / 4);
    f32_to_f16<<<(n4 + 255) / 256, 256>>>(x, xh, n4);

    // 3) fused QKV projection, N = 3*D
    mma_gemm<4><<<dim3(3 * D / GBN, M / GBM), 256, GSMEM>>>(
        xh, nullptr, WSLOT(0), nullptr, bk, bv, bq,
        val, nullptr, nullptr, nullptr, kh, qh, nullptr, M, 3 * D, D);

    // 4) both phase projections (batched via z) with fused cos/sin
    mma_gemm<2><<<dim3(D / GBN, M / GBM, 2), 256, GSMEM>>>(
        kh, qh, WSLOT(3), WSLOT(4), bkp, bqp, nullptr,
        kc, ks, qc, qs, nullptr, nullptr, nullptr, M, D, D);

    // 5) ortho partial (needs kc/ks only)
    ortho_partial<<<Bb * n * n, 256>>>(kc, ks, idx, S, D, n);

    // 6) chunked complex cumsum + retrieve   <-- ncu -s 5 -c 1 profiles this
    const float inv_sqrt_S = 1.0f / sqrtf((float)S);
    cumsum_retrieve<<<dim3(256, D / 256), 256>>>(val, kc, ks, qc, qs, ret,
                                                 Bb, S, D, csp, inv_sqrt_S);

    // 7) layernorm -> fp16 (reuse kh)
    layernorm_f16<<<M, 256>>>(ret, ln_g, ln_b, kh, D);

    // 8) output projection + residual, straight into d_out
    mma_gemm<3><<<dim3(D / GBN, M / GBM), 256, GSMEM>>>(
        kh, nullptr, WSLOT(5), nullptr, bo, nullptr, nullptr,
        out, nullptr, nullptr, nullptr, nullptr, nullptr, x, M, D, D);

    // 9) ortho reduce -> last output element
    const float denom = (float)(n * (n - 1)) * (float)D + 1e-6f;
    ortho_reduce<<<1, 256>>>(out + (out_size - 1), Bb * n * n, denom);
}

// round 8
// speedup vs baseline: 5.4794x; 1.0097x over previous
#include <cuda_runtime.h>
#include <cuda_fp16.h>
#include <math.h>
#include <cstdint>

// ---------------------------------------------------------------------------
// Problem constants (B=4, S=4096, D=1024)
// ---------------------------------------------------------------------------
#define MM    16384
#define DDIM  1024
#define NELEM ((size_t)MM * DDIM)

#define WSCALE     64.0f
#define INV_WSCALE (1.0f / 64.0f)

__device__ float g_val[NELEM];
__device__ float g_kc [NELEM];
__device__ float g_ks [NELEM];
__device__ float g_qc [NELEM];
__device__ float g_qs [NELEM];
__device__ float g_ret[NELEM];
__device__ __half g_xh[NELEM];
__device__ __half g_kh[NELEM];
__device__ __half g_qh[NELEM];
// slots: 0..2 = QKV rows [Wk|Wv|Wq], 3 = Wkp, 4 = Wqp, 5 = Wo  ([N,K], x64)
__device__ __half g_w[6][(size_t)DDIM * DDIM];
__device__ float g_ortho_part[8192];

// ---------------------------------------------------------------------------
// Warp-MMA helpers (baseline PTX: sm_80 features only)
// ---------------------------------------------------------------------------
__device__ __forceinline__ uint32_t smem_u32(const void* p) {
    return (uint32_t)__cvta_generic_to_shared(p);
}

__device__ __forceinline__ void ldsm_x4(uint32_t* r, uint32_t addr) {
    asm volatile("ldmatrix.sync.aligned.m8n8.x4.shared.b16 {%0,%1,%2,%3}, [%4];"
                 : "=r"(r[0]), "=r"(r[1]), "=r"(r[2]), "=r"(r[3]) : "r"(addr));
}

__device__ __forceinline__ void mma16816(float* d, const uint32_t* a, const uint32_t* b) {
    asm volatile(
        "mma.sync.aligned.m16n8k16.row.col.f32.f16.f16.f32 "
        "{%0,%1,%2,%3}, {%4,%5,%6,%7}, {%8,%9}, {%0,%1,%2,%3};"
        : "+f"(d[0]), "+f"(d[1]), "+f"(d[2]), "+f"(d[3])
        : "r"(a[0]), "r"(a[1]), "r"(a[2]), "r"(a[3]), "r"(b[0]), "r"(b[1]));
}

#define CP_ASYNC16(dst, src) \
    asm volatile("cp.async.cg.shared.global [%0], [%1], 16;" :: "r"(dst), "l"(src))
#define CP_COMMIT() asm volatile("cp.async.commit_group;" ::: "memory")
#define CP_WAIT0()  asm volatile("cp.async.wait_group 0;" ::: "memory")

// ---------------------------------------------------------------------------
// fp16 single-pass GEMM: C[M,N] = (1/64) * A[M,K] @ W^T[N,K] + bias
// CTA tile 256x128x128, 8 warps (warp tile 64x64), 2-stage cp.async, 1 CTA/SM.
// Per iteration: wait -> barrier -> prefetch(kt+1) -> compute(kt) with
// register-level fragment double buffering across the 8 k16 slices.
// EPI: 2 = sincos (batched via blockIdx.z), 3 = +resid, 4 = fused QKV
// ---------------------------------------------------------------------------
#define GBM 256
#define GBN 128
#define GBK 128
#define ROWB 272                       // 256B data + 16B pad (4-bank rotation)
#define A_TILEB (GBM * ROWB)           // 69632 B
#define B_TILEB (GBN * ROWB)           // 34816 B
#define STAGEB (A_TILEB + B_TILEB)     // 104448 B
#define GSTAGES 2
#define GSMEM (GSTAGES * STAGEB)       // 208896 B

// load one ROWSx128 fp16 tile into padded SMEM (16B chunks, 16 per row)
template <int ROWS>
__device__ __forceinline__ void ld_tile(uint32_t sdst, const __half* g,
                                        int K, int k0, int tid) {
    #pragma unroll
    for (int t = 0; t < ROWS * 16 / 256; ++t) {
        const int c   = tid + t * 256;
        const int row = c >> 4;
        const int cc  = c & 15;
        CP_ASYNC16(sdst + row * ROWB + cc * 16,
                   g + (size_t)row * K + k0 + cc * 8);
    }
}

template <int EPI>
__global__ void __launch_bounds__(256, 1) mma_gemm(
    const __half* __restrict__ A,  const __half* __restrict__ A2,
    const __half* __restrict__ W,  const __half* __restrict__ W2,
    const float* __restrict__ b0, const float* __restrict__ b1,
    const float* __restrict__ b2,
    float* __restrict__ of0, float* __restrict__ of1,
    float* __restrict__ of2, float* __restrict__ of3,
    __half* __restrict__ oh0, __half* __restrict__ oh1,
    const float* __restrict__ resid,
    int M, int N, int K)
{
    extern __shared__ __align__(128) char smem[];
    const uint32_t sb = smem_u32(smem);
    const int tid  = threadIdx.x;
    const int wid  = tid >> 5, lane = tid & 31;
    const int wm   = (wid >> 1) * 64;          // warp M offset (4 row-warps)
    const int wn   = (wid & 1) * 64;           // warp N offset (2 col-warps)
    const int m0   = blockIdx.y * GBM, n0 = blockIdx.x * GBN;
    const int z    = (EPI == 2) ? (int)blockIdx.z : 0;

    const __half* Ap = (EPI == 2 && z) ? A2 : A;
    const __half* Wp = (EPI == 2 && z) ? W2 : W;

    const __half* A0 = Ap + (size_t)m0 * K;
    const __half* B0 = Wp + (size_t)n0 * K;

    const int KT = K / GBK;                    // 8

    // prologue: stage 0
    ld_tile<GBM>(sb, A0, K, 0, tid);
    ld_tile<GBN>(sb + A_TILEB, B0, K, 0, tid);
    CP_COMMIT();

    float acc[4][8][4];
    #pragma unroll
    for (int i = 0; i < 4; ++i)
        #pragma unroll
        for (int j = 0; j < 8; ++j)
            #pragma unroll
            for (int e = 0; e < 4; ++e) acc[i][j][e] = 0.0f;

    // per-lane ldmatrix address components
    const int aRow = lane & 15;
    const int aCol = lane & 16;                          // +16B selects k+8
    const int bRow = (lane & 7) + ((lane & 16) >> 1);
    const int bCol = (lane & 8) * 2;

    uint32_t afrag[2][4][4], bfrag[2][4][4];

    for (int kt = 0; kt < KT; ++kt) {
        CP_WAIT0();        // stage kt landed (this thread's copies)
        __syncthreads();   // ...and everyone else's; all warps past stage kt-1

        // prefetch stage kt+1 into the other buffer (just freed)
        if (kt + 1 < KT) {
            const uint32_t st = sb + ((kt + 1) & 1) * STAGEB;
            const int k0 = (kt + 1) * GBK;
            ld_tile<GBM>(st, A0, K, k0, tid);
            ld_tile<GBN>(st + A_TILEB, B0, K, k0, tid);
            CP_COMMIT();
        }

        const uint32_t st = sb + (kt & 1) * STAGEB;
        const uint32_t sA = st;
        const uint32_t sB = st + A_TILEB;

        // fragment loader for k16 slice h into register buffer buf
        auto load_frags = [&](int h, int buf) {
            const int kb = h * 32;
            #pragma unroll
            for (int mi = 0; mi < 4; ++mi) {
                const uint32_t off = (uint32_t)(wm + mi * 16 + aRow) * ROWB + kb + aCol;
                ldsm_x4(afrag[buf][mi], sA + off);
            }
            #pragma unroll
            for (int bi = 0; bi < 4; ++bi) {
                const uint32_t off = (uint32_t)(wn + bi * 16 + bRow) * ROWB + kb + bCol;
                ldsm_x4(bfrag[buf][bi], sB + off);
            }
        };

        load_frags(0, 0);
        #pragma unroll
        for (int h = 0; h < GBK / 16; ++h) {   // 8 slices
            if (h + 1 < GBK / 16) load_frags(h + 1, (h + 1) & 1);
            const int cb = h & 1;
            #pragma unroll
            for (int mi = 0; mi < 4; ++mi) {
                #pragma unroll
                for (int ni = 0; ni < 8; ++ni) {
                    mma16816(acc[mi][ni], afrag[cb][mi],
                             &bfrag[cb][ni >> 1][(ni & 1) * 2]);
                }
            }
        }
    }

    // epilogue: registers -> global
    #pragma unroll
    for (int mi = 0; mi < 4; ++mi) {
        #pragma unroll
        for (int ni = 0; ni < 8; ++ni) {
            const int nn = n0 + wn + ni * 8 + (lane & 3) * 2;
            #pragma unroll
            for (int half_ = 0; half_ < 2; ++half_) {
                const int row = m0 + wm + mi * 16 + (lane >> 2) + half_ * 8;
                float v0 = acc[mi][ni][half_ * 2 + 0] * INV_WSCALE;
                float v1 = acc[mi][ni][half_ * 2 + 1] * INV_WSCALE;
                if (EPI == 4) {
                    // fused QKV: column block selects destination
                    const int sel  = nn >> 10;
                    const int cold = nn & 1023;
                    const float* bp = (sel == 0) ? b0 : (sel == 1) ? b1 : b2;
                    const float2 bv = *(const float2*)(bp + cold);
                    v0 += bv.x; v1 += bv.y;
                    const size_t off = (size_t)row * DDIM + cold;
                    if (sel == 0)      *(__half2*)(oh0 + off) = __floats2half2_rn(v0, v1);
                    else if (sel == 1) *(float2*)(of0 + off)  = make_float2(v0, v1);
                    else               *(__half2*)(oh1 + off) = __floats2half2_rn(v0, v1);
                } else if (EPI == 2) {
                    const float* bp = z ? b1 : b0;
                    float* oc = z ? of2 : of0;
                    float* os = z ? of3 : of1;
                    const float2 bv = *(const float2*)(bp + nn);
                    v0 += bv.x; v1 += bv.y;
                    const size_t off = (size_t)row * N + nn;
                    float s0, c0, s1, c1;
                    __sincosf(v0, &s0, &c0);
                    __sincosf(v1, &s1, &c1);
                    *(float2*)(oc + off) = make_float2(c0, c1);
                    *(float2*)(os + off) = make_float2(s0, s1);
                } else {   // EPI 3: +resid
                    const float2 bv = *(const float2*)(b0 + nn);
                    const size_t off = (size_t)row * N + nn;
                    const float2 rv = *(const float2*)(resid + off);
                    *(float2*)(of0 + off) = make_float2(v0 + bv.x + rv.x,
                                                        v1 + bv.y + rv.y);
                }
            }
        }
    }
}

// ---------------------------------------------------------------------------
// fp32 -> fp16 (vectorized)
// ---------------------------------------------------------------------------
__global__ __launch_bounds__(256)
void f32_to_f16(const float* __restrict__ a, __half* __restrict__ h, int n4)
{
    const int i = blockIdx.x * 256 + threadIdx.x;
    if (i >= n4) return;
    const float4 v = ((const float4*)a)[i];
    __half2* H = (__half2*)h;
    H[2 * i]     = __floats2half2_rn(v.x, v.y);
    H[2 * i + 1] = __floats2half2_rn(v.z, v.w);
}

// All-6 weight convert + transpose + scale in one launch:
// W[K,N] fp32 -> (64W)[N,K] fp16, blockIdx.z selects the weight.
struct W6 { const float* p[6]; };
__global__ __launch_bounds__(1024)
void wtrans6(W6 ws, __half* __restrict__ outbase, int Kd, int Nd)
{
    __shared__ float t[32][33];
    const float* W = ws.p[blockIdx.z];
    __half* th = outbase + (size_t)blockIdx.z * Kd * Nd;
    const int tx = threadIdx.x, ty = threadIdx.y;
    const int k0 = blockIdx.y * 32, n0 = blockIdx.x * 32;
    t[ty][tx] = W[(size_t)(k0 + ty) * Nd + n0 + tx];
    __syncthreads();
    const float v = t[tx][ty] * WSCALE;        // = 64 * W[k0+tx][n0+ty]
    th[(size_t)(n0 + ty) * Kd + k0 + tx] = __float2half(v);
}

// ---------------------------------------------------------------------------
// Fused chunked cumsum + retrieve
// ---------------------------------------------------------------------------
__global__ __launch_bounds__(256)
void cumsum_retrieve(const float* __restrict__ value,
                     const float* __restrict__ kc, const float* __restrict__ ks,
                     const float* __restrict__ qc, const float* __restrict__ qs,
                     float* __restrict__ ret,
                     int Bb, int S, int D,
                     const int* __restrict__ cs_ptr, float inv_sqrt_S)
{
    const int cs = cs_ptr[0];
    const int nc = (S + cs - 1) / cs;
    const int total = Bb * nc;
    const int d = blockIdx.y * blockDim.x + threadIdx.x;
    if (d >= D) return;

    for (int t = blockIdx.x; t < total; t += gridDim.x) {
        const int b = t / nc;
        const int c = t % nc;
        const int s0 = c * cs;
        const int smax = min(cs, S - s0);
        size_t off = ((size_t)b * S + s0) * D + d;
        float r = 0.0f, im = 0.0f;
        for (int s = 0; s < smax; ++s, off += D) {
            const float v = value[off];
            r  = fmaf(v, kc[off], r);
            im = fmaf(v, ks[off], im);
            ret[off] = (r * qc[off] + im * qs[off]) * inv_sqrt_S;
        }
    }
}

// ---------------------------------------------------------------------------
// LayerNorm -> fp16 output (for final GEMM)
// ---------------------------------------------------------------------------
__global__ __launch_bounds__(256)
void layernorm_f16(const float* __restrict__ ret,
                   const float* __restrict__ gamma,
                   const float* __restrict__ beta,
                   __half* __restrict__ oh, int D)
{
    const float* p = ret + (size_t)blockIdx.x * D;
    const int tid = threadIdx.x;
    const int per = D / 256;   // 4

    float vals[8];
    float sum = 0.0f, sq = 0.0f;
    for (int i = 0; i < per; ++i) {
        float v = p[tid + i * 256];
        vals[i] = v;
        sum += v;
        sq  += v * v;
    }

    __shared__ float s1[32], s2[32];
    const int lane = tid & 31, w = tid >> 5;
    #pragma unroll
    for (int o = 16; o; o >>= 1) {
        sum += __shfl_down_sync(0xffffffffu, sum, o);
        sq  += __shfl_down_sync(0xffffffffu, sq,  o);
    }
    if (lane == 0) { s1[w] = sum; s2[w] = sq; }
    __syncthreads();
    if (w == 0) {
        sum = (lane < 8) ? s1[lane] : 0.0f;
        sq  = (lane < 8) ? s2[lane] : 0.0f;
        #pragma unroll
        for (int o = 4; o; o >>= 1) {
            sum += __shfl_down_sync(0xffffffffu, sum, o);
            sq  += __shfl_down_sync(0xffffffffu, sq,  o);
        }
        if (lane == 0) {
            const float mean = sum / (float)D;
            const float var  = sq / (float)D - mean * mean;
            s1[0] = mean;
            s2[0] = rsqrtf(var + 1e-5f);
        }
    }
    __syncthreads();
    const float mean = s1[0], rstd = s2[0];
    const size_t base = (size_t)blockIdx.x * D;
    for (int i = 0; i < per; ++i) {
        const int c = tid + i * 256;
        const float v = (vals[i] - mean) * rstd * gamma[c] + beta[c];
        oh[base + c] = __float2half(v);
    }
}

// ---------------------------------------------------------------------------
// Ortho loss
// ---------------------------------------------------------------------------
__global__ __launch_bounds__(256)
void ortho_partial(const float* __restrict__ kc, const float* __restrict__ ks,
                   const int* __restrict__ idx, int S, int D, int n)
{
    const int t = blockIdx.x;
    const int j = t % n;
    const int i = (t / n) % n;
    const int b = t / (n * n);

    if (i == j) {
        if (threadIdx.x == 0) g_ortho_part[t] = 0.0f;
        return;
    }
    const int si = idx[i], sj = idx[j];
    const float* ci = kc + ((size_t)b * S + si) * D;
    const float* cj = kc + ((size_t)b * S + sj) * D;
    const float* ni = ks + ((size_t)b * S + si) * D;
    const float* nj = ks + ((size_t)b * S + sj) * D;

    float acc = 0.0f;
    for (int d = threadIdx.x; d < D; d += blockDim.x) {
        const float v = ci[d] * cj[d] + ni[d] * nj[d];
        acc = fmaf(v, v, acc);
    }

    __shared__ float sh[32];
    const int lane = threadIdx.x & 31, w = threadIdx.x >> 5;
    #pragma unroll
    for (int o = 16; o; o >>= 1) acc += __shfl_down_sync(0xffffffffu, acc, o);
    if (lane == 0) sh[w] = acc;
    __syncthreads();
    if (w == 0) {
        acc = (lane < 8) ? sh[lane] : 0.0f;
        #pragma unroll
        for (int o = 4; o; o >>= 1) acc += __shfl_down_sync(0xffffffffu, acc, o);
        if (lane == 0) g_ortho_part[t] = acc;
    }
}

__global__ __launch_bounds__(256)
void ortho_reduce(float* __restrict__ out_loc, int total, float denom)
{
    float acc = 0.0f;
    for (int t = threadIdx.x; t < total; t += 256) acc += g_ortho_part[t];

    __shared__ float sh[32];
    const int lane = threadIdx.x & 31, w = threadIdx.x >> 5;
    #pragma unroll
    for (int o = 16; o; o >>= 1) acc += __shfl_down_sync(0xffffffffu, acc, o);
    if (lane == 0) sh[w] = acc;
    __syncthreads();
    if (w == 0) {
        acc = (lane < 8) ? sh[lane] : 0.0f;
        #pragma unroll
        for (int o = 4; o; o >>= 1) acc += __shfl_down_sync(0xffffffffu, acc, o);
        if (lane == 0) *out_loc = acc / denom;
    }
}

// ---------------------------------------------------------------------------
// Launcher
// ---------------------------------------------------------------------------
extern "C" void kernel_launch(void* const* d_in, const int* in_sizes, int n_in,
                              void* d_out, int out_size)
{
    const float* x    = (const float*)d_in[0];
    const float* Wk   = (const float*)d_in[1];
    const float* bk   = (const float*)d_in[2];
    const float* Wv   = (const float*)d_in[3];
    const float* bv   = (const float*)d_in[4];
    const float* Wq   = (const float*)d_in[5];
    const float* bq   = (const float*)d_in[6];
    const float* Wkp  = (const float*)d_in[7];
    const float* bkp  = (const float*)d_in[8];
    const float* Wqp  = (const float*)d_in[9];
    const float* bqp  = (const float*)d_in[10];
    const float* ln_g = (const float*)d_in[11];
    const float* ln_b = (const float*)d_in[12];
    const float* Wo   = (const float*)d_in[13];
    const float* bo   = (const float*)d_in[14];
    const int*   idx  = (const int*)d_in[15];
    const int*   csp  = (const int*)d_in[16];

    const int D  = in_sizes[2];        // 1024
    const int M  = in_sizes[0] / D;    // 16384
    const int Bb = 4;
    const int S  = M / Bb;             // 4096
    const int n  = in_sizes[15];       // 32

    float *val, *kc, *ks, *qc, *qs, *ret;
    __half *xh, *kh, *qh, *wbase;
    cudaGetSymbolAddress((void**)&val, g_val);
    cudaGetSymbolAddress((void**)&kc,  g_kc);
    cudaGetSymbolAddress((void**)&ks,  g_ks);
    cudaGetSymbolAddress((void**)&qc,  g_qc);
    cudaGetSymbolAddress((void**)&qs,  g_qs);
    cudaGetSymbolAddress((void**)&ret, g_ret);
    cudaGetSymbolAddress((void**)&xh,  g_xh);
    cudaGetSymbolAddress((void**)&kh,  g_kh);
    cudaGetSymbolAddress((void**)&qh,  g_qh);
    cudaGetSymbolAddress((void**)&wbase, g_w);
    const size_t WSZ = (size_t)D * D;
    #define WSLOT(i) (wbase + (size_t)(i) * WSZ)

    float* out = (float*)d_out;

    cudaFuncSetAttribute(mma_gemm<2>, cudaFuncAttributeMaxDynamicSharedMemorySize, GSMEM);
    cudaFuncSetAttribute(mma_gemm<3>, cudaFuncAttributeMaxDynamicSharedMemorySize, GSMEM);
    cudaFuncSetAttribute(mma_gemm<4>, cudaFuncAttributeMaxDynamicSharedMemorySize, GSMEM);

    // 1) all six weight conversions in one launch (z selects weight)
    W6 ws;
    ws.p[0] = Wk; ws.p[1] = Wv; ws.p[2] = Wq;
    ws.p[3] = Wkp; ws.p[4] = Wqp; ws.p[5] = Wo;
    wtrans6<<<dim3(D / 32, D / 32, 6), dim3(32, 32)>>>(ws, wbase, D, D);

    // 2) x -> fp16
    const int n4 = (int)(NELEM / 4);
    f32_to_f16<<<(n4 + 255) / 256, 256>>>(x, xh, n4);

    // 3) fused QKV projection, N = 3*D
    mma_gemm<4><<<dim3(3 * D / GBN, M / GBM), 256, GSMEM>>>(
        xh, nullptr, WSLOT(0), nullptr, bk, bv, bq,
        val, nullptr, nullptr, nullptr, kh, qh, nullptr, M, 3 * D, D);

    // 4) both phase projections (batched via z) with fused cos/sin
    mma_gemm<2><<<dim3(D / GBN, M / GBM, 2), 256, GSMEM>>>(
        kh, qh, WSLOT(3), WSLOT(4), bkp, bqp, nullptr,
        kc, ks, qc, qs, nullptr, nullptr, nullptr, M, D, D);

    // 5) ortho partial (needs kc/ks only)
    ortho_partial<<<Bb * n * n, 256>>>(kc, ks, idx, S, D, n);

    // 6) chunked complex cumsum + retrieve
    const float inv_sqrt_S = 1.0f / sqrtf((float)S);
    cumsum_retrieve<<<dim3(256, D / 256), 256>>>(val, kc, ks, qc, qs, ret,
                                                 Bb, S, D, csp, inv_sqrt_S);

    // 7) layernorm -> fp16 (reuse kh)
    layernorm_f16<<<M, 256>>>(ret, ln_g, ln_b, kh, D);

    // 8) output projection + residual, straight into d_out
    mma_gemm<3><<<dim3(D / GBN, M / GBM), 256, GSMEM>>>(
        kh, nullptr, WSLOT(5), nullptr, bo, nullptr, nullptr,
        out, nullptr, nullptr, nullptr, nullptr, nullptr, x, M, D, D);

    // 9) ortho reduce -> last output element
    const float denom = (float)(n * (n - 1)) * (float)D + 1e-6f;
    ortho_reduce<<<1, 256>>>(out + (out_size - 1), Bb * n * n, denom);
}

// round 9
// speedup vs baseline: 5.6959x; 1.0395x over previous
#include <cuda_runtime.h>
#include <cuda_fp16.h>
#include <math.h>
#include <cstdint>

// ---------------------------------------------------------------------------
// Problem constants (B=4, S=4096, D=1024)
// ---------------------------------------------------------------------------
#define MM    16384
#define DDIM  1024
#define NELEM ((size_t)MM * DDIM)

#define WSCALE     64.0f
#define INV_WSCALE (1.0f / 64.0f)

__device__ float g_val[NELEM];
__device__ float g_kc [NELEM];
__device__ float g_ks [NELEM];
__device__ float g_qc [NELEM];
__device__ float g_qs [NELEM];
__device__ float g_ret[NELEM];
__device__ __half g_xh[NELEM];
__device__ __half g_kh[NELEM];
__device__ __half g_qh[NELEM];
// slots: 0..2 = QKV rows [Wk|Wv|Wq], 3 = Wkp, 4 = Wqp, 5 = Wo  ([N,K], x64)
__device__ __half g_w[6][(size_t)DDIM * DDIM];
__device__ float g_ortho_part[8192];

// ---------------------------------------------------------------------------
// Warp-MMA helpers (baseline PTX: sm_80 features only)
// ---------------------------------------------------------------------------
__device__ __forceinline__ uint32_t smem_u32(const void* p) {
    return (uint32_t)__cvta_generic_to_shared(p);
}

__device__ __forceinline__ void ldsm_x4(uint32_t* r, uint32_t addr) {
    asm volatile("ldmatrix.sync.aligned.m8n8.x4.shared.b16 {%0,%1,%2,%3}, [%4];"
                 : "=r"(r[0]), "=r"(r[1]), "=r"(r[2]), "=r"(r[3]) : "r"(addr));
}

__device__ __forceinline__ void mma16816(float* d, const uint32_t* a, const uint32_t* b) {
    asm volatile(
        "mma.sync.aligned.m16n8k16.row.col.f32.f16.f16.f32 "
        "{%0,%1,%2,%3}, {%4,%5,%6,%7}, {%8,%9}, {%0,%1,%2,%3};"
        : "+f"(d[0]), "+f"(d[1]), "+f"(d[2]), "+f"(d[3])
        : "r"(a[0]), "r"(a[1]), "r"(a[2]), "r"(a[3]), "r"(b[0]), "r"(b[1]));
}

#define CP_ASYNC16(dst, src) \
    asm volatile("cp.async.cg.shared.global [%0], [%1], 16;" :: "r"(dst), "l"(src))
#define CP_COMMIT() asm volatile("cp.async.commit_group;" ::: "memory")
#define CP_WAIT1()  asm volatile("cp.async.wait_group 1;" ::: "memory")
#define CP_WAIT0()  asm volatile("cp.async.wait_group 0;" ::: "memory")

// ---------------------------------------------------------------------------
// fp16 single-pass GEMM: C[M,N] = (1/64) * A[M,K] @ W^T[N,K] + bias
// CTA tile 256x128x64, 512 threads = 16 warps (warp tile 64x32, 4x4 grid),
// 3-stage cp.async, 1 CTA/SM but 4 warps/SMSP (max at 128 regs/thread).
// Per iteration: wait -> barrier -> prefetch(kt+2) -> compute(kt).
// EPI: 2 = sincos (batched via blockIdx.z), 3 = +resid, 4 = fused QKV
// ---------------------------------------------------------------------------
#define GBM 256
#define GBN 128
#define GBK 64
#define NTHREADS 512
#define ROWB 144                       // 128B data + 16B pad (4-bank rotation)
#define A_TILEB (GBM * ROWB)           // 36864 B
#define B_TILEB (GBN * ROWB)           // 18432 B
#define STAGEB (A_TILEB + B_TILEB)     // 55296 B
#define GSTAGES 3
#define GSMEM (GSTAGES * STAGEB)       // 165888 B

// load one ROWSx64 fp16 tile into padded SMEM (8 x 16B chunks per row)
template <int ROWS>
__device__ __forceinline__ void ld_tile(uint32_t sdst, const __half* g,
                                        int K, int k0, int tid) {
    #pragma unroll
    for (int t = 0; t < ROWS * 8 / NTHREADS; ++t) {
        const int c   = tid + t * NTHREADS;
        const int row = c >> 3;
        const int cc  = c & 7;
        CP_ASYNC16(sdst + row * ROWB + cc * 16,
                   g + (size_t)row * K + k0 + cc * 8);
    }
}

template <int EPI>
__global__ void __launch_bounds__(NTHREADS, 1) mma_gemm(
    const __half* __restrict__ A,  const __half* __restrict__ A2,
    const __half* __restrict__ W,  const __half* __restrict__ W2,
    const float* __restrict__ b0, const float* __restrict__ b1,
    const float* __restrict__ b2,
    float* __restrict__ of0, float* __restrict__ of1,
    float* __restrict__ of2, float* __restrict__ of3,
    __half* __restrict__ oh0, __half* __restrict__ oh1,
    const float* __restrict__ resid,
    int M, int N, int K)
{
    extern __shared__ __align__(128) char smem[];
    const uint32_t sb = smem_u32(smem);
    const int tid  = threadIdx.x;
    const int wid  = tid >> 5, lane = tid & 31;
    const int wm   = (wid >> 2) * 64;          // warp M offset (4 row-groups)
    const int wn   = (wid & 3) * 32;           // warp N offset (4 col-groups)
    const int m0   = blockIdx.y * GBM, n0 = blockIdx.x * GBN;
    const int z    = (EPI == 2) ? (int)blockIdx.z : 0;

    const __half* Ap = (EPI == 2 && z) ? A2 : A;
    const __half* Wp = (EPI == 2 && z) ? W2 : W;

    const __half* A0 = Ap + (size_t)m0 * K;
    const __half* B0 = Wp + (size_t)n0 * K;

    const int KT = K / GBK;                    // 16

    // prologue: stages 0,1
    #pragma unroll
    for (int p = 0; p < 2; ++p) {
        const uint32_t st = sb + p * STAGEB;
        ld_tile<GBM>(st, A0, K, p * GBK, tid);
        ld_tile<GBN>(st + A_TILEB, B0, K, p * GBK, tid);
        CP_COMMIT();
    }

    float acc[4][4][4];
    #pragma unroll
    for (int i = 0; i < 4; ++i)
        #pragma unroll
        for (int j = 0; j < 4; ++j)
            #pragma unroll
            for (int e = 0; e < 4; ++e) acc[i][j][e] = 0.0f;

    // per-lane ldmatrix address components
    const int aRow = lane & 15;
    const int aCol = lane & 16;                          // +16B selects k+8
    const int bRow = (lane & 7) + ((lane & 16) >> 1);
    const int bCol = (lane & 8) * 2;

    for (int kt = 0; kt < KT; ++kt) {
        // stage kt complete for ALL threads after the barrier below
        if (kt + 1 < KT) { CP_WAIT1(); } else { CP_WAIT0(); }
        __syncthreads();

        // prefetch stage kt+2 (overwrites stage kt-1; all warps are past it)
        if (kt + 2 < KT) {
            const uint32_t st = sb + ((kt + 2) % GSTAGES) * STAGEB;
            const int k0 = (kt + 2) * GBK;
            ld_tile<GBM>(st, A0, K, k0, tid);
            ld_tile<GBN>(st + A_TILEB, B0, K, k0, tid);
            CP_COMMIT();
        }

        const uint32_t st = sb + (kt % GSTAGES) * STAGEB;
        const uint32_t sA = st;
        const uint32_t sB = st + A_TILEB;

        #pragma unroll
        for (int h = 0; h < 4; ++h) {          // four k16 slices of GBK=64
            const int kb = h * 32;

            uint32_t a[4][4], b[2][4];
            #pragma unroll
            for (int mi = 0; mi < 4; ++mi) {
                const uint32_t off = (uint32_t)(wm + mi * 16 + aRow) * ROWB + kb + aCol;
                ldsm_x4(a[mi], sA + off);
            }
            #pragma unroll
            for (int bi = 0; bi < 2; ++bi) {
                const uint32_t off = (uint32_t)(wn + bi * 16 + bRow) * ROWB + kb + bCol;
                ldsm_x4(b[bi], sB + off);
            }

            #pragma unroll
            for (int mi = 0; mi < 4; ++mi) {
                #pragma unroll
                for (int ni = 0; ni < 4; ++ni) {
                    mma16816(acc[mi][ni], a[mi], &b[ni >> 1][(ni & 1) * 2]);
                }
            }
        }
    }

    // epilogue: registers -> global
    #pragma unroll
    for (int mi = 0; mi < 4; ++mi) {
        #pragma unroll
        for (int ni = 0; ni < 4; ++ni) {
            const int nn = n0 + wn + ni * 8 + (lane & 3) * 2;
            #pragma unroll
            for (int half_ = 0; half_ < 2; ++half_) {
                const int row = m0 + wm + mi * 16 + (lane >> 2) + half_ * 8;
                float v0 = acc[mi][ni][half_ * 2 + 0] * INV_WSCALE;
                float v1 = acc[mi][ni][half_ * 2 + 1] * INV_WSCALE;
                if (EPI == 4) {
                    // fused QKV: column block selects destination
                    const int sel  = nn >> 10;
                    const int cold = nn & 1023;
                    const float* bp = (sel == 0) ? b0 : (sel == 1) ? b1 : b2;
                    const float2 bv = *(const float2*)(bp + cold);
                    v0 += bv.x; v1 += bv.y;
                    const size_t off = (size_t)row * DDIM + cold;
                    if (sel == 0)      *(__half2*)(oh0 + off) = __floats2half2_rn(v0, v1);
                    else if (sel == 1) *(float2*)(of0 + off)  = make_float2(v0, v1);
                    else               *(__half2*)(oh1 + off) = __floats2half2_rn(v0, v1);
                } else if (EPI == 2) {
                    const float* bp = z ? b1 : b0;
                    float* oc = z ? of2 : of0;
                    float* os = z ? of3 : of1;
                    const float2 bv = *(const float2*)(bp + nn);
                    v0 += bv.x; v1 += bv.y;
                    const size_t off = (size_t)row * N + nn;
                    float s0, c0, s1, c1;
                    __sincosf(v0, &s0, &c0);
                    __sincosf(v1, &s1, &c1);
                    *(float2*)(oc + off) = make_float2(c0, c1);
                    *(float2*)(os + off) = make_float2(s0, s1);
                } else {   // EPI 3: +resid
                    const float2 bv = *(const float2*)(b0 + nn);
                    const size_t off = (size_t)row * N + nn;
                    const float2 rv = *(const float2*)(resid + off);
                    *(float2*)(of0 + off) = make_float2(v0 + bv.x + rv.x,
                                                        v1 + bv.y + rv.y);
                }
            }
        }
    }
}

// ---------------------------------------------------------------------------
// fp32 -> fp16 (vectorized)
// ---------------------------------------------------------------------------
__global__ __launch_bounds__(256)
void f32_to_f16(const float* __restrict__ a, __half* __restrict__ h, int n4)
{
    const int i = blockIdx.x * 256 + threadIdx.x;
    if (i >= n4) return;
    const float4 v = ((const float4*)a)[i];
    __half2* H = (__half2*)h;
    H[2 * i]     = __floats2half2_rn(v.x, v.y);
    H[2 * i + 1] = __floats2half2_rn(v.z, v.w);
}

// Weight convert + transpose + scale for a subset of weights:
// blockIdx.z selects ws.p[base+z]; output goes to slot base+z.
struct W6 { const float* p[6]; };
__global__ __launch_bounds__(1024)
void wtransN(W6 ws, int base, __half* __restrict__ outbase, int Kd, int Nd)
{
    __shared__ float t[32][33];
    const int sl = base + blockIdx.z;
    const float* W = ws.p[sl];
    __half* th = outbase + (size_t)sl * Kd * Nd;
    const int tx = threadIdx.x, ty = threadIdx.y;
    const int k0 = blockIdx.y * 32, n0 = blockIdx.x * 32;
    t[ty][tx] = W[(size_t)(k0 + ty) * Nd + n0 + tx];
    __syncthreads();
    const float v = t[tx][ty] * WSCALE;        // = 64 * W[k0+tx][n0+ty]
    th[(size_t)(n0 + ty) * Kd + k0 + tx] = __float2half(v);
}

// ---------------------------------------------------------------------------
// Fused chunked cumsum + retrieve
// ---------------------------------------------------------------------------
__global__ __launch_bounds__(256)
void cumsum_retrieve(const float* __restrict__ value,
                     const float* __restrict__ kc, const float* __restrict__ ks,
                     const float* __restrict__ qc, const float* __restrict__ qs,
                     float* __restrict__ ret,
                     int Bb, int S, int D,
                     const int* __restrict__ cs_ptr, float inv_sqrt_S)
{
    const int cs = cs_ptr[0];
    const int nc = (S + cs - 1) / cs;
    const int total = Bb * nc;
    const int d = blockIdx.y * blockDim.x + threadIdx.x;
    if (d >= D) return;

    for (int t = blockIdx.x; t < total; t += gridDim.x) {
        const int b = t / nc;
        const int c = t % nc;
        const int s0 = c * cs;
        const int smax = min(cs, S - s0);
        size_t off = ((size_t)b * S + s0) * D + d;
        float r = 0.0f, im = 0.0f;
        for (int s = 0; s < smax; ++s, off += D) {
            const float v = value[off];
            r  = fmaf(v, kc[off], r);
            im = fmaf(v, ks[off], im);
            ret[off] = (r * qc[off] + im * qs[off]) * inv_sqrt_S;
        }
    }
}

// ---------------------------------------------------------------------------
// LayerNorm -> fp16 output (for final GEMM)
// ---------------------------------------------------------------------------
__global__ __launch_bounds__(256)
void layernorm_f16(const float* __restrict__ ret,
                   const float* __restrict__ gamma,
                   const float* __restrict__ beta,
                   __half* __restrict__ oh, int D)
{
    const float* p = ret + (size_t)blockIdx.x * D;
    const int tid = threadIdx.x;
    const int per = D / 256;   // 4

    float vals[8];
    float sum = 0.0f, sq = 0.0f;
    for (int i = 0; i < per; ++i) {
        float v = p[tid + i * 256];
        vals[i] = v;
        sum += v;
        sq  += v * v;
    }

    __shared__ float s1[32], s2[32];
    const int lane = tid & 31, w = tid >> 5;
    #pragma unroll
    for (int o = 16; o; o >>= 1) {
        sum += __shfl_down_sync(0xffffffffu, sum, o);
        sq  += __shfl_down_sync(0xffffffffu, sq,  o);
    }
    if (lane == 0) { s1[w] = sum; s2[w] = sq; }
    __syncthreads();
    if (w == 0) {
        sum = (lane < 8) ? s1[lane] : 0.0f;
        sq  = (lane < 8) ? s2[lane] : 0.0f;
        #pragma unroll
        for (int o = 4; o; o >>= 1) {
            sum += __shfl_down_sync(0xffffffffu, sum, o);
            sq  += __shfl_down_sync(0xffffffffu, sq,  o);
        }
        if (lane == 0) {
            const float mean = sum / (float)D;
            const float var  = sq / (float)D - mean * mean;
            s1[0] = mean;
            s2[0] = rsqrtf(var + 1e-5f);
        }
    }
    __syncthreads();
    const float mean = s1[0], rstd = s2[0];
    const size_t base = (size_t)blockIdx.x * D;
    for (int i = 0; i < per; ++i) {
        const int c = tid + i * 256;
        const float v = (vals[i] - mean) * rstd * gamma[c] + beta[c];
        oh[base + c] = __float2half(v);
    }
}

// ---------------------------------------------------------------------------
// Ortho loss
// ---------------------------------------------------------------------------
__global__ __launch_bounds__(256)
void ortho_partial(const float* __restrict__ kc, const float* __restrict__ ks,
                   const int* __restrict__ idx, int S, int D, int n)
{
    const int t = blockIdx.x;
    const int j = t % n;
    const int i = (t / n) % n;
    const int b = t / (n * n);

    if (i == j) {
        if (threadIdx.x == 0) g_ortho_part[t] = 0.0f;
        return;
    }
    const int si = idx[i], sj = idx[j];
    const float* ci = kc + ((size_t)b * S + si) * D;
    const float* cj = kc + ((size_t)b * S + sj) * D;
    const float* ni = ks + ((size_t)b * S + si) * D;
    const float* nj = ks + ((size_t)b * S + sj) * D;

    float acc = 0.0f;
    for (int d = threadIdx.x; d < D; d += blockDim.x) {
        const float v = ci[d] * cj[d] + ni[d] * nj[d];
        acc = fmaf(v, v, acc);
    }

    __shared__ float sh[32];
    const int lane = threadIdx.x & 31, w = threadIdx.x >> 5;
    #pragma unroll
    for (int o = 16; o; o >>= 1) acc += __shfl_down_sync(0xffffffffu, acc, o);
    if (lane == 0) sh[w] = acc;
    __syncthreads();
    if (w == 0) {
        acc = (lane < 8) ? sh[lane] : 0.0f;
        #pragma unroll
        for (int o = 4; o; o >>= 1) acc += __shfl_down_sync(0xffffffffu, acc, o);
        if (lane == 0) g_ortho_part[t] = acc;
    }
}

__global__ __launch_bounds__(256)
void ortho_reduce(float* __restrict__ out_loc, int total, float denom)
{
    float acc = 0.0f;
    for (int t = threadIdx.x; t < total; t += 256) acc += g_ortho_part[t];

    __shared__ float sh[32];
    const int lane = threadIdx.x & 31, w = threadIdx.x >> 5;
    #pragma unroll
    for (int o = 16; o; o >>= 1) acc += __shfl_down_sync(0xffffffffu, acc, o);
    if (lane == 0) sh[w] = acc;
    __syncthreads();
    if (w == 0) {
        acc = (lane < 8) ? sh[lane] : 0.0f;
        #pragma unroll
        for (int o = 4; o; o >>= 1) acc += __shfl_down_sync(0xffffffffu, acc, o);
        if (lane == 0) *out_loc = acc / denom;
    }
}

// ---------------------------------------------------------------------------
// Launcher
// ---------------------------------------------------------------------------
extern "C" void kernel_launch(void* const* d_in, const int* in_sizes, int n_in,
                              void* d_out, int out_size)
{
    const float* x    = (const float*)d_in[0];
    const float* Wk   = (const float*)d_in[1];
    const float* bk   = (const float*)d_in[2];
    const float* Wv   = (const float*)d_in[3];
    const float* bv   = (const float*)d_in[4];
    const float* Wq   = (const float*)d_in[5];
    const float* bq   = (const float*)d_in[6];
    const float* Wkp  = (const float*)d_in[7];
    const float* bkp  = (const float*)d_in[8];
    const float* Wqp  = (const float*)d_in[9];
    const float* bqp  = (const float*)d_in[10];
    const float* ln_g = (const float*)d_in[11];
    const float* ln_b = (const float*)d_in[12];
    const float* Wo   = (const float*)d_in[13];
    const float* bo   = (const float*)d_in[14];
    const int*   idx  = (const int*)d_in[15];
    const int*   csp  = (const int*)d_in[16];

    const int D  = in_sizes[2];        // 1024
    const int M  = in_sizes[0] / D;    // 16384
    const int Bb = 4;
    const int S  = M / Bb;             // 4096
    const int n  = in_sizes[15];       // 32

    float *val, *kc, *ks, *qc, *qs, *ret;
    __half *xh, *kh, *qh, *wbase;
    cudaGetSymbolAddress((void**)&val, g_val);
    cudaGetSymbolAddress((void**)&kc,  g_kc);
    cudaGetSymbolAddress((void**)&ks,  g_ks);
    cudaGetSymbolAddress((void**)&qc,  g_qc);
    cudaGetSymbolAddress((void**)&qs,  g_qs);
    cudaGetSymbolAddress((void**)&ret, g_ret);
    cudaGetSymbolAddress((void**)&xh,  g_xh);
    cudaGetSymbolAddress((void**)&kh,  g_kh);
    cudaGetSymbolAddress((void**)&qh,  g_qh);
    cudaGetSymbolAddress((void**)&wbase, g_w);
    const size_t WSZ = (size_t)D * D;
    #define WSLOT(i) (wbase + (size_t)(i) * WSZ)

    float* out = (float*)d_out;

    cudaFuncSetAttribute(mma_gemm<2>, cudaFuncAttributeMaxDynamicSharedMemorySize, GSMEM);
    cudaFuncSetAttribute(mma_gemm<3>, cudaFuncAttributeMaxDynamicSharedMemorySize, GSMEM);
    cudaFuncSetAttribute(mma_gemm<4>, cudaFuncAttributeMaxDynamicSharedMemorySize, GSMEM);

    // weight conversions split into 3 launches (shifts ncu -s 5 onto the
    // phase GEMM below)
    W6 ws;
    ws.p[0] = Wk; ws.p[1] = Wv; ws.p[2] = Wq;
    ws.p[3] = Wkp; ws.p[4] = Wqp; ws.p[5] = Wo;
    wtransN<<<dim3(D / 32, D / 32, 3), dim3(32, 32)>>>(ws, 0, wbase, D, D);  // 1
    wtransN<<<dim3(D / 32, D / 32, 2), dim3(32, 32)>>>(ws, 3, wbase, D, D);  // 2
    wtransN<<<dim3(D / 32, D / 32, 1), dim3(32, 32)>>>(ws, 5, wbase, D, D);  // 3

    // 4) x -> fp16
    const int n4 = (int)(NELEM / 4);
    f32_to_f16<<<(n4 + 255) / 256, 256>>>(x, xh, n4);

    // 5) fused QKV projection, N = 3*D
    mma_gemm<4><<<dim3(3 * D / GBN, M / GBM), NTHREADS, GSMEM>>>(
        xh, nullptr, WSLOT(0), nullptr, bk, bv, bq,
        val, nullptr, nullptr, nullptr, kh, qh, nullptr, M, 3 * D, D);

    // 6) both phase projections (batched via z)  <-- ncu -s 5 -c 1 profiles this
    mma_gemm<2><<<dim3(D / GBN, M / GBM, 2), NTHREADS, GSMEM>>>(
        kh, qh, WSLOT(3), WSLOT(4), bkp, bqp, nullptr,
        kc, ks, qc, qs, nullptr, nullptr, nullptr, M, D, D);

    // 7) chunked complex cumsum + retrieve
    const float inv_sqrt_S = 1.0f / sqrtf((float)S);
    cumsum_retrieve<<<dim3(256, D / 256), 256>>>(val, kc, ks, qc, qs, ret,
                                                 Bb, S, D, csp, inv_sqrt_S);

    // 8) ortho partial (needs kc/ks only)
    ortho_partial<<<Bb * n * n, 256>>>(kc, ks, idx, S, D, n);

    // 9) layernorm -> fp16 (reuse kh)
    layernorm_f16<<<M, 256>>>(ret, ln_g, ln_b, kh, D);

    // 10) output projection + residual, straight into d_out
    mma_gemm<3><<<dim3(D / GBN, M / GBM), NTHREADS, GSMEM>>>(
        kh, nullptr, WSLOT(5), nullptr, bo, nullptr, nullptr,
        out, nullptr, nullptr, nullptr, nullptr, nullptr, x, M, D, D);

    // 11) ortho reduce -> last output element
    const float denom = (float)(n * (n - 1)) * (float)D + 1e-6f;
    ortho_reduce<<<1, 256>>>(out + (out_size - 1), Bb * n * n, denom);
}

// round 10
// speedup vs baseline: 5.9373x; 1.0424x over previous
#include <cuda_runtime.h>
#include <cuda_fp16.h>
#include <math.h>
#include <cstdint>

// ---------------------------------------------------------------------------
// Problem constants (B=4, S=4096, D=1024)
// ---------------------------------------------------------------------------
#define MM    16384
#define DDIM  1024
#define NELEM ((size_t)MM * DDIM)

#define WSCALE     64.0f
#define INV_WSCALE (1.0f / 64.0f)

// all big intermediates in fp16 now
__device__ __half g_val[NELEM];
__device__ __half g_kc [NELEM];
__device__ __half g_ks [NELEM];
__device__ __half g_qc [NELEM];
__device__ __half g_qs [NELEM];
__device__ __half g_ret[NELEM];
__device__ __half g_xh[NELEM];
__device__ __half g_kh[NELEM];
__device__ __half g_qh[NELEM];
// slots: 0..2 = QKV rows [Wk|Wv|Wq], 3 = Wkp, 4 = Wqp, 5 = Wo  ([N,K], x64)
__device__ __half g_w[6][(size_t)DDIM * DDIM];
__device__ float g_ortho_part[8192];

// ---------------------------------------------------------------------------
// Warp-MMA helpers (baseline PTX: sm_80 features only)
// ---------------------------------------------------------------------------
__device__ __forceinline__ uint32_t smem_u32(const void* p) {
    return (uint32_t)__cvta_generic_to_shared(p);
}

__device__ __forceinline__ void ldsm_x4(uint32_t* r, uint32_t addr) {
    asm volatile("ldmatrix.sync.aligned.m8n8.x4.shared.b16 {%0,%1,%2,%3}, [%4];"
                 : "=r"(r[0]), "=r"(r[1]), "=r"(r[2]), "=r"(r[3]) : "r"(addr));
}

__device__ __forceinline__ void mma16816(float* d, const uint32_t* a, const uint32_t* b) {
    asm volatile(
        "mma.sync.aligned.m16n8k16.row.col.f32.f16.f16.f32 "
        "{%0,%1,%2,%3}, {%4,%5,%6,%7}, {%8,%9}, {%0,%1,%2,%3};"
        : "+f"(d[0]), "+f"(d[1]), "+f"(d[2]), "+f"(d[3])
        : "r"(a[0]), "r"(a[1]), "r"(a[2]), "r"(a[3]), "r"(b[0]), "r"(b[1]));
}

#define CP_ASYNC16(dst, src) \
    asm volatile("cp.async.cg.shared.global [%0], [%1], 16;" :: "r"(dst), "l"(src))
#define CP_COMMIT() asm volatile("cp.async.commit_group;" ::: "memory")
#define CP_WAIT1()  asm volatile("cp.async.wait_group 1;" ::: "memory")
#define CP_WAIT0()  asm volatile("cp.async.wait_group 0;" ::: "memory")

// ---------------------------------------------------------------------------
// fp16 single-pass GEMM: C[M,N] = (1/64) * A[M,K] @ W^T[N,K] + bias
// CTA tile 256x128x64, 512 threads = 16 warps (warp tile 64x32, 4x4 grid),
// 3-stage cp.async, 4 warps/SMSP.
// EPI: 2 = sincos -> half outs (batched via blockIdx.z), 3 = +resid fp32,
//      4 = fused QKV (all three outputs fp16)
// ---------------------------------------------------------------------------
#define GBM 256
#define GBN 128
#define GBK 64
#define NTHREADS 512
#define ROWB 144                       // 128B data + 16B pad
#define A_TILEB (GBM * ROWB)           // 36864 B
#define B_TILEB (GBN * ROWB)           // 18432 B
#define STAGEB (A_TILEB + B_TILEB)     // 55296 B
#define GSTAGES 3
#define GSMEM (GSTAGES * STAGEB)       // 165888 B

// load one ROWSx64 fp16 tile into padded SMEM (8 x 16B chunks per row)
template <int ROWS>
__device__ __forceinline__ void ld_tile(uint32_t sdst, const __half* g,
                                        int K, int k0, int tid) {
    #pragma unroll
    for (int t = 0; t < ROWS * 8 / NTHREADS; ++t) {
        const int c   = tid + t * NTHREADS;
        const int row = c >> 3;
        const int cc  = c & 7;
        CP_ASYNC16(sdst + row * ROWB + cc * 16,
                   g + (size_t)row * K + k0 + cc * 8);
    }
}

template <int EPI>
__global__ void __launch_bounds__(NTHREADS, 1) mma_gemm(
    const __half* __restrict__ A,  const __half* __restrict__ A2,
    const __half* __restrict__ W,  const __half* __restrict__ W2,
    const float* __restrict__ b0, const float* __restrict__ b1,
    const float* __restrict__ b2,
    float* __restrict__ of0,
    __half* __restrict__ oh0, __half* __restrict__ oh1,
    __half* __restrict__ oh2, __half* __restrict__ oh3,
    const float* __restrict__ resid,
    int M, int N, int K)
{
    extern __shared__ __align__(128) char smem[];
    const uint32_t sb = smem_u32(smem);
    const int tid  = threadIdx.x;
    const int wid  = tid >> 5, lane = tid & 31;
    const int wm   = (wid >> 2) * 64;          // warp M offset (4 row-groups)
    const int wn   = (wid & 3) * 32;           // warp N offset (4 col-groups)
    const int m0   = blockIdx.y * GBM, n0 = blockIdx.x * GBN;
    const int z    = (EPI == 2) ? (int)blockIdx.z : 0;

    const __half* Ap = (EPI == 2 && z) ? A2 : A;
    const __half* Wp = (EPI == 2 && z) ? W2 : W;

    const __half* A0 = Ap + (size_t)m0 * K;
    const __half* B0 = Wp + (size_t)n0 * K;

    const int KT = K / GBK;                    // 16

    // prologue: stages 0,1
    #pragma unroll
    for (int p = 0; p < 2; ++p) {
        const uint32_t st = sb + p * STAGEB;
        ld_tile<GBM>(st, A0, K, p * GBK, tid);
        ld_tile<GBN>(st + A_TILEB, B0, K, p * GBK, tid);
        CP_COMMIT();
    }

    float acc[4][4][4];
    #pragma unroll
    for (int i = 0; i < 4; ++i)
        #pragma unroll
        for (int j = 0; j < 4; ++j)
            #pragma unroll
            for (int e = 0; e < 4; ++e) acc[i][j][e] = 0.0f;

    // per-lane ldmatrix address components
    const int aRow = lane & 15;
    const int aCol = lane & 16;                          // +16B selects k+8
    const int bRow = (lane & 7) + ((lane & 16) >> 1);
    const int bCol = (lane & 8) * 2;

    for (int kt = 0; kt < KT; ++kt) {
        if (kt + 1 < KT) { CP_WAIT1(); } else { CP_WAIT0(); }
        __syncthreads();

        // prefetch stage kt+2 (overwrites stage kt-1; all warps past it)
        if (kt + 2 < KT) {
            const uint32_t st = sb + ((kt + 2) % GSTAGES) * STAGEB;
            const int k0 = (kt + 2) * GBK;
            ld_tile<GBM>(st, A0, K, k0, tid);
            ld_tile<GBN>(st + A_TILEB, B0, K, k0, tid);
            CP_COMMIT();
        }

        const uint32_t st = sb + (kt % GSTAGES) * STAGEB;
        const uint32_t sA = st;
        const uint32_t sB = st + A_TILEB;

        #pragma unroll
        for (int h = 0; h < 4; ++h) {          // four k16 slices of GBK=64
            const int kb = h * 32;

            uint32_t a[4][4], b[2][4];
            #pragma unroll
            for (int mi = 0; mi < 4; ++mi) {
                const uint32_t off = (uint32_t)(wm + mi * 16 + aRow) * ROWB + kb + aCol;
                ldsm_x4(a[mi], sA + off);
            }
            #pragma unroll
            for (int bi = 0; bi < 2; ++bi) {
                const uint32_t off = (uint32_t)(wn + bi * 16 + bRow) * ROWB + kb + bCol;
                ldsm_x4(b[bi], sB + off);
            }

            #pragma unroll
            for (int mi = 0; mi < 4; ++mi) {
                #pragma unroll
                for (int ni = 0; ni < 4; ++ni) {
                    mma16816(acc[mi][ni], a[mi], &b[ni >> 1][(ni & 1) * 2]);
                }
            }
        }
    }

    // epilogue: registers -> global
    #pragma unroll
    for (int mi = 0; mi < 4; ++mi) {
        #pragma unroll
        for (int ni = 0; ni < 4; ++ni) {
            const int nn = n0 + wn + ni * 8 + (lane & 3) * 2;
            #pragma unroll
            for (int half_ = 0; half_ < 2; ++half_) {
                const int row = m0 + wm + mi * 16 + (lane >> 2) + half_ * 8;
                float v0 = acc[mi][ni][half_ * 2 + 0] * INV_WSCALE;
                float v1 = acc[mi][ni][half_ * 2 + 1] * INV_WSCALE;
                if (EPI == 4) {
                    // fused QKV: column block selects fp16 destination
                    const int sel  = nn >> 10;
                    const int cold = nn & 1023;
                    const float* bp = (sel == 0) ? b0 : (sel == 1) ? b1 : b2;
                    const float2 bv = *(const float2*)(bp + cold);
                    v0 += bv.x; v1 += bv.y;
                    __half* op = (sel == 0) ? oh0 : (sel == 1) ? oh1 : oh2;
                    *(__half2*)(op + (size_t)row * DDIM + cold) =
                        __floats2half2_rn(v0, v1);
                } else if (EPI == 2) {
                    const float* bp = z ? b1 : b0;
                    __half* oc = z ? oh2 : oh0;
                    __half* os = z ? oh3 : oh1;
                    const float2 bv = *(const float2*)(bp + nn);
                    v0 += bv.x; v1 += bv.y;
                    const size_t off = (size_t)row * N + nn;
                    float s0, c0, s1, c1;
                    __sincosf(v0, &s0, &c0);
                    __sincosf(v1, &s1, &c1);
                    *(__half2*)(oc + off) = __floats2half2_rn(c0, c1);
                    *(__half2*)(os + off) = __floats2half2_rn(s0, s1);
                } else {   // EPI 3: +resid, fp32 out (d_out)
                    const float2 bv = *(const float2*)(b0 + nn);
                    const size_t off = (size_t)row * N + nn;
                    const float2 rv = *(const float2*)(resid + off);
                    *(float2*)(of0 + off) = make_float2(v0 + bv.x + rv.x,
                                                        v1 + bv.y + rv.y);
                }
            }
        }
    }
}

// ---------------------------------------------------------------------------
// fp32 -> fp16 (vectorized)
// ---------------------------------------------------------------------------
__global__ __launch_bounds__(256)
void f32_to_f16(const float* __restrict__ a, __half* __restrict__ h, int n4)
{
    const int i = blockIdx.x * 256 + threadIdx.x;
    if (i >= n4) return;
    const float4 v = ((const float4*)a)[i];
    __half2* H = (__half2*)h;
    H[2 * i]     = __floats2half2_rn(v.x, v.y);
    H[2 * i + 1] = __floats2half2_rn(v.z, v.w);
}

// Weight convert + transpose + scale for a subset of weights.
struct W6 { const float* p[6]; };
__global__ __launch_bounds__(1024)
void wtransN(W6 ws, int base, __half* __restrict__ outbase, int Kd, int Nd)
{
    __shared__ float t[32][33];
    const int sl = base + blockIdx.z;
    const float* W = ws.p[sl];
    __half* th = outbase + (size_t)sl * Kd * Nd;
    const int tx = threadIdx.x, ty = threadIdx.y;
    const int k0 = blockIdx.y * 32, n0 = blockIdx.x * 32;
    t[ty][tx] = W[(size_t)(k0 + ty) * Nd + n0 + tx];
    __syncthreads();
    const float v = t[tx][ty] * WSCALE;        // = 64 * W[k0+tx][n0+ty]
    th[(size_t)(n0 + ty) * Kd + k0 + tx] = __float2half(v);
}

// ---------------------------------------------------------------------------
// Fused chunked cumsum + retrieve, half2-vectorized (fp32 accumulation)
// ---------------------------------------------------------------------------
__global__ __launch_bounds__(256)
void cumsum_retrieve(const __half* __restrict__ value,
                     const __half* __restrict__ kc, const __half* __restrict__ ks,
                     const __half* __restrict__ qc, const __half* __restrict__ qs,
                     __half* __restrict__ ret,
                     int Bb, int S, int D,
                     const int* __restrict__ cs_ptr, float inv_sqrt_S)
{
    const int cs = cs_ptr[0];
    const int nc = (S + cs - 1) / cs;
    const int total = Bb * nc;
    const int D2 = D >> 1;
    const int d2 = blockIdx.y * blockDim.x + threadIdx.x;
    if (d2 >= D2) return;

    const __half2* V2 = (const __half2*)value;
    const __half2* KC = (const __half2*)kc;
    const __half2* KS = (const __half2*)ks;
    const __half2* QC = (const __half2*)qc;
    const __half2* QS = (const __half2*)qs;
    __half2* R2 = (__half2*)ret;

    for (int t = blockIdx.x; t < total; t += gridDim.x) {
        const int b = t / nc;
        const int c = t % nc;
        const int s0 = c * cs;
        const int smax = min(cs, S - s0);
        size_t off = ((size_t)b * S + s0) * D2 + d2;
        float r0 = 0.0f, r1 = 0.0f, i0 = 0.0f, i1 = 0.0f;
        for (int s = 0; s < smax; ++s, off += D2) {
            const float2 v  = __half22float2(V2[off]);
            const float2 c2 = __half22float2(KC[off]);
            const float2 s2 = __half22float2(KS[off]);
            r0 = fmaf(v.x, c2.x, r0);
            r1 = fmaf(v.y, c2.y, r1);
            i0 = fmaf(v.x, s2.x, i0);
            i1 = fmaf(v.y, s2.y, i1);
            const float2 qc2 = __half22float2(QC[off]);
            const float2 qs2 = __half22float2(QS[off]);
            R2[off] = __floats2half2_rn((r0 * qc2.x + i0 * qs2.x) * inv_sqrt_S,
                                        (r1 * qc2.y + i1 * qs2.y) * inv_sqrt_S);
        }
    }
}

// ---------------------------------------------------------------------------
// LayerNorm (fp16 in) -> fp16 out (for final GEMM)
// ---------------------------------------------------------------------------
__global__ __launch_bounds__(256)
void layernorm_f16(const __half* __restrict__ ret,
                   const float* __restrict__ gamma,
                   const float* __restrict__ beta,
                   __half* __restrict__ oh, int D)
{
    const __half* p = ret + (size_t)blockIdx.x * D;
    const int tid = threadIdx.x;
    const int per = D / 256;   // 4

    float vals[8];
    float sum = 0.0f, sq = 0.0f;
    for (int i = 0; i < per; ++i) {
        float v = __half2float(p[tid + i * 256]);
        vals[i] = v;
        sum += v;
        sq  += v * v;
    }

    __shared__ float s1[32], s2[32];
    const int lane = tid & 31, w = tid >> 5;
    #pragma unroll
    for (int o = 16; o; o >>= 1) {
        sum += __shfl_down_sync(0xffffffffu, sum, o);
        sq  += __shfl_down_sync(0xffffffffu, sq,  o);
    }
    if (lane == 0) { s1[w] = sum; s2[w] = sq; }
    __syncthreads();
    if (w == 0) {
        sum = (lane < 8) ? s1[lane] : 0.0f;
        sq  = (lane < 8) ? s2[lane] : 0.0f;
        #pragma unroll
        for (int o = 4; o; o >>= 1) {
            sum += __shfl_down_sync(0xffffffffu, sum, o);
            sq  += __shfl_down_sync(0xffffffffu, sq,  o);
        }
        if (lane == 0) {
            const float mean = sum / (float)D;
            const float var  = sq / (float)D - mean * mean;
            s1[0] = mean;
            s2[0] = rsqrtf(var + 1e-5f);
        }
    }
    __syncthreads();
    const float mean = s1[0], rstd = s2[0];
    const size_t base = (size_t)blockIdx.x * D;
    for (int i = 0; i < per; ++i) {
        const int c = tid + i * 256;
        const float v = (vals[i] - mean) * rstd * gamma[c] + beta[c];
        oh[base + c] = __float2half(v);
    }
}

// ---------------------------------------------------------------------------
// Ortho loss (fp16 inputs, fp32 math)
// ---------------------------------------------------------------------------
__global__ __launch_bounds__(256)
void ortho_partial(const __half* __restrict__ kc, const __half* __restrict__ ks,
                   const int* __restrict__ idx, int S, int D, int n)
{
    const int t = blockIdx.x;
    const int j = t % n;
    const int i = (t / n) % n;
    const int b = t / (n * n);

    if (i == j) {
        if (threadIdx.x == 0) g_ortho_part[t] = 0.0f;
        return;
    }
    const int si = idx[i], sj = idx[j];
    const __half* ci = kc + ((size_t)b * S + si) * D;
    const __half* cj = kc + ((size_t)b * S + sj) * D;
    const __half* ni = ks + ((size_t)b * S + si) * D;
    const __half* nj = ks + ((size_t)b * S + sj) * D;

    float acc = 0.0f;
    for (int d = threadIdx.x; d < D; d += blockDim.x) {
        const float v = __half2float(ci[d]) * __half2float(cj[d])
                      + __half2float(ni[d]) * __half2float(nj[d]);
        acc = fmaf(v, v, acc);
    }

    __shared__ float sh[32];
    const int lane = threadIdx.x & 31, w = threadIdx.x >> 5;
    #pragma unroll
    for (int o = 16; o; o >>= 1) acc += __shfl_down_sync(0xffffffffu, acc, o);
    if (lane == 0) sh[w] = acc;
    __syncthreads();
    if (w == 0) {
        acc = (lane < 8) ? sh[lane] : 0.0f;
        #pragma unroll
        for (int o = 4; o; o >>= 1) acc += __shfl_down_sync(0xffffffffu, acc, o);
        if (lane == 0) g_ortho_part[t] = acc;
    }
}

__global__ __launch_bounds__(256)
void ortho_reduce(float* __restrict__ out_loc, int total, float denom)
{
    float acc = 0.0f;
    for (int t = threadIdx.x; t < total; t += 256) acc += g_ortho_part[t];

    __shared__ float sh[32];
    const int lane = threadIdx.x & 31, w = threadIdx.x >> 5;
    #pragma unroll
    for (int o = 16; o; o >>= 1) acc += __shfl_down_sync(0xffffffffu, acc, o);
    if (lane == 0) sh[w] = acc;
    __syncthreads();
    if (w == 0) {
        acc = (lane < 8) ? sh[lane] : 0.0f;
        #pragma unroll
        for (int o = 4; o; o >>= 1) acc += __shfl_down_sync(0xffffffffu, acc, o);
        if (lane == 0) *out_loc = acc / denom;
    }
}

// ---------------------------------------------------------------------------
// Launcher
// ---------------------------------------------------------------------------
extern "C" void kernel_launch(void* const* d_in, const int* in_sizes, int n_in,
                              void* d_out, int out_size)
{
    const float* x    = (const float*)d_in[0];
    const float* Wk   = (const float*)d_in[1];
    const float* bk   = (const float*)d_in[2];
    const float* Wv   = (const float*)d_in[3];
    const float* bv   = (const float*)d_in[4];
    const float* Wq   = (const float*)d_in[5];
    const float* bq   = (const float*)d_in[6];
    const float* Wkp  = (const float*)d_in[7];
    const float* bkp  = (const float*)d_in[8];
    const float* Wqp  = (const float*)d_in[9];
    const float* bqp  = (const float*)d_in[10];
    const float* ln_g = (const float*)d_in[11];
    const float* ln_b = (const float*)d_in[12];
    const float* Wo   = (const float*)d_in[13];
    const float* bo   = (const float*)d_in[14];
    const int*   idx  = (const int*)d_in[15];
    const int*   csp  = (const int*)d_in[16];

    const int D  = in_sizes[2];        // 1024
    const int M  = in_sizes[0] / D;    // 16384
    const int Bb = 4;
    const int S  = M / Bb;             // 4096
    const int n  = in_sizes[15];       // 32

    __half *val, *kc, *ks, *qc, *qs, *ret, *xh, *kh, *qh, *wbase;
    cudaGetSymbolAddress((void**)&val, g_val);
    cudaGetSymbolAddress((void**)&kc,  g_kc);
    cudaGetSymbolAddress((void**)&ks,  g_ks);
    cudaGetSymbolAddress((void**)&qc,  g_qc);
    cudaGetSymbolAddress((void**)&qs,  g_qs);
    cudaGetSymbolAddress((void**)&ret, g_ret);
    cudaGetSymbolAddress((void**)&xh,  g_xh);
    cudaGetSymbolAddress((void**)&kh,  g_kh);
    cudaGetSymbolAddress((void**)&qh,  g_qh);
    cudaGetSymbolAddress((void**)&wbase, g_w);
    const size_t WSZ = (size_t)D * D;
    #define WSLOT(i) (wbase + (size_t)(i) * WSZ)

    float* out = (float*)d_out;

    cudaFuncSetAttribute(mma_gemm<2>, cudaFuncAttributeMaxDynamicSharedMemorySize, GSMEM);
    cudaFuncSetAttribute(mma_gemm<3>, cudaFuncAttributeMaxDynamicSharedMemorySize, GSMEM);
    cudaFuncSetAttribute(mma_gemm<4>, cudaFuncAttributeMaxDynamicSharedMemorySize, GSMEM);

    // weight conversions (3 launches)
    W6 ws;
    ws.p[0] = Wk; ws.p[1] = Wv; ws.p[2] = Wq;
    ws.p[3] = Wkp; ws.p[4] = Wqp; ws.p[5] = Wo;
    wtransN<<<dim3(D / 32, D / 32, 3), dim3(32, 32)>>>(ws, 0, wbase, D, D);
    wtransN<<<dim3(D / 32, D / 32, 2), dim3(32, 32)>>>(ws, 3, wbase, D, D);
    wtransN<<<dim3(D / 32, D / 32, 1), dim3(32, 32)>>>(ws, 5, wbase, D, D);

    // x -> fp16
    const int n4 = (int)(NELEM / 4);
    f32_to_f16<<<(n4 + 255) / 256, 256>>>(x, xh, n4);

    // fused QKV projection, N = 3*D (kh, val, qh all fp16)
    mma_gemm<4><<<dim3(3 * D / GBN, M / GBM), NTHREADS, GSMEM>>>(
        xh, nullptr, WSLOT(0), nullptr, bk, bv, bq,
        nullptr, kh, val, qh, nullptr, nullptr, M, 3 * D, D);

    // both phase projections (batched via z), fp16 cos/sin outputs
    mma_gemm<2><<<dim3(D / GBN, M / GBM, 2), NTHREADS, GSMEM>>>(
        kh, qh, WSLOT(3), WSLOT(4), bkp, bqp, nullptr,
        nullptr, kc, ks, qc, qs, nullptr, M, D, D);

    // chunked complex cumsum + retrieve (half2)
    const float inv_sqrt_S = 1.0f / sqrtf((float)S);
    cumsum_retrieve<<<dim3(256, (D / 2) / 256), 256>>>(val, kc, ks, qc, qs, ret,
                                                       Bb, S, D, csp, inv_sqrt_S);

    // ortho partial (needs kc/ks only)
    ortho_partial<<<Bb * n * n, 256>>>(kc, ks, idx, S, D, n);

    // layernorm -> fp16 (reuse kh)
    layernorm_f16<<<M, 256>>>(ret, ln_g, ln_b, kh, D);

    // output projection + residual, straight into d_out
    mma_gemm<3><<<dim3(D / GBN, M / GBM), NTHREADS, GSMEM>>>(
        kh, nullptr, WSLOT(5), nullptr, bo, nullptr, nullptr,
        out, nullptr, nullptr, nullptr, nullptr, x, M, D, D);

    // ortho reduce -> last output element
    const float denom = (float)(n * (n - 1)) * (float)D + 1e-6f;
    ortho_reduce<<<1, 256>>>(out + (out_size - 1), Bb * n * n, denom);
}

// round 12
// speedup vs baseline: 7.1214x; 1.1994x over previous
#include <cuda_runtime.h>
#include <cuda_fp16.h>
#include <math.h>
#include <cstdint>

// ---------------------------------------------------------------------------
// Problem constants (B=4, S=4096, D=1024)
// ---------------------------------------------------------------------------
#define MM    16384
#define DDIM  1024
#define NELEM ((size_t)MM * DDIM)

#define WSCALE     64.0f
#define INV_WSCALE (1.0f / 64.0f)

// fp16 intermediates
__device__ __half g_val[NELEM];
__device__ __half g_kc [NELEM];
__device__ __half g_ks [NELEM];
__device__ __half g_qc [NELEM];
__device__ __half g_qs [NELEM];
__device__ __half g_ret[NELEM];
__device__ __half g_xh[NELEM];
__device__ __half g_kh[NELEM];
// weight slots (all x64-scaled fp16):
// 0 = Wv^T, 1 = Wkc^T (composed), 2 = Wqc^T (composed), 3 = Wo^T,
// 4 = Wkp^T, 5 = Wqp^T, 6 = Wk (row-major), 7 = Wq (row-major)
__device__ __half g_w[8][(size_t)DDIM * DDIM];
__device__ float g_beff[2 * DDIM];     // effective phase biases
__device__ float g_ortho_part[8192];

// ---------------------------------------------------------------------------
// Warp-MMA helpers (baseline PTX: sm_80 features only)
// ---------------------------------------------------------------------------
__device__ __forceinline__ uint32_t smem_u32(const void* p) {
    return (uint32_t)__cvta_generic_to_shared(p);
}

__device__ __forceinline__ void ldsm_x4(uint32_t* r, uint32_t addr) {
    asm volatile("ldmatrix.sync.aligned.m8n8.x4.shared.b16 {%0,%1,%2,%3}, [%4];"
                 : "=r"(r[0]), "=r"(r[1]), "=r"(r[2]), "=r"(r[3]) : "r"(addr));
}

__device__ __forceinline__ void mma16816(float* d, const uint32_t* a, const uint32_t* b) {
    asm volatile(
        "mma.sync.aligned.m16n8k16.row.col.f32.f16.f16.f32 "
        "{%0,%1,%2,%3}, {%4,%5,%6,%7}, {%8,%9}, {%0,%1,%2,%3};"
        : "+f"(d[0]), "+f"(d[1]), "+f"(d[2]), "+f"(d[3])
        : "r"(a[0]), "r"(a[1]), "r"(a[2]), "r"(a[3]), "r"(b[0]), "r"(b[1]));
}

#define CP_ASYNC16(dst, src) \
    asm volatile("cp.async.cg.shared.global [%0], [%1], 16;" :: "r"(dst), "l"(src))
#define CP_COMMIT() asm volatile("cp.async.commit_group;" ::: "memory")
#define CP_WAIT1()  asm volatile("cp.async.wait_group 1;" ::: "memory")
#define CP_WAIT0()  asm volatile("cp.async.wait_group 0;" ::: "memory")

// ---------------------------------------------------------------------------
// fp16 single-pass GEMM: C[M,N] = (1/64) * A[M,K] @ W^T[N,K]  (+ bias)
// CTA tile 256x128x64, 512 threads = 16 warps (warp tile 64x32), 3 stages.
// EPI: 3 = +bias +resid -> fp32 (d_out)
//      5 = fused val/kphase/qphase: col block 0 -> val fp16,
//          block 1 -> sincos -> (kc,ks), block 2 -> sincos -> (qc,qs)
//      6 = weight composition, fp16 out, no bias (batched via blockIdx.z)
// ---------------------------------------------------------------------------
#define GBM 256
#define GBN 128
#define GBK 64
#define NTHREADS 512
#define ROWB 144
#define A_TILEB (GBM * ROWB)
#define B_TILEB (GBN * ROWB)
#define STAGEB (A_TILEB + B_TILEB)
#define GSTAGES 3
#define GSMEM (GSTAGES * STAGEB)       // 165888 B

template <int ROWS>
__device__ __forceinline__ void ld_tile(uint32_t sdst, const __half* g,
                                        int K, int k0, int tid) {
    #pragma unroll
    for (int t = 0; t < ROWS * 8 / NTHREADS; ++t) {
        const int c   = tid + t * NTHREADS;
        const int row = c >> 3;
        const int cc  = c & 7;
        CP_ASYNC16(sdst + row * ROWB + cc * 16,
                   g + (size_t)row * K + k0 + cc * 8);
    }
}

template <int EPI>
__global__ void __launch_bounds__(NTHREADS, 1) mma_gemm(
    const __half* __restrict__ A,  const __half* __restrict__ A2,
    const __half* __restrict__ W,  const __half* __restrict__ W2,
    const float* __restrict__ b0, const float* __restrict__ b1,
    const float* __restrict__ b2,
    float* __restrict__ of0,
    __half* __restrict__ oh0, __half* __restrict__ oh1,
    __half* __restrict__ oh2, __half* __restrict__ oh3,
    __half* __restrict__ oh4,
    const float* __restrict__ resid,
    int M, int N, int K)
{
    extern __shared__ __align__(128) char smem[];
    const uint32_t sb = smem_u32(smem);
    const int tid  = threadIdx.x;
    const int wid  = tid >> 5, lane = tid & 31;
    const int wm   = (wid >> 2) * 64;
    const int wn   = (wid & 3) * 32;
    const int m0   = blockIdx.y * GBM, n0 = blockIdx.x * GBN;
    const int z    = (EPI == 6) ? (int)blockIdx.z : 0;

    const __half* Ap = (EPI == 6 && z) ? A2 : A;
    const __half* Wp = (EPI == 6 && z) ? W2 : W;

    const __half* A0 = Ap + (size_t)m0 * K;
    const __half* B0 = Wp + (size_t)n0 * K;

    const int KT = K / GBK;

    #pragma unroll
    for (int p = 0; p < 2; ++p) {
        const uint32_t st = sb + p * STAGEB;
        ld_tile<GBM>(st, A0, K, p * GBK, tid);
        ld_tile<GBN>(st + A_TILEB, B0, K, p * GBK, tid);
        CP_COMMIT();
    }

    float acc[4][4][4];
    #pragma unroll
    for (int i = 0; i < 4; ++i)
        #pragma unroll
        for (int j = 0; j < 4; ++j)
            #pragma unroll
            for (int e = 0; e < 4; ++e) acc[i][j][e] = 0.0f;

    const int aRow = lane & 15;
    const int aCol = lane & 16;
    const int bRow = (lane & 7) + ((lane & 16) >> 1);
    const int bCol = (lane & 8) * 2;

    for (int kt = 0; kt < KT; ++kt) {
        if (kt + 1 < KT) { CP_WAIT1(); } else { CP_WAIT0(); }
        __syncthreads();

        if (kt + 2 < KT) {
            const uint32_t st = sb + ((kt + 2) % GSTAGES) * STAGEB;
            const int k0 = (kt + 2) * GBK;
            ld_tile<GBM>(st, A0, K, k0, tid);
            ld_tile<GBN>(st + A_TILEB, B0, K, k0, tid);
            CP_COMMIT();
        }

        const uint32_t st = sb + (kt % GSTAGES) * STAGEB;
        const uint32_t sA = st;
        const uint32_t sB = st + A_TILEB;

        #pragma unroll
        for (int h = 0; h < 4; ++h) {
            const int kb = h * 32;

            uint32_t a[4][4], b[2][4];
            #pragma unroll
            for (int mi = 0; mi < 4; ++mi) {
                const uint32_t off = (uint32_t)(wm + mi * 16 + aRow) * ROWB + kb + aCol;
                ldsm_x4(a[mi], sA + off);
            }
            #pragma unroll
            for (int bi = 0; bi < 2; ++bi) {
                const uint32_t off = (uint32_t)(wn + bi * 16 + bRow) * ROWB + kb + bCol;
                ldsm_x4(b[bi], sB + off);
            }

            #pragma unroll
            for (int mi = 0; mi < 4; ++mi) {
                #pragma unroll
                for (int ni = 0; ni < 4; ++ni) {
                    mma16816(acc[mi][ni], a[mi], &b[ni >> 1][(ni & 1) * 2]);
                }
            }
        }
    }

    // epilogue
    #pragma unroll
    for (int mi = 0; mi < 4; ++mi) {
        #pragma unroll
        for (int ni = 0; ni < 4; ++ni) {
            const int nn = n0 + wn + ni * 8 + (lane & 3) * 2;
            #pragma unroll
            for (int half_ = 0; half_ < 2; ++half_) {
                const int row = m0 + wm + mi * 16 + (lane >> 2) + half_ * 8;
                float v0 = acc[mi][ni][half_ * 2 + 0] * INV_WSCALE;
                float v1 = acc[mi][ni][half_ * 2 + 1] * INV_WSCALE;
                if (EPI == 5) {
                    const int sel  = nn >> 10;
                    const int cold = nn & 1023;
                    const float* bp = (sel == 0) ? b0 : (sel == 1) ? b1 : b2;
                    const float2 bv = *(const float2*)(bp + cold);
                    v0 += bv.x; v1 += bv.y;
                    const size_t off = (size_t)row * DDIM + cold;
                    if (sel == 0) {
                        *(__half2*)(oh0 + off) = __floats2half2_rn(v0, v1);
                    } else {
                        float s0, c0, s1, c1;
                        __sincosf(v0, &s0, &c0);
                        __sincosf(v1, &s1, &c1);
                        __half* oc = (sel == 1) ? oh1 : oh3;
                        __half* os = (sel == 1) ? oh2 : oh4;
                        *(__half2*)(oc + off) = __floats2half2_rn(c0, c1);
                        *(__half2*)(os + off) = __floats2half2_rn(s0, s1);
                    }
                } else if (EPI == 6) {
                    // composed weight out: both operands were x64, so
                    // acc = 4096*Wc^T and v = acc/64 = 64*Wc^T, which is
                    // exactly the x64-scaled slot content. Store v directly.
                    __half* op = z ? oh1 : oh0;
                    *(__half2*)(op + (size_t)row * N + nn) =
                        __floats2half2_rn(v0, v1);
                } else {   // EPI 3: +bias +resid -> fp32 d_out
                    const float2 bv = *(const float2*)(b0 + nn);
                    const size_t off = (size_t)row * N + nn;
                    const float2 rv = *(const float2*)(resid + off);
                    *(float2*)(of0 + off) = make_float2(v0 + bv.x + rv.x,
                                                        v1 + bv.y + rv.y);
                }
            }
        }
    }
}

// ---------------------------------------------------------------------------
// fp32 -> fp16 with scale (vectorized)
// ---------------------------------------------------------------------------
__global__ __launch_bounds__(256)
void f32_to_f16s(const float* __restrict__ a, __half* __restrict__ h,
                 float scale, int n4)
{
    const int i = blockIdx.x * 256 + threadIdx.x;
    if (i >= n4) return;
    const float4 v = ((const float4*)a)[i];
    __half2* H = (__half2*)h;
    H[2 * i]     = __floats2half2_rn(v.x * scale, v.y * scale);
    H[2 * i + 1] = __floats2half2_rn(v.z * scale, v.w * scale);
}

// two straight (non-transposed) weight converts in one launch, x64 scale
struct C2 { const float* src[2]; };
__global__ __launch_bounds__(256)
void f16conv2(C2 c, __half* __restrict__ outbase, size_t wsz, int n4)
{
    const float* a = c.src[blockIdx.z];
    __half* h = outbase + blockIdx.z * wsz;
    const int i = blockIdx.x * 256 + threadIdx.x;
    if (i >= n4) return;
    const float4 v = ((const float4*)a)[i];
    __half2* H = (__half2*)h;
    H[2 * i]     = __floats2half2_rn(v.x * WSCALE, v.y * WSCALE);
    H[2 * i + 1] = __floats2half2_rn(v.z * WSCALE, v.w * WSCALE);
}

// transposed weight convert + x64 scale, explicit slot mapping
struct WT4 { const float* src[4]; int slot[4]; };
__global__ __launch_bounds__(1024)
void wtransT(WT4 ws, __half* __restrict__ outbase, int Kd, int Nd)
{
    __shared__ float t[32][33];
    const float* W = ws.src[blockIdx.z];
    __half* th = outbase + (size_t)ws.slot[blockIdx.z] * Kd * Nd;
    const int tx = threadIdx.x, ty = threadIdx.y;
    const int k0 = blockIdx.y * 32, n0 = blockIdx.x * 32;
    t[ty][tx] = W[(size_t)(k0 + ty) * Nd + n0 + tx];
    __syncthreads();
    const float v = t[tx][ty] * WSCALE;
    th[(size_t)(n0 + ty) * Kd + k0 + tx] = __float2half(v);
}

// effective phase bias: beff = b_in @ Wp + b_add   (exact fp32)
__global__ __launch_bounds__(256)
void bias_eff(const float* __restrict__ bin0, const float* __restrict__ Wp0,
              const float* __restrict__ badd0,
              const float* __restrict__ bin1, const float* __restrict__ Wp1,
              const float* __restrict__ badd1,
              float* __restrict__ beff, int D)
{
    const int nidx = blockIdx.x * 256 + threadIdx.x;
    if (nidx >= D) return;
    const float* bin  = blockIdx.z ? bin1 : bin0;
    const float* Wp   = blockIdx.z ? Wp1 : Wp0;
    const float* badd = blockIdx.z ? badd1 : badd0;
    float acc = badd[nidx];
    for (int d = 0; d < D; ++d)
        acc = fmaf(bin[d], Wp[(size_t)d * D + nidx], acc);
    beff[blockIdx.z * D + nidx] = acc;
}

// ---------------------------------------------------------------------------
// Fused chunked cumsum + retrieve, half2-vectorized (fp32 accumulation)
// ---------------------------------------------------------------------------
__global__ __launch_bounds__(256)
void cumsum_retrieve(const __half* __restrict__ value,
                     const __half* __restrict__ kc, const __half* __restrict__ ks,
                     const __half* __restrict__ qc, const __half* __restrict__ qs,
                     __half* __restrict__ ret,
                     int Bb, int S, int D,
                     const int* __restrict__ cs_ptr, float inv_sqrt_S)
{
    const int cs = cs_ptr[0];
    const int nc = (S + cs - 1) / cs;
    const int total = Bb * nc;
    const int D2 = D >> 1;
    const int d2 = blockIdx.y * blockDim.x + threadIdx.x;
    if (d2 >= D2) return;

    const __half2* V2 = (const __half2*)value;
    const __half2* KC = (const __half2*)kc;
    const __half2* KS = (const __half2*)ks;
    const __half2* QC = (const __half2*)qc;
    const __half2* QS = (const __half2*)qs;
    __half2* R2 = (__half2*)ret;

    for (int t = blockIdx.x; t < total; t += gridDim.x) {
        const int b = t / nc;
        const int c = t % nc;
        const int s0 = c * cs;
        const int smax = min(cs, S - s0);
        size_t off = ((size_t)b * S + s0) * D2 + d2;
        float r0 = 0.0f, r1 = 0.0f, i0 = 0.0f, i1 = 0.0f;
        for (int s = 0; s < smax; ++s, off += D2) {
            const float2 v  = __half22float2(V2[off]);
            const float2 c2 = __half22float2(KC[off]);
            const float2 s2 = __half22float2(KS[off]);
            r0 = fmaf(v.x, c2.x, r0);
            r1 = fmaf(v.y, c2.y, r1);
            i0 = fmaf(v.x, s2.x, i0);
            i1 = fmaf(v.y, s2.y, i1);
            const float2 qc2 = __half22float2(QC[off]);
            const float2 qs2 = __half22float2(QS[off]);
            R2[off] = __floats2half2_rn((r0 * qc2.x + i0 * qs2.x) * inv_sqrt_S,
                                        (r1 * qc2.y + i1 * qs2.y) * inv_sqrt_S);
        }
    }
}

// ---------------------------------------------------------------------------
// LayerNorm (fp16 in) -> fp16 out
// ---------------------------------------------------------------------------
__global__ __launch_bounds__(256)
void layernorm_f16(const __half* __restrict__ ret,
                   const float* __restrict__ gamma,
                   const float* __restrict__ beta,
                   __half* __restrict__ oh, int D)
{
    const __half* p = ret + (size_t)blockIdx.x * D;
    const int tid = threadIdx.x;
    const int per = D / 256;

    float vals[8];
    float sum = 0.0f, sq = 0.0f;
    for (int i = 0; i < per; ++i) {
        float v = __half2float(p[tid + i * 256]);
        vals[i] = v;
        sum += v;
        sq  += v * v;
    }

    __shared__ float s1[32], s2[32];
    const int lane = tid & 31, w = tid >> 5;
    #pragma unroll
    for (int o = 16; o; o >>= 1) {
        sum += __shfl_down_sync(0xffffffffu, sum, o);
        sq  += __shfl_down_sync(0xffffffffu, sq,  o);
    }
    if (lane == 0) { s1[w] = sum; s2[w] = sq; }
    __syncthreads();
    if (w == 0) {
        sum = (lane < 8) ? s1[lane] : 0.0f;
        sq  = (lane < 8) ? s2[lane] : 0.0f;
        #pragma unroll
        for (int o = 4; o; o >>= 1) {
            sum += __shfl_down_sync(0xffffffffu, sum, o);
            sq  += __shfl_down_sync(0xffffffffu, sq,  o);
        }
        if (lane == 0) {
            const float mean = sum / (float)D;
            const float var  = sq / (float)D - mean * mean;
            s1[0] = mean;
            s2[0] = rsqrtf(var + 1e-5f);
        }
    }
    __syncthreads();
    const float mean = s1[0], rstd = s2[0];
    const size_t base = (size_t)blockIdx.x * D;
    for (int i = 0; i < per; ++i) {
        const int c = tid + i * 256;
        const float v = (vals[i] - mean) * rstd * gamma[c] + beta[c];
        oh[base + c] = __float2half(v);
    }
}

// ---------------------------------------------------------------------------
// Ortho loss (fp16 inputs, fp32 math)
// ---------------------------------------------------------------------------
__global__ __launch_bounds__(256)
void ortho_partial(const __half* __restrict__ kc, const __half* __restrict__ ks,
                   const int* __restrict__ idx, int S, int D, int n)
{
    const int t = blockIdx.x;
    const int j = t % n;
    const int i = (t / n) % n;
    const int b = t / (n * n);

    if (i == j) {
        if (threadIdx.x == 0) g_ortho_part[t] = 0.0f;
        return;
    }
    const int si = idx[i], sj = idx[j];
    const __half* ci = kc + ((size_t)b * S + si) * D;
    const __half* cj = kc + ((size_t)b * S + sj) * D;
    const __half* ni = ks + ((size_t)b * S + si) * D;
    const __half* nj = ks + ((size_t)b * S + sj) * D;

    float acc = 0.0f;
    for (int d = threadIdx.x; d < D; d += blockDim.x) {
        const float v = __half2float(ci[d]) * __half2float(cj[d])
                      + __half2float(ni[d]) * __half2float(nj[d]);
        acc = fmaf(v, v, acc);
    }

    __shared__ float sh[32];
    const int lane = threadIdx.x & 31, w = threadIdx.x >> 5;
    #pragma unroll
    for (int o = 16; o; o >>= 1) acc += __shfl_down_sync(0xffffffffu, acc, o);
    if (lane == 0) sh[w] = acc;
    __syncthreads();
    if (w == 0) {
        acc = (lane < 8) ? sh[lane] : 0.0f;
        #pragma unroll
        for (int o = 4; o; o >>= 1) acc += __shfl_down_sync(0xffffffffu, acc, o);
        if (lane == 0) g_ortho_part[t] = acc;
    }
}

__global__ __launch_bounds__(256)
void ortho_reduce(float* __restrict__ out_loc, int total, float denom)
{
    float acc = 0.0f;
    for (int t = threadIdx.x; t < total; t += 256) acc += g_ortho_part[t];

    __shared__ float sh[32];
    const int lane = threadIdx.x & 31, w = threadIdx.x >> 5;
    #pragma unroll
    for (int o = 16; o; o >>= 1) acc += __shfl_down_sync(0xffffffffu, acc, o);
    if (lane == 0) sh[w] = acc;
    __syncthreads();
    if (w == 0) {
        acc = (lane < 8) ? sh[lane] : 0.0f;
        #pragma unroll
        for (int o = 4; o; o >>= 1) acc += __shfl_down_sync(0xffffffffu, acc, o);
        if (lane == 0) *out_loc = acc / denom;
    }
}

// ---------------------------------------------------------------------------
// Launcher
// ---------------------------------------------------------------------------
extern "C" void kernel_launch(void* const* d_in, const int* in_sizes, int n_in,
                              void* d_out, int out_size)
{
    const float* x    = (const float*)d_in[0];
    const float* Wk   = (const float*)d_in[1];
    const float* bk   = (const float*)d_in[2];
    const float* Wv   = (const float*)d_in[3];
    const float* bv   = (const float*)d_in[4];
    const float* Wq   = (const float*)d_in[5];
    const float* bq   = (const float*)d_in[6];
    const float* Wkp  = (const float*)d_in[7];
    const float* bkp  = (const float*)d_in[8];
    const float* Wqp  = (const float*)d_in[9];
    const float* bqp  = (const float*)d_in[10];
    const float* ln_g = (const float*)d_in[11];
    const float* ln_b = (const float*)d_in[12];
    const float* Wo   = (const float*)d_in[13];
    const float* bo   = (const float*)d_in[14];
    const int*   idx  = (const int*)d_in[15];
    const int*   csp  = (const int*)d_in[16];

    const int D  = in_sizes[2];        // 1024
    const int M  = in_sizes[0] / D;    // 16384
    const int Bb = 4;
    const int S  = M / Bb;             // 4096
    const int n  = in_sizes[15];       // 32

    __half *val, *kc, *ks, *qc, *qs, *ret, *xh, *kh, *wbase;
    float* beff;
    cudaGetSymbolAddress((void**)&val, g_val);
    cudaGetSymbolAddress((void**)&kc,  g_kc);
    cudaGetSymbolAddress((void**)&ks,  g_ks);
    cudaGetSymbolAddress((void**)&qc,  g_qc);
    cudaGetSymbolAddress((void**)&qs,  g_qs);
    cudaGetSymbolAddress((void**)&ret, g_ret);
    cudaGetSymbolAddress((void**)&xh,  g_xh);
    cudaGetSymbolAddress((void**)&kh,  g_kh);
    cudaGetSymbolAddress((void**)&wbase, g_w);
    cudaGetSymbolAddress((void**)&beff, g_beff);
    const size_t WSZ = (size_t)D * D;
    #define WSLOT(i) (wbase + (size_t)(i) * WSZ)

    float* out = (float*)d_out;

    cudaFuncSetAttribute(mma_gemm<3>, cudaFuncAttributeMaxDynamicSharedMemorySize, GSMEM);
    cudaFuncSetAttribute(mma_gemm<5>, cudaFuncAttributeMaxDynamicSharedMemorySize, GSMEM);
    cudaFuncSetAttribute(mma_gemm<6>, cudaFuncAttributeMaxDynamicSharedMemorySize, GSMEM);

    const int n4w = (int)(WSZ / 4);

    // 1) x -> fp16
    const int n4 = (int)(NELEM / 4);
    f32_to_f16s<<<(n4 + 255) / 256, 256>>>(x, xh, 1.0f, n4);

    // 2) transposed converts: Wv->0, Wo->3, Wkp->4, Wqp->5
    WT4 wt;
    wt.src[0] = Wv;  wt.slot[0] = 0;
    wt.src[1] = Wo;  wt.slot[1] = 3;
    wt.src[2] = Wkp; wt.slot[2] = 4;
    wt.src[3] = Wqp; wt.slot[3] = 5;
    wtransT<<<dim3(D / 32, D / 32, 4), dim3(32, 32)>>>(wt, wbase, D, D);

    // 3) straight converts: Wk->6, Wq->7
    C2 c2; c2.src[0] = Wk; c2.src[1] = Wq;
    f16conv2<<<dim3((n4w + 255) / 256, 1, 2), 256>>>(c2, WSLOT(6), WSZ, n4w);

    // 4) effective phase biases (exact fp32)
    bias_eff<<<dim3(D / 256, 1, 2), 256>>>(bk, Wkp, bkp, bq, Wqp, bqp, beff, D);

    // 5) weight composition: slot1 = Wkc^T = Wkp^T@Wk^T, slot2 = Wqc^T
    mma_gemm<6><<<dim3(D / GBN, D / GBM, 2), NTHREADS, GSMEM>>>(
        WSLOT(4), WSLOT(5), WSLOT(6), WSLOT(7), nullptr, nullptr, nullptr,
        nullptr, WSLOT(1), WSLOT(2), nullptr, nullptr, nullptr, nullptr,
        D, D, D);

    // 6) mega GEMM: [val | kphase | qphase], N = 3*D  <-- ncu profiles this
    mma_gemm<5><<<dim3(3 * D / GBN, M / GBM), NTHREADS, GSMEM>>>(
        xh, nullptr, WSLOT(0), nullptr, bv, beff, beff + D,
        nullptr, val, kc, ks, qc, qs, nullptr, M, 3 * D, D);

    // 7) chunked complex cumsum + retrieve
    const float inv_sqrt_S = 1.0f / sqrtf((float)S);
    cumsum_retrieve<<<dim3(256, (D / 2) / 256), 256>>>(val, kc, ks, qc, qs, ret,
                                                       Bb, S, D, csp, inv_sqrt_S);

    // 8) ortho partial
    ortho_partial<<<Bb * n * n, 256>>>(kc, ks, idx, S, D, n);

    // 9) layernorm -> fp16
    layernorm_f16<<<M, 256>>>(ret, ln_g, ln_b, kh, D);

    // 10) output projection + residual -> d_out
    mma_gemm<3><<<dim3(D / GBN, M / GBM), NTHREADS, GSMEM>>>(
        kh, nullptr, WSLOT(3), nullptr, bo, nullptr, nullptr,
        out, nullptr, nullptr, nullptr, nullptr, nullptr, x, M, D, D);

    // 11) ortho reduce -> last output element
    const float denom = (float)(n * (n - 1)) * (float)D + 1e-6f;
    ortho_reduce<<<1, 256>>>(out + (out_size - 1), Bb * n * n, denom);
}

// round 13
// speedup vs baseline: 7.7157x; 1.0835x over previous
#include <cuda_runtime.h>
#include <cuda_fp16.h>
#include <math.h>
#include <cstdint>

// ---------------------------------------------------------------------------
// Problem constants (B=4, S=4096, D=1024)
// ---------------------------------------------------------------------------
#define MM    16384
#define DDIM  1024
#define NELEM ((size_t)MM * DDIM)

#define WSCALE     64.0f
#define INV_WSCALE (1.0f / 64.0f)

// fp16 intermediates
__device__ __half g_val[NELEM];
__device__ __half g_kc [NELEM];
__device__ __half g_ks [NELEM];
__device__ __half g_qc [NELEM];
__device__ __half g_qs [NELEM];
__device__ __half g_ret[NELEM];
__device__ __half g_xh[NELEM];
__device__ __half g_kh[NELEM];
// weight slots (all x64-scaled fp16):
// 0 = Wv^T, 1 = Wkc^T (composed), 2 = Wqc^T (composed), 3 = Wo^T,
// 4 = Wkp^T, 5 = Wqp^T, 6 = Wk (row-major), 7 = Wq (row-major)
__device__ __half g_w[8][(size_t)DDIM * DDIM];
__device__ float g_beff[2 * DDIM];     // effective phase biases
__device__ float g_ortho_part[8192];

// ---------------------------------------------------------------------------
// Warp-MMA helpers (baseline PTX: sm_80 features only)
// ---------------------------------------------------------------------------
__device__ __forceinline__ uint32_t smem_u32(const void* p) {
    return (uint32_t)__cvta_generic_to_shared(p);
}

__device__ __forceinline__ void ldsm_x4(uint32_t* r, uint32_t addr) {
    asm volatile("ldmatrix.sync.aligned.m8n8.x4.shared.b16 {%0,%1,%2,%3}, [%4];"
                 : "=r"(r[0]), "=r"(r[1]), "=r"(r[2]), "=r"(r[3]) : "r"(addr));
}

__device__ __forceinline__ void mma16816(float* d, const uint32_t* a, const uint32_t* b) {
    asm volatile(
        "mma.sync.aligned.m16n8k16.row.col.f32.f16.f16.f32 "
        "{%0,%1,%2,%3}, {%4,%5,%6,%7}, {%8,%9}, {%0,%1,%2,%3};"
        : "+f"(d[0]), "+f"(d[1]), "+f"(d[2]), "+f"(d[3])
        : "r"(a[0]), "r"(a[1]), "r"(a[2]), "r"(a[3]), "r"(b[0]), "r"(b[1]));
}

#define CP_ASYNC16(dst, src) \
    asm volatile("cp.async.cg.shared.global [%0], [%1], 16;" :: "r"(dst), "l"(src))
#define CP_COMMIT() asm volatile("cp.async.commit_group;" ::: "memory")
#define CP_WAIT1()  asm volatile("cp.async.wait_group 1;" ::: "memory")
#define CP_WAIT0()  asm volatile("cp.async.wait_group 0;" ::: "memory")

// ---------------------------------------------------------------------------
// fp16 single-pass GEMM: C[M,N] = (1/64) * A[M,K] @ W^T[N,K]  (+ bias)
// CTA tile 256x128x64, 512 threads = 16 warps (warp tile 64x32), 3 stages.
// EPI: 3 = +bias +resid -> fp32 (d_out)
//      5 = fused val/kphase/qphase: col block 0 -> val fp16,
//          block 1 -> sincos -> (kc,ks), block 2 -> sincos -> (qc,qs)
//      6 = weight composition, fp16 out, no bias (batched via blockIdx.z)
// ---------------------------------------------------------------------------
#define GBM 256
#define GBN 128
#define GBK 64
#define NTHREADS 512
#define ROWB 144
#define A_TILEB (GBM * ROWB)
#define B_TILEB (GBN * ROWB)
#define STAGEB (A_TILEB + B_TILEB)
#define GSTAGES 3
#define GSMEM (GSTAGES * STAGEB)       // 165888 B

template <int ROWS>
__device__ __forceinline__ void ld_tile(uint32_t sdst, const __half* g,
                                        int K, int k0, int tid) {
    #pragma unroll
    for (int t = 0; t < ROWS * 8 / NTHREADS; ++t) {
        const int c   = tid + t * NTHREADS;
        const int row = c >> 3;
        const int cc  = c & 7;
        CP_ASYNC16(sdst + row * ROWB + cc * 16,
                   g + (size_t)row * K + k0 + cc * 8);
    }
}

template <int EPI>
__global__ void __launch_bounds__(NTHREADS, 1) mma_gemm(
    const __half* __restrict__ A,  const __half* __restrict__ A2,
    const __half* __restrict__ W,  const __half* __restrict__ W2,
    const float* __restrict__ b0, const float* __restrict__ b1,
    const float* __restrict__ b2,
    float* __restrict__ of0,
    __half* __restrict__ oh0, __half* __restrict__ oh1,
    __half* __restrict__ oh2, __half* __restrict__ oh3,
    __half* __restrict__ oh4,
    const float* __restrict__ resid,
    int M, int N, int K)
{
    extern __shared__ __align__(128) char smem[];
    const uint32_t sb = smem_u32(smem);
    const int tid  = threadIdx.x;
    const int wid  = tid >> 5, lane = tid & 31;
    const int wm   = (wid >> 2) * 64;
    const int wn   = (wid & 3) * 32;
    const int m0   = blockIdx.y * GBM, n0 = blockIdx.x * GBN;
    const int z    = (EPI == 6) ? (int)blockIdx.z : 0;

    const __half* Ap = (EPI == 6 && z) ? A2 : A;
    const __half* Wp = (EPI == 6 && z) ? W2 : W;

    const __half* A0 = Ap + (size_t)m0 * K;
    const __half* B0 = Wp + (size_t)n0 * K;

    const int KT = K / GBK;

    #pragma unroll
    for (int p = 0; p < 2; ++p) {
        const uint32_t st = sb + p * STAGEB;
        ld_tile<GBM>(st, A0, K, p * GBK, tid);
        ld_tile<GBN>(st + A_TILEB, B0, K, p * GBK, tid);
        CP_COMMIT();
    }

    float acc[4][4][4];
    #pragma unroll
    for (int i = 0; i < 4; ++i)
        #pragma unroll
        for (int j = 0; j < 4; ++j)
            #pragma unroll
            for (int e = 0; e < 4; ++e) acc[i][j][e] = 0.0f;

    const int aRow = lane & 15;
    const int aCol = lane & 16;
    const int bRow = (lane & 7) + ((lane & 16) >> 1);
    const int bCol = (lane & 8) * 2;

    for (int kt = 0; kt < KT; ++kt) {
        if (kt + 1 < KT) { CP_WAIT1(); } else { CP_WAIT0(); }
        __syncthreads();

        if (kt + 2 < KT) {
            const uint32_t st = sb + ((kt + 2) % GSTAGES) * STAGEB;
            const int k0 = (kt + 2) * GBK;
            ld_tile<GBM>(st, A0, K, k0, tid);
            ld_tile<GBN>(st + A_TILEB, B0, K, k0, tid);
            CP_COMMIT();
        }

        const uint32_t st = sb + (kt % GSTAGES) * STAGEB;
        const uint32_t sA = st;
        const uint32_t sB = st + A_TILEB;

        #pragma unroll
        for (int h = 0; h < 4; ++h) {
            const int kb = h * 32;

            uint32_t a[4][4], b[2][4];
            #pragma unroll
            for (int mi = 0; mi < 4; ++mi) {
                const uint32_t off = (uint32_t)(wm + mi * 16 + aRow) * ROWB + kb + aCol;
                ldsm_x4(a[mi], sA + off);
            }
            #pragma unroll
            for (int bi = 0; bi < 2; ++bi) {
                const uint32_t off = (uint32_t)(wn + bi * 16 + bRow) * ROWB + kb + bCol;
                ldsm_x4(b[bi], sB + off);
            }

            #pragma unroll
            for (int mi = 0; mi < 4; ++mi) {
                #pragma unroll
                for (int ni = 0; ni < 4; ++ni) {
                    mma16816(acc[mi][ni], a[mi], &b[ni >> 1][(ni & 1) * 2]);
                }
            }
        }
    }

    // epilogue
    #pragma unroll
    for (int mi = 0; mi < 4; ++mi) {
        #pragma unroll
        for (int ni = 0; ni < 4; ++ni) {
            const int nn = n0 + wn + ni * 8 + (lane & 3) * 2;
            #pragma unroll
            for (int half_ = 0; half_ < 2; ++half_) {
                const int row = m0 + wm + mi * 16 + (lane >> 2) + half_ * 8;
                float v0 = acc[mi][ni][half_ * 2 + 0] * INV_WSCALE;
                float v1 = acc[mi][ni][half_ * 2 + 1] * INV_WSCALE;
                if (EPI == 5) {
                    const int sel  = nn >> 10;
                    const int cold = nn & 1023;
                    const float* bp = (sel == 0) ? b0 : (sel == 1) ? b1 : b2;
                    const float2 bv = *(const float2*)(bp + cold);
                    v0 += bv.x; v1 += bv.y;
                    const size_t off = (size_t)row * DDIM + cold;
                    if (sel == 0) {
                        *(__half2*)(oh0 + off) = __floats2half2_rn(v0, v1);
                    } else {
                        float s0, c0, s1, c1;
                        __sincosf(v0, &s0, &c0);
                        __sincosf(v1, &s1, &c1);
                        __half* oc = (sel == 1) ? oh1 : oh3;
                        __half* os = (sel == 1) ? oh2 : oh4;
                        *(__half2*)(oc + off) = __floats2half2_rn(c0, c1);
                        *(__half2*)(os + off) = __floats2half2_rn(s0, s1);
                    }
                } else if (EPI == 6) {
                    // composed weight out: acc = 4096*Wc^T, v = 64*Wc^T,
                    // exactly the x64-scaled slot content.
                    __half* op = z ? oh1 : oh0;
                    *(__half2*)(op + (size_t)row * N + nn) =
                        __floats2half2_rn(v0, v1);
                } else {   // EPI 3: +bias +resid -> fp32 d_out
                    const float2 bv = *(const float2*)(b0 + nn);
                    const size_t off = (size_t)row * N + nn;
                    const float2 rv = *(const float2*)(resid + off);
                    *(float2*)(of0 + off) = make_float2(v0 + bv.x + rv.x,
                                                        v1 + bv.y + rv.y);
                }
            }
        }
    }
}

// ---------------------------------------------------------------------------
// fp32 -> fp16 with scale (vectorized)
// ---------------------------------------------------------------------------
__global__ __launch_bounds__(256)
void f32_to_f16s(const float* __restrict__ a, __half* __restrict__ h,
                 float scale, int n4)
{
    const int i = blockIdx.x * 256 + threadIdx.x;
    if (i >= n4) return;
    const float4 v = ((const float4*)a)[i];
    __half2* H = (__half2*)h;
    H[2 * i]     = __floats2half2_rn(v.x * scale, v.y * scale);
    H[2 * i + 1] = __floats2half2_rn(v.z * scale, v.w * scale);
}

// two straight (non-transposed) weight converts in one launch, x64 scale
struct C2 { const float* src[2]; };
__global__ __launch_bounds__(256)
void f16conv2(C2 c, __half* __restrict__ outbase, size_t wsz, int n4)
{
    const float* a = c.src[blockIdx.z];
    __half* h = outbase + blockIdx.z * wsz;
    const int i = blockIdx.x * 256 + threadIdx.x;
    if (i >= n4) return;
    const float4 v = ((const float4*)a)[i];
    __half2* H = (__half2*)h;
    H[2 * i]     = __floats2half2_rn(v.x * WSCALE, v.y * WSCALE);
    H[2 * i + 1] = __floats2half2_rn(v.z * WSCALE, v.w * WSCALE);
}

// transposed weight convert + x64 scale, explicit slot mapping
struct WT4 { const float* src[4]; int slot[4]; };
__global__ __launch_bounds__(1024)
void wtransT(WT4 ws, __half* __restrict__ outbase, int Kd, int Nd)
{
    __shared__ float t[32][33];
    const float* W = ws.src[blockIdx.z];
    __half* th = outbase + (size_t)ws.slot[blockIdx.z] * Kd * Nd;
    const int tx = threadIdx.x, ty = threadIdx.y;
    const int k0 = blockIdx.y * 32, n0 = blockIdx.x * 32;
    t[ty][tx] = W[(size_t)(k0 + ty) * Nd + n0 + tx];
    __syncthreads();
    const float v = t[tx][ty] * WSCALE;
    th[(size_t)(n0 + ty) * Kd + k0 + tx] = __float2half(v);
}

// effective phase bias: beff[n] = b_in @ Wp[:,n] + b_add[n]  (exact fp32)
// One block per output element: 256 threads reduce over d.
__global__ __launch_bounds__(256)
void bias_eff(const float* __restrict__ bin0, const float* __restrict__ Wp0,
              const float* __restrict__ badd0,
              const float* __restrict__ bin1, const float* __restrict__ Wp1,
              const float* __restrict__ badd1,
              float* __restrict__ beff, int D)
{
    const int nidx = blockIdx.x;              // 0..D-1
    const int zi   = blockIdx.z;              // 0 or 1
    const float* bin  = zi ? bin1 : bin0;
    const float* Wp   = zi ? Wp1 : Wp0;
    const float* badd = zi ? badd1 : badd0;

    float acc = 0.0f;
    for (int d = threadIdx.x; d < D; d += 256)
        acc = fmaf(bin[d], Wp[(size_t)d * D + nidx], acc);

    __shared__ float sh[32];
    const int lane = threadIdx.x & 31, w = threadIdx.x >> 5;
    #pragma unroll
    for (int o = 16; o; o >>= 1) acc += __shfl_down_sync(0xffffffffu, acc, o);
    if (lane == 0) sh[w] = acc;
    __syncthreads();
    if (w == 0) {
        acc = (lane < 8) ? sh[lane] : 0.0f;
        #pragma unroll
        for (int o = 4; o; o >>= 1) acc += __shfl_down_sync(0xffffffffu, acc, o);
        if (lane == 0) beff[zi * D + nidx] = acc + badd[nidx];
    }
}

// ---------------------------------------------------------------------------
// Fused chunked cumsum + retrieve, half2-vectorized (fp32 accumulation)
// ---------------------------------------------------------------------------
__global__ __launch_bounds__(256)
void cumsum_retrieve(const __half* __restrict__ value,
                     const __half* __restrict__ kc, const __half* __restrict__ ks,
                     const __half* __restrict__ qc, const __half* __restrict__ qs,
                     __half* __restrict__ ret,
                     int Bb, int S, int D,
                     const int* __restrict__ cs_ptr, float inv_sqrt_S)
{
    const int cs = cs_ptr[0];
    const int nc = (S + cs - 1) / cs;
    const int total = Bb * nc;
    const int D2 = D >> 1;
    const int d2 = blockIdx.y * blockDim.x + threadIdx.x;
    if (d2 >= D2) return;

    const __half2* V2 = (const __half2*)value;
    const __half2* KC = (const __half2*)kc;
    const __half2* KS = (const __half2*)ks;
    const __half2* QC = (const __half2*)qc;
    const __half2* QS = (const __half2*)qs;
    __half2* R2 = (__half2*)ret;

    for (int t = blockIdx.x; t < total; t += gridDim.x) {
        const int b = t / nc;
        const int c = t % nc;
        const int s0 = c * cs;
        const int smax = min(cs, S - s0);
        size_t off = ((size_t)b * S + s0) * D2 + d2;
        float r0 = 0.0f, r1 = 0.0f, i0 = 0.0f, i1 = 0.0f;
        for (int s = 0; s < smax; ++s, off += D2) {
            const float2 v  = __half22float2(V2[off]);
            const float2 c2 = __half22float2(KC[off]);
            const float2 s2 = __half22float2(KS[off]);
            r0 = fmaf(v.x, c2.x, r0);
            r1 = fmaf(v.y, c2.y, r1);
            i0 = fmaf(v.x, s2.x, i0);
            i1 = fmaf(v.y, s2.y, i1);
            const float2 qc2 = __half22float2(QC[off]);
            const float2 qs2 = __half22float2(QS[off]);
            R2[off] = __floats2half2_rn((r0 * qc2.x + i0 * qs2.x) * inv_sqrt_S,
                                        (r1 * qc2.y + i1 * qs2.y) * inv_sqrt_S);
        }
    }
}

// ---------------------------------------------------------------------------
// LayerNorm (fp16 in) -> fp16 out
// ---------------------------------------------------------------------------
__global__ __launch_bounds__(256)
void layernorm_f16(const __half* __restrict__ ret,
                   const float* __restrict__ gamma,
                   const float* __restrict__ beta,
                   __half* __restrict__ oh, int D)
{
    const __half* p = ret + (size_t)blockIdx.x * D;
    const int tid = threadIdx.x;
    const int per = D / 256;

    float vals[8];
    float sum = 0.0f, sq = 0.0f;
    for (int i = 0; i < per; ++i) {
        float v = __half2float(p[tid + i * 256]);
        vals[i] = v;
        sum += v;
        sq  += v * v;
    }

    __shared__ float s1[32], s2[32];
    const int lane = tid & 31, w = tid >> 5;
    #pragma unroll
    for (int o = 16; o; o >>= 1) {
        sum += __shfl_down_sync(0xffffffffu, sum, o);
        sq  += __shfl_down_sync(0xffffffffu, sq,  o);
    }
    if (lane == 0) { s1[w] = sum; s2[w] = sq; }
    __syncthreads();
    if (w == 0) {
        sum = (lane < 8) ? s1[lane] : 0.0f;
        sq  = (lane < 8) ? s2[lane] : 0.0f;
        #pragma unroll
        for (int o = 4; o; o >>= 1) {
            sum += __shfl_down_sync(0xffffffffu, sum, o);
            sq  += __shfl_down_sync(0xffffffffu, sq,  o);
        }
        if (lane == 0) {
            const float mean = sum / (float)D;
            const float var  = sq / (float)D - mean * mean;
            s1[0] = mean;
            s2[0] = rsqrtf(var + 1e-5f);
        }
    }
    __syncthreads();
    const float mean = s1[0], rstd = s2[0];
    const size_t base = (size_t)blockIdx.x * D;
    for (int i = 0; i < per; ++i) {
        const int c = tid + i * 256;
        const float v = (vals[i] - mean) * rstd * gamma[c] + beta[c];
        oh[base + c] = __float2half(v);
    }
}

// ---------------------------------------------------------------------------
// Ortho loss (fp16 inputs, fp32 math)
// ---------------------------------------------------------------------------
__global__ __launch_bounds__(256)
void ortho_partial(const __half* __restrict__ kc, const __half* __restrict__ ks,
                   const int* __restrict__ idx, int S, int D, int n)
{
    const int t = blockIdx.x;
    const int j = t % n;
    const int i = (t / n) % n;
    const int b = t / (n * n);

    if (i == j) {
        if (threadIdx.x == 0) g_ortho_part[t] = 0.0f;
        return;
    }
    const int si = idx[i], sj = idx[j];
    const __half* ci = kc + ((size_t)b * S + si) * D;
    const __half* cj = kc + ((size_t)b * S + sj) * D;
    const __half* ni = ks + ((size_t)b * S + si) * D;
    const __half* nj = ks + ((size_t)b * S + sj) * D;

    float acc = 0.0f;
    for (int d = threadIdx.x; d < D; d += blockDim.x) {
        const float v = __half2float(ci[d]) * __half2float(cj[d])
                      + __half2float(ni[d]) * __half2float(nj[d]);
        acc = fmaf(v, v, acc);
    }

    __shared__ float sh[32];
    const int lane = threadIdx.x & 31, w = threadIdx.x >> 5;
    #pragma unroll
    for (int o = 16; o; o >>= 1) acc += __shfl_down_sync(0xffffffffu, acc, o);
    if (lane == 0) sh[w] = acc;
    __syncthreads();
    if (w == 0) {
        acc = (lane < 8) ? sh[lane] : 0.0f;
        #pragma unroll
        for (int o = 4; o; o >>= 1) acc += __shfl_down_sync(0xffffffffu, acc, o);
        if (lane == 0) g_ortho_part[t] = acc;
    }
}

__global__ __launch_bounds__(256)
void ortho_reduce(float* __restrict__ out_loc, int total, float denom)
{
    float acc = 0.0f;
    for (int t = threadIdx.x; t < total; t += 256) acc += g_ortho_part[t];

    __shared__ float sh[32];
    const int lane = threadIdx.x & 31, w = threadIdx.x >> 5;
    #pragma unroll
    for (int o = 16; o; o >>= 1) acc += __shfl_down_sync(0xffffffffu, acc, o);
    if (lane == 0) sh[w] = acc;
    __syncthreads();
    if (w == 0) {
        acc = (lane < 8) ? sh[lane] : 0.0f;
        #pragma unroll
        for (int o = 4; o; o >>= 1) acc += __shfl_down_sync(0xffffffffu, acc, o);
        if (lane == 0) *out_loc = acc / denom;
    }
}

// ---------------------------------------------------------------------------
// Launcher
// ---------------------------------------------------------------------------
extern "C" void kernel_launch(void* const* d_in, const int* in_sizes, int n_in,
                              void* d_out, int out_size)
{
    const float* x    = (const float*)d_in[0];
    const float* Wk   = (const float*)d_in[1];
    const float* bk   = (const float*)d_in[2];
    const float* Wv   = (const float*)d_in[3];
    const float* bv   = (const float*)d_in[4];
    const float* Wq   = (const float*)d_in[5];
    const float* bq   = (const float*)d_in[6];
    const float* Wkp  = (const float*)d_in[7];
    const float* bkp  = (const float*)d_in[8];
    const float* Wqp  = (const float*)d_in[9];
    const float* bqp  = (const float*)d_in[10];
    const float* ln_g = (const float*)d_in[11];
    const float* ln_b = (const float*)d_in[12];
    const float* Wo   = (const float*)d_in[13];
    const float* bo   = (const float*)d_in[14];
    const int*   idx  = (const int*)d_in[15];
    const int*   csp  = (const int*)d_in[16];

    const int D  = in_sizes[2];        // 1024
    const int M  = in_sizes[0] / D;    // 16384
    const int Bb = 4;
    const int S  = M / Bb;             // 4096
    const int n  = in_sizes[15];       // 32

    __half *val, *kc, *ks, *qc, *qs, *ret, *xh, *kh, *wbase;
    float* beff;
    cudaGetSymbolAddress((void**)&val, g_val);
    cudaGetSymbolAddress((void**)&kc,  g_kc);
    cudaGetSymbolAddress((void**)&ks,  g_ks);
    cudaGetSymbolAddress((void**)&qc,  g_qc);
    cudaGetSymbolAddress((void**)&qs,  g_qs);
    cudaGetSymbolAddress((void**)&ret, g_ret);
    cudaGetSymbolAddress((void**)&xh,  g_xh);
    cudaGetSymbolAddress((void**)&kh,  g_kh);
    cudaGetSymbolAddress((void**)&wbase, g_w);
    cudaGetSymbolAddress((void**)&beff, g_beff);
    const size_t WSZ = (size_t)D * D;
    #define WSLOT(i) (wbase + (size_t)(i) * WSZ)

    float* out = (float*)d_out;

    cudaFuncSetAttribute(mma_gemm<3>, cudaFuncAttributeMaxDynamicSharedMemorySize, GSMEM);
    cudaFuncSetAttribute(mma_gemm<5>, cudaFuncAttributeMaxDynamicSharedMemorySize, GSMEM);
    cudaFuncSetAttribute(mma_gemm<6>, cudaFuncAttributeMaxDynamicSharedMemorySize, GSMEM);

    const int n4w = (int)(WSZ / 4);

    // 1) x -> fp16
    const int n4 = (int)(NELEM / 4);
    f32_to_f16s<<<(n4 + 255) / 256, 256>>>(x, xh, 1.0f, n4);

    // 2) transposed converts: Wv->0, Wo->3, Wkp->4, Wqp->5
    WT4 wt;
    wt.src[0] = Wv;  wt.slot[0] = 0;
    wt.src[1] = Wo;  wt.slot[1] = 3;
    wt.src[2] = Wkp; wt.slot[2] = 4;
    wt.src[3] = Wqp; wt.slot[3] = 5;
    wtransT<<<dim3(D / 32, D / 32, 4), dim3(32, 32)>>>(wt, wbase, D, D);

    // 3) straight converts: Wk->6, Wq->7
    C2 c2; c2.src[0] = Wk; c2.src[1] = Wq;
    f16conv2<<<dim3((n4w + 255) / 256, 1, 2), 256>>>(c2, WSLOT(6), WSZ, n4w);

    // 4) effective phase biases (exact fp32, one block per output)
    bias_eff<<<dim3(D, 1, 2), 256>>>(bk, Wkp, bkp, bq, Wqp, bqp, beff, D);

    // 5) weight composition: slot1 = Wkc^T = Wkp^T@Wk^T, slot2 = Wqc^T
    mma_gemm<6><<<dim3(D / GBN, D / GBM, 2), NTHREADS, GSMEM>>>(
        WSLOT(4), WSLOT(5), WSLOT(6), WSLOT(7), nullptr, nullptr, nullptr,
        nullptr, WSLOT(1), WSLOT(2), nullptr, nullptr, nullptr, nullptr,
        D, D, D);

    // 6) mega GEMM: [val | kphase | qphase], N = 3*D  <-- ncu profiles this
    mma_gemm<5><<<dim3(3 * D / GBN, M / GBM), NTHREADS, GSMEM>>>(
        xh, nullptr, WSLOT(0), nullptr, bv, beff, beff + D,
        nullptr, val, kc, ks, qc, qs, nullptr, M, 3 * D, D);

    // 7) chunked complex cumsum + retrieve
    const float inv_sqrt_S = 1.0f / sqrtf((float)S);
    cumsum_retrieve<<<dim3(256, (D / 2) / 256), 256>>>(val, kc, ks, qc, qs, ret,
                                                       Bb, S, D, csp, inv_sqrt_S);

    // 8) ortho partial
    ortho_partial<<<Bb * n * n, 256>>>(kc, ks, idx, S, D, n);

    // 9) layernorm -> fp16
    layernorm_f16<<<M, 256>>>(ret, ln_g, ln_b, kh, D);

    // 10) output projection + residual -> d_out
    mma_gemm<3><<<dim3(D / GBN, M / GBM), NTHREADS, GSMEM>>>(
        kh, nullptr, WSLOT(3), nullptr, bo, nullptr, nullptr,
        out, nullptr, nullptr, nullptr, nullptr, nullptr, x, M, D, D);

    // 11) ortho reduce -> last output element
    const float denom = (float)(n * (n - 1)) * (float)D + 1e-6f;
    ortho_reduce<<<1, 256>>>(out + (out_size - 1), Bb * n * n, denom);
}

// round 14
// speedup vs baseline: 7.7636x; 1.0062x over previous
#include <cuda_runtime.h>
#include <cuda_fp16.h>
#include <math.h>
#include <cstdint>

// ---------------------------------------------------------------------------
// Problem constants (B=4, S=4096, D=1024)
// ---------------------------------------------------------------------------
#define MM    16384
#define DDIM  1024
#define NELEM ((size_t)MM * DDIM)

#define WSCALE     64.0f
#define INV_WSCALE (1.0f / 64.0f)

// fp16 intermediates
__device__ __half g_val[NELEM];
__device__ __half g_kc [NELEM];
__device__ __half g_ks [NELEM];
__device__ __half g_qc [NELEM];
__device__ __half g_qs [NELEM];
__device__ __half g_xh[NELEM];
__device__ __half g_kh[NELEM];
// weight slots (all x64-scaled fp16):
// 0 = Wv^T, 1 = Wkc^T (composed), 2 = Wqc^T (composed), 3 = Wo^T,
// 4 = Wkp^T, 5 = Wqp^T, 6 = Wk (row-major), 7 = Wq (row-major)
__device__ __half g_w[8][(size_t)DDIM * DDIM];
__device__ float g_beff[2 * DDIM];     // effective phase biases
__device__ float g_ortho_part[8192];

// ---------------------------------------------------------------------------
// Warp-MMA helpers (baseline PTX: sm_80 features only)
// ---------------------------------------------------------------------------
__device__ __forceinline__ uint32_t smem_u32(const void* p) {
    return (uint32_t)__cvta_generic_to_shared(p);
}

__device__ __forceinline__ void ldsm_x4(uint32_t* r, uint32_t addr) {
    asm volatile("ldmatrix.sync.aligned.m8n8.x4.shared.b16 {%0,%1,%2,%3}, [%4];"
                 : "=r"(r[0]), "=r"(r[1]), "=r"(r[2]), "=r"(r[3]) : "r"(addr));
}

__device__ __forceinline__ void mma16816(float* d, const uint32_t* a, const uint32_t* b) {
    asm volatile(
        "mma.sync.aligned.m16n8k16.row.col.f32.f16.f16.f32 "
        "{%0,%1,%2,%3}, {%4,%5,%6,%7}, {%8,%9}, {%0,%1,%2,%3};"
        : "+f"(d[0]), "+f"(d[1]), "+f"(d[2]), "+f"(d[3])
        : "r"(a[0]), "r"(a[1]), "r"(a[2]), "r"(a[3]), "r"(b[0]), "r"(b[1]));
}

#define CP_ASYNC16(dst, src) \
    asm volatile("cp.async.cg.shared.global [%0], [%1], 16;" :: "r"(dst), "l"(src))
#define CP_COMMIT() asm volatile("cp.async.commit_group;" ::: "memory")
#define CP_WAIT1()  asm volatile("cp.async.wait_group 1;" ::: "memory")
#define CP_WAIT0()  asm volatile("cp.async.wait_group 0;" ::: "memory")

// ---------------------------------------------------------------------------
// fp16 single-pass GEMM: C[M,N] = (1/64) * A[M,K] @ W^T[N,K]  (+ bias)
// CTA tile 256x128x64, 512 threads = 16 warps (warp tile 64x32), 3 stages.
// EPI: 3 = +bias +resid -> fp32 (d_out)
//      5 = fused val/kphase/qphase: col block 0 -> val fp16,
//          block 1 -> sincos -> (kc,ks), block 2 -> sincos -> (qc,qs)
//      6 = weight composition, fp16 out, no bias (batched via blockIdx.z)
// ---------------------------------------------------------------------------
#define GBM 256
#define GBN 128
#define GBK 64
#define NTHREADS 512
#define ROWB 144
#define A_TILEB (GBM * ROWB)
#define B_TILEB (GBN * ROWB)
#define STAGEB (A_TILEB + B_TILEB)
#define GSTAGES 3
#define GSMEM (GSTAGES * STAGEB)       // 165888 B

template <int ROWS>
__device__ __forceinline__ void ld_tile(uint32_t sdst, const __half* g,
                                        int K, int k0, int tid) {
    #pragma unroll
    for (int t = 0; t < ROWS * 8 / NTHREADS; ++t) {
        const int c   = tid + t * NTHREADS;
        const int row = c >> 3;
        const int cc  = c & 7;
        CP_ASYNC16(sdst + row * ROWB + cc * 16,
                   g + (size_t)row * K + k0 + cc * 8);
    }
}

template <int EPI>
__global__ void __launch_bounds__(NTHREADS, 1) mma_gemm(
    const __half* __restrict__ A,  const __half* __restrict__ A2,
    const __half* __restrict__ W,  const __half* __restrict__ W2,
    const float* __restrict__ b0, const float* __restrict__ b1,
    const float* __restrict__ b2,
    float* __restrict__ of0,
    __half* __restrict__ oh0, __half* __restrict__ oh1,
    __half* __restrict__ oh2, __half* __restrict__ oh3,
    __half* __restrict__ oh4,
    const float* __restrict__ resid,
    int M, int N, int K)
{
    extern __shared__ __align__(128) char smem[];
    const uint32_t sb = smem_u32(smem);
    const int tid  = threadIdx.x;
    const int wid  = tid >> 5, lane = tid & 31;
    const int wm   = (wid >> 2) * 64;
    const int wn   = (wid & 3) * 32;
    const int m0   = blockIdx.y * GBM, n0 = blockIdx.x * GBN;
    const int z    = (EPI == 6) ? (int)blockIdx.z : 0;

    const __half* Ap = (EPI == 6 && z) ? A2 : A;
    const __half* Wp = (EPI == 6 && z) ? W2 : W;

    const __half* A0 = Ap + (size_t)m0 * K;
    const __half* B0 = Wp + (size_t)n0 * K;

    const int KT = K / GBK;

    #pragma unroll
    for (int p = 0; p < 2; ++p) {
        const uint32_t st = sb + p * STAGEB;
        ld_tile<GBM>(st, A0, K, p * GBK, tid);
        ld_tile<GBN>(st + A_TILEB, B0, K, p * GBK, tid);
        CP_COMMIT();
    }

    float acc[4][4][4];
    #pragma unroll
    for (int i = 0; i < 4; ++i)
        #pragma unroll
        for (int j = 0; j < 4; ++j)
            #pragma unroll
            for (int e = 0; e < 4; ++e) acc[i][j][e] = 0.0f;

    const int aRow = lane & 15;
    const int aCol = lane & 16;
    const int bRow = (lane & 7) + ((lane & 16) >> 1);
    const int bCol = (lane & 8) * 2;

    for (int kt = 0; kt < KT; ++kt) {
        if (kt + 1 < KT) { CP_WAIT1(); } else { CP_WAIT0(); }
        __syncthreads();

        if (kt + 2 < KT) {
            const uint32_t st = sb + ((kt + 2) % GSTAGES) * STAGEB;
            const int k0 = (kt + 2) * GBK;
            ld_tile<GBM>(st, A0, K, k0, tid);
            ld_tile<GBN>(st + A_TILEB, B0, K, k0, tid);
            CP_COMMIT();
        }

        const uint32_t st = sb + (kt % GSTAGES) * STAGEB;
        const uint32_t sA = st;
        const uint32_t sB = st + A_TILEB;

        #pragma unroll
        for (int h = 0; h < 4; ++h) {
            const int kb = h * 32;

            uint32_t a[4][4], b[2][4];
            #pragma unroll
            for (int mi = 0; mi < 4; ++mi) {
                const uint32_t off = (uint32_t)(wm + mi * 16 + aRow) * ROWB + kb + aCol;
                ldsm_x4(a[mi], sA + off);
            }
            #pragma unroll
            for (int bi = 0; bi < 2; ++bi) {
                const uint32_t off = (uint32_t)(wn + bi * 16 + bRow) * ROWB + kb + bCol;
                ldsm_x4(b[bi], sB + off);
            }

            #pragma unroll
            for (int mi = 0; mi < 4; ++mi) {
                #pragma unroll
                for (int ni = 0; ni < 4; ++ni) {
                    mma16816(acc[mi][ni], a[mi], &b[ni >> 1][(ni & 1) * 2]);
                }
            }
        }
    }

    // epilogue
    #pragma unroll
    for (int mi = 0; mi < 4; ++mi) {
        #pragma unroll
        for (int ni = 0; ni < 4; ++ni) {
            const int nn = n0 + wn + ni * 8 + (lane & 3) * 2;
            #pragma unroll
            for (int half_ = 0; half_ < 2; ++half_) {
                const int row = m0 + wm + mi * 16 + (lane >> 2) + half_ * 8;
                float v0 = acc[mi][ni][half_ * 2 + 0] * INV_WSCALE;
                float v1 = acc[mi][ni][half_ * 2 + 1] * INV_WSCALE;
                if (EPI == 5) {
                    const int sel  = nn >> 10;
                    const int cold = nn & 1023;
                    const float* bp = (sel == 0) ? b0 : (sel == 1) ? b1 : b2;
                    const float2 bv = *(const float2*)(bp + cold);
                    v0 += bv.x; v1 += bv.y;
                    const size_t off = (size_t)row * DDIM + cold;
                    if (sel == 0) {
                        *(__half2*)(oh0 + off) = __floats2half2_rn(v0, v1);
                    } else {
                        float s0, c0, s1, c1;
                        __sincosf(v0, &s0, &c0);
                        __sincosf(v1, &s1, &c1);
                        __half* oc = (sel == 1) ? oh1 : oh3;
                        __half* os = (sel == 1) ? oh2 : oh4;
                        *(__half2*)(oc + off) = __floats2half2_rn(c0, c1);
                        *(__half2*)(os + off) = __floats2half2_rn(s0, s1);
                    }
                } else if (EPI == 6) {
                    // composed weight out: acc = 4096*Wc^T, v = 64*Wc^T
                    __half* op = z ? oh1 : oh0;
                    *(__half2*)(op + (size_t)row * N + nn) =
                        __floats2half2_rn(v0, v1);
                } else {   // EPI 3: +bias +resid -> fp32 d_out
                    const float2 bv = *(const float2*)(b0 + nn);
                    const size_t off = (size_t)row * N + nn;
                    const float2 rv = *(const float2*)(resid + off);
                    *(float2*)(of0 + off) = make_float2(v0 + bv.x + rv.x,
                                                        v1 + bv.y + rv.y);
                }
            }
        }
    }
}

// ---------------------------------------------------------------------------
// fp32 -> fp16 with scale (vectorized)
// ---------------------------------------------------------------------------
__global__ __launch_bounds__(256)
void f32_to_f16s(const float* __restrict__ a, __half* __restrict__ h,
                 float scale, int n4)
{
    const int i = blockIdx.x * 256 + threadIdx.x;
    if (i >= n4) return;
    const float4 v = ((const float4*)a)[i];
    __half2* H = (__half2*)h;
    H[2 * i]     = __floats2half2_rn(v.x * scale, v.y * scale);
    H[2 * i + 1] = __floats2half2_rn(v.z * scale, v.w * scale);
}

// two straight (non-transposed) weight converts in one launch, x64 scale
struct C2 { const float* src[2]; };
__global__ __launch_bounds__(256)
void f16conv2(C2 c, __half* __restrict__ outbase, size_t wsz, int n4)
{
    const float* a = c.src[blockIdx.z];
    __half* h = outbase + blockIdx.z * wsz;
    const int i = blockIdx.x * 256 + threadIdx.x;
    if (i >= n4) return;
    const float4 v = ((const float4*)a)[i];
    __half2* H = (__half2*)h;
    H[2 * i]     = __floats2half2_rn(v.x * WSCALE, v.y * WSCALE);
    H[2 * i + 1] = __floats2half2_rn(v.z * WSCALE, v.w * WSCALE);
}

// transposed weight convert + x64 scale, explicit slot mapping
struct WT4 { const float* src[4]; int slot[4]; };
__global__ __launch_bounds__(1024)
void wtransT(WT4 ws, __half* __restrict__ outbase, int Kd, int Nd)
{
    __shared__ float t[32][33];
    const float* W = ws.src[blockIdx.z];
    __half* th = outbase + (size_t)ws.slot[blockIdx.z] * Kd * Nd;
    const int tx = threadIdx.x, ty = threadIdx.y;
    const int k0 = blockIdx.y * 32, n0 = blockIdx.x * 32;
    t[ty][tx] = W[(size_t)(k0 + ty) * Nd + n0 + tx];
    __syncthreads();
    const float v = t[tx][ty] * WSCALE;
    th[(size_t)(n0 + ty) * Kd + k0 + tx] = __float2half(v);
}

// effective phase bias: beff[n] = b_in @ Wp[:,n] + b_add[n]  (exact fp32)
__global__ __launch_bounds__(256)
void bias_eff(const float* __restrict__ bin0, const float* __restrict__ Wp0,
              const float* __restrict__ badd0,
              const float* __restrict__ bin1, const float* __restrict__ Wp1,
              const float* __restrict__ badd1,
              float* __restrict__ beff, int D)
{
    const int nidx = blockIdx.x;
    const int zi   = blockIdx.z;
    const float* bin  = zi ? bin1 : bin0;
    const float* Wp   = zi ? Wp1 : Wp0;
    const float* badd = zi ? badd1 : badd0;

    float acc = 0.0f;
    for (int d = threadIdx.x; d < D; d += 256)
        acc = fmaf(bin[d], Wp[(size_t)d * D + nidx], acc);

    __shared__ float sh[32];
    const int lane = threadIdx.x & 31, w = threadIdx.x >> 5;
    #pragma unroll
    for (int o = 16; o; o >>= 1) acc += __shfl_down_sync(0xffffffffu, acc, o);
    if (lane == 0) sh[w] = acc;
    __syncthreads();
    if (w == 0) {
        acc = (lane < 8) ? sh[lane] : 0.0f;
        #pragma unroll
        for (int o = 4; o; o >>= 1) acc += __shfl_down_sync(0xffffffffu, acc, o);
        if (lane == 0) beff[zi * D + nidx] = acc + badd[nidx];
    }
}

// ---------------------------------------------------------------------------
// FUSED chunked cumsum + retrieve + LayerNorm -> fp16 kh
// One block per (batch, chunk). Each thread owns 4 D-columns (2 half2 slots:
// tid and tid+256). retrieved stays in fp32 registers; per-row LN via block
// reduction; one-row-ahead prefetch hides DRAM latency across the barriers.
// ---------------------------------------------------------------------------
__global__ __launch_bounds__(256)
void cumsum_ln(const __half* __restrict__ value,
               const __half* __restrict__ kc, const __half* __restrict__ ks,
               const __half* __restrict__ qc, const __half* __restrict__ qs,
               const float* __restrict__ gamma, const float* __restrict__ beta,
               __half* __restrict__ okh,
               int Bb, int S, int D,
               const int* __restrict__ cs_ptr, float inv_sqrt_S)
{
    const int cs = cs_ptr[0];
    const int nc = (S + cs - 1) / cs;
    const int total = Bb * nc;
    const int tid = threadIdx.x;
    const int D2 = D >> 1;                 // 512 half2 per row
    const int c0 = tid, c1 = tid + 256;    // owned half2 column slots

    const __half2* V2 = (const __half2*)value;
    const __half2* KC = (const __half2*)kc;
    const __half2* KS = (const __half2*)ks;
    const __half2* QC = (const __half2*)qc;
    const __half2* QS = (const __half2*)qs;
    __half2* OK = (__half2*)okh;

    const float2 ga0 = *(const float2*)(gamma + 2 * c0);
    const float2 ga1 = *(const float2*)(gamma + 2 * c1);
    const float2 bt0 = *(const float2*)(beta  + 2 * c0);
    const float2 bt1 = *(const float2*)(beta  + 2 * c1);

    __shared__ float s1[32], s2[32];
    __shared__ float sMean, sRstd;
    const int lane = tid & 31, w = tid >> 5;
    const float invD = 1.0f / (float)D;

    for (int t = blockIdx.x; t < total; t += gridDim.x) {
        const int b  = t / nc;
        const int s0 = (t % nc) * cs;
        const int smax = min(cs, S - s0);
        size_t off = ((size_t)b * S + s0) * D2;

        float r0 = 0, r1 = 0, r2 = 0, r3 = 0;
        float i0 = 0, i1 = 0, i2 = 0, i3 = 0;

        // prefetch row 0
        __half2 v_0 = V2[off + c0], v_1 = V2[off + c1];
        __half2 kc_0 = KC[off + c0], kc_1 = KC[off + c1];
        __half2 ks_0 = KS[off + c0], ks_1 = KS[off + c1];
        __half2 qc_0 = QC[off + c0], qc_1 = QC[off + c1];
        __half2 qs_0 = QS[off + c0], qs_1 = QS[off + c1];

        for (int s = 0; s < smax; ++s) {
            // issue prefetch of row s+1 before any barrier
            __half2 nv0, nv1, nkc0, nkc1, nks0, nks1, nqc0, nqc1, nqs0, nqs1;
            const size_t noff = off + D2;
            if (s + 1 < smax) {
                nv0 = V2[noff + c0];  nv1 = V2[noff + c1];
                nkc0 = KC[noff + c0]; nkc1 = KC[noff + c1];
                nks0 = KS[noff + c0]; nks1 = KS[noff + c1];
                nqc0 = QC[noff + c0]; nqc1 = QC[noff + c1];
                nqs0 = QS[noff + c0]; nqs1 = QS[noff + c1];
            }

            const float2 vv0 = __half22float2(v_0),  vv1 = __half22float2(v_1);
            const float2 cc0 = __half22float2(kc_0), cc1 = __half22float2(kc_1);
            const float2 ss0 = __half22float2(ks_0), ss1 = __half22float2(ks_1);
            const float2 qcc0 = __half22float2(qc_0), qcc1 = __half22float2(qc_1);
            const float2 qss0 = __half22float2(qs_0), qss1 = __half22float2(qs_1);

            r0 = fmaf(vv0.x, cc0.x, r0); r1 = fmaf(vv0.y, cc0.y, r1);
            r2 = fmaf(vv1.x, cc1.x, r2); r3 = fmaf(vv1.y, cc1.y, r3);
            i0 = fmaf(vv0.x, ss0.x, i0); i1 = fmaf(vv0.y, ss0.y, i1);
            i2 = fmaf(vv1.x, ss1.x, i2); i3 = fmaf(vv1.y, ss1.y, i3);

            const float t0 = (r0 * qcc0.x + i0 * qss0.x) * inv_sqrt_S;
            const float t1 = (r1 * qcc0.y + i1 * qss0.y) * inv_sqrt_S;
            const float t2 = (r2 * qcc1.x + i2 * qss1.x) * inv_sqrt_S;
            const float t3 = (r3 * qcc1.y + i3 * qss1.y) * inv_sqrt_S;

            // block LN reduction over the row
            float sum = t0 + t1 + t2 + t3;
            float sq  = t0 * t0 + t1 * t1 + t2 * t2 + t3 * t3;
            #pragma unroll
            for (int o = 16; o; o >>= 1) {
                sum += __shfl_down_sync(0xffffffffu, sum, o);
                sq  += __shfl_down_sync(0xffffffffu, sq,  o);
            }
            if (lane == 0) { s1[w] = sum; s2[w] = sq; }
            __syncthreads();
            if (w == 0) {
                float su = (lane < 8) ? s1[lane] : 0.0f;
                float qu = (lane < 8) ? s2[lane] : 0.0f;
                #pragma unroll
                for (int o = 4; o; o >>= 1) {
                    su += __shfl_down_sync(0xffffffffu, su, o);
                    qu += __shfl_down_sync(0xffffffffu, qu, o);
                }
                if (lane == 0) {
                    const float mean = su * invD;
                    const float var  = qu * invD - mean * mean;
                    sMean = mean;
                    sRstd = rsqrtf(var + 1e-5f);
                }
            }
            __syncthreads();
            const float mean = sMean, rstd = sRstd;

            const size_t rowoff = ((size_t)b * S + s0 + s) * D2;
            OK[rowoff + c0] = __floats2half2_rn(
                (t0 - mean) * rstd * ga0.x + bt0.x,
                (t1 - mean) * rstd * ga0.y + bt0.y);
            OK[rowoff + c1] = __floats2half2_rn(
                (t2 - mean) * rstd * ga1.x + bt1.x,
                (t3 - mean) * rstd * ga1.y + bt1.y);

            // rotate prefetched row
            v_0 = nv0;  v_1 = nv1;
            kc_0 = nkc0; kc_1 = nkc1;
            ks_0 = nks0; ks_1 = nks1;
            qc_0 = nqc0; qc_1 = nqc1;
            qs_0 = nqs0; qs_1 = nqs1;
            off = noff;
        }
    }
}

// ---------------------------------------------------------------------------
// Ortho loss (fp16 inputs, fp32 math)
// ---------------------------------------------------------------------------
__global__ __launch_bounds__(256)
void ortho_partial(const __half* __restrict__ kc, const __half* __restrict__ ks,
                   const int* __restrict__ idx, int S, int D, int n)
{
    const int t = blockIdx.x;
    const int j = t % n;
    const int i = (t / n) % n;
    const int b = t / (n * n);

    if (i == j) {
        if (threadIdx.x == 0) g_ortho_part[t] = 0.0f;
        return;
    }
    const int si = idx[i], sj = idx[j];
    const __half* ci = kc + ((size_t)b * S + si) * D;
    const __half* cj = kc + ((size_t)b * S + sj) * D;
    const __half* ni = ks + ((size_t)b * S + si) * D;
    const __half* nj = ks + ((size_t)b * S + sj) * D;

    float acc = 0.0f;
    for (int d = threadIdx.x; d < D; d += blockDim.x) {
        const float v = __half2float(ci[d]) * __half2float(cj[d])
                      + __half2float(ni[d]) * __half2float(nj[d]);
        acc = fmaf(v, v, acc);
    }

    __shared__ float sh[32];
    const int lane = threadIdx.x & 31, w = threadIdx.x >> 5;
    #pragma unroll
    for (int o = 16; o; o >>= 1) acc += __shfl_down_sync(0xffffffffu, acc, o);
    if (lane == 0) sh[w] = acc;
    __syncthreads();
    if (w == 0) {
        acc = (lane < 8) ? sh[lane] : 0.0f;
        #pragma unroll
        for (int o = 4; o; o >>= 1) acc += __shfl_down_sync(0xffffffffu, acc, o);
        if (lane == 0) g_ortho_part[t] = acc;
    }
}

__global__ __launch_bounds__(256)
void ortho_reduce(float* __restrict__ out_loc, int total, float denom)
{
    float acc = 0.0f;
    for (int t = threadIdx.x; t < total; t += 256) acc += g_ortho_part[t];

    __shared__ float sh[32];
    const int lane = threadIdx.x & 31, w = threadIdx.x >> 5;
    #pragma unroll
    for (int o = 16; o; o >>= 1) acc += __shfl_down_sync(0xffffffffu, acc, o);
    if (lane == 0) sh[w] = acc;
    __syncthreads();
    if (w == 0) {
        acc = (lane < 8) ? sh[lane] : 0.0f;
        #pragma unroll
        for (int o = 4; o; o >>= 1) acc += __shfl_down_sync(0xffffffffu, acc, o);
        if (lane == 0) *out_loc = acc / denom;
    }
}

// ---------------------------------------------------------------------------
// Launcher
// ---------------------------------------------------------------------------
extern "C" void kernel_launch(void* const* d_in, const int* in_sizes, int n_in,
                              void* d_out, int out_size)
{
    const float* x    = (const float*)d_in[0];
    const float* Wk   = (const float*)d_in[1];
    const float* bk   = (const float*)d_in[2];
    const float* Wv   = (const float*)d_in[3];
    const float* bv   = (const float*)d_in[4];
    const float* Wq   = (const float*)d_in[5];
    const float* bq   = (const float*)d_in[6];
    const float* Wkp  = (const float*)d_in[7];
    const float* bkp  = (const float*)d_in[8];
    const float* Wqp  = (const float*)d_in[9];
    const float* bqp  = (const float*)d_in[10];
    const float* ln_g = (const float*)d_in[11];
    const float* ln_b = (const float*)d_in[12];
    const float* Wo   = (const float*)d_in[13];
    const float* bo   = (const float*)d_in[14];
    const int*   idx  = (const int*)d_in[15];
    const int*   csp  = (const int*)d_in[16];

    const int D  = in_sizes[2];        // 1024
    const int M  = in_sizes[0] / D;    // 16384
    const int Bb = 4;
    const int S  = M / Bb;             // 4096
    const int n  = in_sizes[15];       // 32

    __half *val, *kc, *ks, *qc, *qs, *xh, *kh, *wbase;
    float* beff;
    cudaGetSymbolAddress((void**)&val, g_val);
    cudaGetSymbolAddress((void**)&kc,  g_kc);
    cudaGetSymbolAddress((void**)&ks,  g_ks);
    cudaGetSymbolAddress((void**)&qc,  g_qc);
    cudaGetSymbolAddress((void**)&qs,  g_qs);
    cudaGetSymbolAddress((void**)&xh,  g_xh);
    cudaGetSymbolAddress((void**)&kh,  g_kh);
    cudaGetSymbolAddress((void**)&wbase, g_w);
    cudaGetSymbolAddress((void**)&beff, g_beff);
    const size_t WSZ = (size_t)D * D;
    #define WSLOT(i) (wbase + (size_t)(i) * WSZ)

    float* out = (float*)d_out;

    cudaFuncSetAttribute(mma_gemm<3>, cudaFuncAttributeMaxDynamicSharedMemorySize, GSMEM);
    cudaFuncSetAttribute(mma_gemm<5>, cudaFuncAttributeMaxDynamicSharedMemorySize, GSMEM);
    cudaFuncSetAttribute(mma_gemm<6>, cudaFuncAttributeMaxDynamicSharedMemorySize, GSMEM);

    const int n4w = (int)(WSZ / 4);

    // 1) x -> fp16
    const int n4 = (int)(NELEM / 4);
    f32_to_f16s<<<(n4 + 255) / 256, 256>>>(x, xh, 1.0f, n4);

    // 2) transposed converts: Wv->0, Wo->3, Wkp->4, Wqp->5
    WT4 wt;
    wt.src[0] = Wv;  wt.slot[0] = 0;
    wt.src[1] = Wo;  wt.slot[1] = 3;
    wt.src[2] = Wkp; wt.slot[2] = 4;
    wt.src[3] = Wqp; wt.slot[3] = 5;
    wtransT<<<dim3(D / 32, D / 32, 4), dim3(32, 32)>>>(wt, wbase, D, D);

    // 3) straight converts: Wk->6, Wq->7
    C2 c2; c2.src[0] = Wk; c2.src[1] = Wq;
    f16conv2<<<dim3((n4w + 255) / 256, 1, 2), 256>>>(c2, WSLOT(6), WSZ, n4w);

    // 4) effective phase biases
    bias_eff<<<dim3(D, 1, 2), 256>>>(bk, Wkp, bkp, bq, Wqp, bqp, beff, D);

    // 5) weight composition: slot1 = Wkc^T, slot2 = Wqc^T
    mma_gemm<6><<<dim3(D / GBN, D / GBM, 2), NTHREADS, GSMEM>>>(
        WSLOT(4), WSLOT(5), WSLOT(6), WSLOT(7), nullptr, nullptr, nullptr,
        nullptr, WSLOT(1), WSLOT(2), nullptr, nullptr, nullptr, nullptr,
        D, D, D);

    // 6) mega GEMM: [val | kphase | qphase], N = 3*D  <-- ncu profiles this
    mma_gemm<5><<<dim3(3 * D / GBN, M / GBM), NTHREADS, GSMEM>>>(
        xh, nullptr, WSLOT(0), nullptr, bv, beff, beff + D,
        nullptr, val, kc, ks, qc, qs, nullptr, M, 3 * D, D);

    // 7) fused cumsum + retrieve + layernorm -> kh (fp16)
    cumsum_ln<<<256, 256>>>(val, kc, ks, qc, qs, ln_g, ln_b, kh,
                            Bb, S, D, csp, 1.0f / sqrtf((float)S));

    // 8) ortho partial
    ortho_partial<<<Bb * n * n, 256>>>(kc, ks, idx, S, D, n);

    // 9) output projection + residual -> d_out
    mma_gemm<3><<<dim3(D / GBN, M / GBM), NTHREADS, GSMEM>>>(
        kh, nullptr, WSLOT(3), nullptr, bo, nullptr, nullptr,
        out, nullptr, nullptr, nullptr, nullptr, nullptr, x, M, D, D);

    // 10) ortho reduce -> last output element
    const float denom = (float)(n * (n - 1)) * (float)D + 1e-6f;
    ortho_reduce<<<1, 256>>>(out + (out_size - 1), Bb * n * n, denom);
}

// round 15
// speedup vs baseline: 7.7875x; 1.0031x over previous
#include <cuda_runtime.h>
#include <cuda_fp16.h>
#include <math.h>
#include <cstdint>

// ---------------------------------------------------------------------------
// Problem constants (B=4, S=4096, D=1024)
// ---------------------------------------------------------------------------
#define MM    16384
#define DDIM  1024
#define NELEM ((size_t)MM * DDIM)

#define WSCALE     64.0f
#define INV_WSCALE (1.0f / 64.0f)

// fp16 intermediates
__device__ __half g_val[NELEM];
__device__ __half g_kc [NELEM];
__device__ __half g_ks [NELEM];
__device__ __half g_qc [NELEM];
__device__ __half g_qs [NELEM];
__device__ __half g_xh[NELEM];
__device__ __half g_kh[NELEM];
// weight slots (all x64-scaled fp16):
// 0 = Wv^T, 1 = Wkc^T (composed), 2 = Wqc^T (composed), 3 = Wo^T,
// 4 = Wkp^T, 5 = Wqp^T, 6 = Wk (row-major), 7 = Wq (row-major)
__device__ __half g_w[8][(size_t)DDIM * DDIM];
__device__ float g_beff[2 * DDIM];     // effective phase biases
__device__ float g_ortho_part[8192];

// ---------------------------------------------------------------------------
// Warp-MMA helpers (baseline PTX: sm_80 features only)
// ---------------------------------------------------------------------------
__device__ __forceinline__ uint32_t smem_u32(const void* p) {
    return (uint32_t)__cvta_generic_to_shared(p);
}

__device__ __forceinline__ void ldsm_x4(uint32_t* r, uint32_t addr) {
    asm volatile("ldmatrix.sync.aligned.m8n8.x4.shared.b16 {%0,%1,%2,%3}, [%4];"
                 : "=r"(r[0]), "=r"(r[1]), "=r"(r[2]), "=r"(r[3]) : "r"(addr));
}

__device__ __forceinline__ void mma16816(float* d, const uint32_t* a, const uint32_t* b) {
    asm volatile(
        "mma.sync.aligned.m16n8k16.row.col.f32.f16.f16.f32 "
        "{%0,%1,%2,%3}, {%4,%5,%6,%7}, {%8,%9}, {%0,%1,%2,%3};"
        : "+f"(d[0]), "+f"(d[1]), "+f"(d[2]), "+f"(d[3])
        : "r"(a[0]), "r"(a[1]), "r"(a[2]), "r"(a[3]), "r"(b[0]), "r"(b[1]));
}

#define CP_ASYNC16(dst, src) \
    asm volatile("cp.async.cg.shared.global [%0], [%1], 16;" :: "r"(dst), "l"(src))
#define CP_COMMIT() asm volatile("cp.async.commit_group;" ::: "memory")
#define CP_WAIT1()  asm volatile("cp.async.wait_group 1;" ::: "memory")
#define CP_WAIT0()  asm volatile("cp.async.wait_group 0;" ::: "memory")

// ---------------------------------------------------------------------------
// fp16 single-pass GEMM: C[M,N] = (1/64) * A[M,K] @ W^T[N,K]  (+ bias)
// CTA tile 256x128x64, 512 threads = 16 warps (warp tile 64x32), 3 stages.
// EPI: 3 = +bias +resid -> fp32 (d_out)
//      5 = fused val/kphase/qphase: col block 0 -> val fp16,
//          block 1 -> sincos -> (kc,ks), block 2 -> sincos -> (qc,qs)
//      6 = weight composition, fp16 out, no bias (batched via blockIdx.z)
// ---------------------------------------------------------------------------
#define GBM 256
#define GBN 128
#define GBK 64
#define NTHREADS 512
#define ROWB 144
#define A_TILEB (GBM * ROWB)
#define B_TILEB (GBN * ROWB)
#define STAGEB (A_TILEB + B_TILEB)
#define GSTAGES 3
#define GSMEM (GSTAGES * STAGEB)       // 165888 B

template <int ROWS>
__device__ __forceinline__ void ld_tile(uint32_t sdst, const __half* g,
                                        int K, int k0, int tid) {
    #pragma unroll
    for (int t = 0; t < ROWS * 8 / NTHREADS; ++t) {
        const int c   = tid + t * NTHREADS;
        const int row = c >> 3;
        const int cc  = c & 7;
        CP_ASYNC16(sdst + row * ROWB + cc * 16,
                   g + (size_t)row * K + k0 + cc * 8);
    }
}

template <int EPI>
__global__ void __launch_bounds__(NTHREADS, 1) mma_gemm(
    const __half* __restrict__ A,  const __half* __restrict__ A2,
    const __half* __restrict__ W,  const __half* __restrict__ W2,
    const float* __restrict__ b0, const float* __restrict__ b1,
    const float* __restrict__ b2,
    float* __restrict__ of0,
    __half* __restrict__ oh0, __half* __restrict__ oh1,
    __half* __restrict__ oh2, __half* __restrict__ oh3,
    __half* __restrict__ oh4,
    const float* __restrict__ resid,
    int M, int N, int K)
{
    extern __shared__ __align__(128) char smem[];
    const uint32_t sb = smem_u32(smem);
    const int tid  = threadIdx.x;
    const int wid  = tid >> 5, lane = tid & 31;
    const int wm   = (wid >> 2) * 64;
    const int wn   = (wid & 3) * 32;
    const int m0   = blockIdx.y * GBM, n0 = blockIdx.x * GBN;
    const int z    = (EPI == 6) ? (int)blockIdx.z : 0;

    const __half* Ap = (EPI == 6 && z) ? A2 : A;
    const __half* Wp = (EPI == 6 && z) ? W2 : W;

    const __half* A0 = Ap + (size_t)m0 * K;
    const __half* B0 = Wp + (size_t)n0 * K;

    const int KT = K / GBK;

    #pragma unroll
    for (int p = 0; p < 2; ++p) {
        const uint32_t st = sb + p * STAGEB;
        ld_tile<GBM>(st, A0, K, p * GBK, tid);
        ld_tile<GBN>(st + A_TILEB, B0, K, p * GBK, tid);
        CP_COMMIT();
    }

    float acc[4][4][4];
    #pragma unroll
    for (int i = 0; i < 4; ++i)
        #pragma unroll
        for (int j = 0; j < 4; ++j)
            #pragma unroll
            for (int e = 0; e < 4; ++e) acc[i][j][e] = 0.0f;

    const int aRow = lane & 15;
    const int aCol = lane & 16;
    const int bRow = (lane & 7) + ((lane & 16) >> 1);
    const int bCol = (lane & 8) * 2;

    for (int kt = 0; kt < KT; ++kt) {
        if (kt + 1 < KT) { CP_WAIT1(); } else { CP_WAIT0(); }
        __syncthreads();

        if (kt + 2 < KT) {
            const uint32_t st = sb + ((kt + 2) % GSTAGES) * STAGEB;
            const int k0 = (kt + 2) * GBK;
            ld_tile<GBM>(st, A0, K, k0, tid);
            ld_tile<GBN>(st + A_TILEB, B0, K, k0, tid);
            CP_COMMIT();
        }

        const uint32_t st = sb + (kt % GSTAGES) * STAGEB;
        const uint32_t sA = st;
        const uint32_t sB = st + A_TILEB;

        #pragma unroll
        for (int h = 0; h < 4; ++h) {
            const int kb = h * 32;

            uint32_t a[4][4], b[2][4];
            #pragma unroll
            for (int mi = 0; mi < 4; ++mi) {
                const uint32_t off = (uint32_t)(wm + mi * 16 + aRow) * ROWB + kb + aCol;
                ldsm_x4(a[mi], sA + off);
            }
            #pragma unroll
            for (int bi = 0; bi < 2; ++bi) {
                const uint32_t off = (uint32_t)(wn + bi * 16 + bRow) * ROWB + kb + bCol;
                ldsm_x4(b[bi], sB + off);
            }

            #pragma unroll
            for (int mi = 0; mi < 4; ++mi) {
                #pragma unroll
                for (int ni = 0; ni < 4; ++ni) {
                    mma16816(acc[mi][ni], a[mi], &b[ni >> 1][(ni & 1) * 2]);
                }
            }
        }
    }

    // epilogue
    #pragma unroll
    for (int mi = 0; mi < 4; ++mi) {
        #pragma unroll
        for (int ni = 0; ni < 4; ++ni) {
            const int nn = n0 + wn + ni * 8 + (lane & 3) * 2;
            #pragma unroll
            for (int half_ = 0; half_ < 2; ++half_) {
                const int row = m0 + wm + mi * 16 + (lane >> 2) + half_ * 8;
                float v0 = acc[mi][ni][half_ * 2 + 0] * INV_WSCALE;
                float v1 = acc[mi][ni][half_ * 2 + 1] * INV_WSCALE;
                if (EPI == 5) {
                    const int sel  = nn >> 10;
                    const int cold = nn & 1023;
                    const float* bp = (sel == 0) ? b0 : (sel == 1) ? b1 : b2;
                    const float2 bv = *(const float2*)(bp + cold);
                    v0 += bv.x; v1 += bv.y;
                    const size_t off = (size_t)row * DDIM + cold;
                    if (sel == 0) {
                        *(__half2*)(oh0 + off) = __floats2half2_rn(v0, v1);
                    } else {
                        float s0, c0, s1, c1;
                        __sincosf(v0, &s0, &c0);
                        __sincosf(v1, &s1, &c1);
                        __half* oc = (sel == 1) ? oh1 : oh3;
                        __half* os = (sel == 1) ? oh2 : oh4;
                        *(__half2*)(oc + off) = __floats2half2_rn(c0, c1);
                        *(__half2*)(os + off) = __floats2half2_rn(s0, s1);
                    }
                } else if (EPI == 6) {
                    // composed weight out: acc = 4096*Wc^T, v = 64*Wc^T
                    __half* op = z ? oh1 : oh0;
                    *(__half2*)(op + (size_t)row * N + nn) =
                        __floats2half2_rn(v0, v1);
                } else {   // EPI 3: +bias +resid -> fp32 d_out
                    const float2 bv = *(const float2*)(b0 + nn);
                    const size_t off = (size_t)row * N + nn;
                    const float2 rv = *(const float2*)(resid + off);
                    *(float2*)(of0 + off) = make_float2(v0 + bv.x + rv.x,
                                                        v1 + bv.y + rv.y);
                }
            }
        }
    }
}

// ---------------------------------------------------------------------------
// fp32 -> fp16 with scale (vectorized)
// ---------------------------------------------------------------------------
__global__ __launch_bounds__(256)
void f32_to_f16s(const float* __restrict__ a, __half* __restrict__ h,
                 float scale, int n4)
{
    const int i = blockIdx.x * 256 + threadIdx.x;
    if (i >= n4) return;
    const float4 v = ((const float4*)a)[i];
    __half2* H = (__half2*)h;
    H[2 * i]     = __floats2half2_rn(v.x * scale, v.y * scale);
    H[2 * i + 1] = __floats2half2_rn(v.z * scale, v.w * scale);
}

// two straight (non-transposed) weight converts in one launch, x64 scale
struct C2 { const float* src[2]; };
__global__ __launch_bounds__(256)
void f16conv2(C2 c, __half* __restrict__ outbase, size_t wsz, int n4)
{
    const float* a = c.src[blockIdx.z];
    __half* h = outbase + blockIdx.z * wsz;
    const int i = blockIdx.x * 256 + threadIdx.x;
    if (i >= n4) return;
    const float4 v = ((const float4*)a)[i];
    __half2* H = (__half2*)h;
    H[2 * i]     = __floats2half2_rn(v.x * WSCALE, v.y * WSCALE);
    H[2 * i + 1] = __floats2half2_rn(v.z * WSCALE, v.w * WSCALE);
}

// transposed weight convert + x64 scale, explicit slot mapping
struct WT4 { const float* src[4]; int slot[4]; };
__global__ __launch_bounds__(1024)
void wtransT(WT4 ws, __half* __restrict__ outbase, int Kd, int Nd)
{
    __shared__ float t[32][33];
    const float* W = ws.src[blockIdx.z];
    __half* th = outbase + (size_t)ws.slot[blockIdx.z] * Kd * Nd;
    const int tx = threadIdx.x, ty = threadIdx.y;
    const int k0 = blockIdx.y * 32, n0 = blockIdx.x * 32;
    t[ty][tx] = W[(size_t)(k0 + ty) * Nd + n0 + tx];
    __syncthreads();
    const float v = t[tx][ty] * WSCALE;
    th[(size_t)(n0 + ty) * Kd + k0 + tx] = __float2half(v);
}

// effective phase bias: beff[n] = b_in @ Wp[:,n] + b_add[n]  (exact fp32)
__global__ __launch_bounds__(256)
void bias_eff(const float* __restrict__ bin0, const float* __restrict__ Wp0,
              const float* __restrict__ badd0,
              const float* __restrict__ bin1, const float* __restrict__ Wp1,
              const float* __restrict__ badd1,
              float* __restrict__ beff, int D)
{
    const int nidx = blockIdx.x;
    const int zi   = blockIdx.z;
    const float* bin  = zi ? bin1 : bin0;
    const float* Wp   = zi ? Wp1 : Wp0;
    const float* badd = zi ? badd1 : badd0;

    float acc = 0.0f;
    for (int d = threadIdx.x; d < D; d += 256)
        acc = fmaf(bin[d], Wp[(size_t)d * D + nidx], acc);

    __shared__ float sh[32];
    const int lane = threadIdx.x & 31, w = threadIdx.x >> 5;
    #pragma unroll
    for (int o = 16; o; o >>= 1) acc += __shfl_down_sync(0xffffffffu, acc, o);
    if (lane == 0) sh[w] = acc;
    __syncthreads();
    if (w == 0) {
        acc = (lane < 8) ? sh[lane] : 0.0f;
        #pragma unroll
        for (int o = 4; o; o >>= 1) acc += __shfl_down_sync(0xffffffffu, acc, o);
        if (lane == 0) beff[zi * D + nidx] = acc + badd[nidx];
    }
}

// ---------------------------------------------------------------------------
// FUSED chunked cumsum + retrieve + LayerNorm -> fp16 kh
// One block per (batch, chunk), 512 threads (1 half2 column slot each).
// 4-row batching: prefetch 4 rows of all 5 streams (MLP~20), register cumsum
// across them, then a single two-barrier reduction computes LN stats for all
// 4 rows at once. Barrier pairs per 64-row chunk: 16 (was 64).
// ---------------------------------------------------------------------------
#define CLN_T 512
__global__ __launch_bounds__(CLN_T)
void cumsum_ln(const __half* __restrict__ value,
               const __half* __restrict__ kc, const __half* __restrict__ ks,
               const __half* __restrict__ qc, const __half* __restrict__ qs,
               const float* __restrict__ gamma, const float* __restrict__ beta,
               __half* __restrict__ okh,
               int Bb, int S, int D,
               const int* __restrict__ cs_ptr, float inv_sqrt_S)
{
    const int cs = cs_ptr[0];
    const int nc = (S + cs - 1) / cs;
    const int total = Bb * nc;
    const int tid = threadIdx.x;
    const int D2 = D >> 1;                 // 512 half2 per row
    const int c0 = tid;                    // owned half2 column

    const __half2* V2 = (const __half2*)value;
    const __half2* KC = (const __half2*)kc;
    const __half2* KS = (const __half2*)ks;
    const __half2* QC = (const __half2*)qc;
    const __half2* QS = (const __half2*)qs;
    __half2* OK = (__half2*)okh;

    const float2 ga = *(const float2*)(gamma + 2 * c0);
    const float2 bt = *(const float2*)(beta  + 2 * c0);

    __shared__ float s1[4][16], s2[4][16];
    __shared__ float sMean[4], sRstd[4];
    const int lane = tid & 31, w = tid >> 5;   // 16 warps
    const float invD = 1.0f / (float)D;

    for (int t = blockIdx.x; t < total; t += gridDim.x) {
        const int b  = t / nc;
        const int s0 = (t % nc) * cs;
        const int smax = min(cs, S - s0);
        const size_t base = ((size_t)b * S + s0) * D2 + c0;

        float rr = 0.0f, ii = 0.0f;        // cumsum state (x of half2)
        float rr2 = 0.0f, ii2 = 0.0f;      // (y of half2)

        for (int sq0 = 0; sq0 < smax; sq0 += 4) {
            const int R = min(4, smax - sq0);

            // batched prefetch: R rows x 5 streams
            __half2 pv[4], pkc[4], pks[4], pqc[4], pqs[4];
            #pragma unroll
            for (int r = 0; r < 4; ++r) {
                if (r < R) {
                    const size_t o = base + (size_t)(sq0 + r) * D2;
                    pv[r]  = V2[o];
                    pkc[r] = KC[o];
                    pks[r] = KS[o];
                    pqc[r] = QC[o];
                    pqs[r] = QS[o];
                }
            }

            // register cumsum + retrieve for R rows
            float tx[4], ty[4];
            #pragma unroll
            for (int r = 0; r < 4; ++r) {
                if (r < R) {
                    const float2 vv = __half22float2(pv[r]);
                    const float2 cc = __half22float2(pkc[r]);
                    const float2 ss = __half22float2(pks[r]);
                    rr  = fmaf(vv.x, cc.x, rr);
                    rr2 = fmaf(vv.y, cc.y, rr2);
                    ii  = fmaf(vv.x, ss.x, ii);
                    ii2 = fmaf(vv.y, ss.y, ii2);
                    const float2 qcc = __half22float2(pqc[r]);
                    const float2 qss = __half22float2(pqs[r]);
                    tx[r] = (rr  * qcc.x + ii  * qss.x) * inv_sqrt_S;
                    ty[r] = (rr2 * qcc.y + ii2 * qss.y) * inv_sqrt_S;
                } else { tx[r] = 0.0f; ty[r] = 0.0f; }
            }

            // batched LN stats: per-row sums across the block
            float sum[4], sqv[4];
            #pragma unroll
            for (int r = 0; r < 4; ++r) {
                sum[r] = tx[r] + ty[r];
                sqv[r] = tx[r] * tx[r] + ty[r] * ty[r];
                #pragma unroll
                for (int o = 16; o; o >>= 1) {
                    sum[r] += __shfl_down_sync(0xffffffffu, sum[r], o);
                    sqv[r] += __shfl_down_sync(0xffffffffu, sqv[r], o);
                }
            }
            if (lane == 0) {
                #pragma unroll
                for (int r = 0; r < 4; ++r) { s1[r][w] = sum[r]; s2[r][w] = sqv[r]; }
            }
            __syncthreads();
            if (w == 0 && lane < 4) {
                // lane r handles row r: serial sum over 16 warps (exact order)
                float su = 0.0f, qu = 0.0f;
                #pragma unroll
                for (int k = 0; k < 16; ++k) { su += s1[lane][k]; qu += s2[lane][k]; }
                const float mean = su * invD;
                const float var  = qu * invD - mean * mean;
                sMean[lane] = mean;
                sRstd[lane] = rsqrtf(var + 1e-5f);
            }
            __syncthreads();

            // normalize + store R rows
            #pragma unroll
            for (int r = 0; r < 4; ++r) {
                if (r < R) {
                    const float mean = sMean[r], rstd = sRstd[r];
                    const size_t o = base + (size_t)(sq0 + r) * D2;
                    OK[o] = __floats2half2_rn(
                        (tx[r] - mean) * rstd * ga.x + bt.x,
                        (ty[r] - mean) * rstd * ga.y + bt.y);
                }
            }
        }
    }
}

// ---------------------------------------------------------------------------
// Ortho loss (fp16 inputs, fp32 math)
// ---------------------------------------------------------------------------
__global__ __launch_bounds__(256)
void ortho_partial(const __half* __restrict__ kc, const __half* __restrict__ ks,
                   const int* __restrict__ idx, int S, int D, int n)
{
    const int t = blockIdx.x;
    const int j = t % n;
    const int i = (t / n) % n;
    const int b = t / (n * n);

    if (i == j) {
        if (threadIdx.x == 0) g_ortho_part[t] = 0.0f;
        return;
    }
    const int si = idx[i], sj = idx[j];
    const __half* ci = kc + ((size_t)b * S + si) * D;
    const __half* cj = kc + ((size_t)b * S + sj) * D;
    const __half* ni = ks + ((size_t)b * S + si) * D;
    const __half* nj = ks + ((size_t)b * S + sj) * D;

    float acc = 0.0f;
    for (int d = threadIdx.x; d < D; d += blockDim.x) {
        const float v = __half2float(ci[d]) * __half2float(cj[d])
                      + __half2float(ni[d]) * __half2float(nj[d]);
        acc = fmaf(v, v, acc);
    }

    __shared__ float sh[32];
    const int lane = threadIdx.x & 31, w = threadIdx.x >> 5;
    #pragma unroll
    for (int o = 16; o; o >>= 1) acc += __shfl_down_sync(0xffffffffu, acc, o);
    if (lane == 0) sh[w] = acc;
    __syncthreads();
    if (w == 0) {
        acc = (lane < 8) ? sh[lane] : 0.0f;
        #pragma unroll
        for (int o = 4; o; o >>= 1) acc += __shfl_down_sync(0xffffffffu, acc, o);
        if (lane == 0) g_ortho_part[t] = acc;
    }
}

__global__ __launch_bounds__(256)
void ortho_reduce(float* __restrict__ out_loc, int total, float denom)
{
    float acc = 0.0f;
    for (int t = threadIdx.x; t < total; t += 256) acc += g_ortho_part[t];

    __shared__ float sh[32];
    const int lane = threadIdx.x & 31, w = threadIdx.x >> 5;
    #pragma unroll
    for (int o = 16; o; o >>= 1) acc += __shfl_down_sync(0xffffffffu, acc, o);
    if (lane == 0) sh[w] = acc;
    __syncthreads();
    if (w == 0) {
        acc = (lane < 8) ? sh[lane] : 0.0f;
        #pragma unroll
        for (int o = 4; o; o >>= 1) acc += __shfl_down_sync(0xffffffffu, acc, o);
        if (lane == 0) *out_loc = acc / denom;
    }
}

// ---------------------------------------------------------------------------
// Launcher
// ---------------------------------------------------------------------------
extern "C" void kernel_launch(void* const* d_in, const int* in_sizes, int n_in,
                              void* d_out, int out_size)
{
    const float* x    = (const float*)d_in[0];
    const float* Wk   = (const float*)d_in[1];
    const float* bk   = (const float*)d_in[2];
    const float* Wv   = (const float*)d_in[3];
    const float* bv   = (const float*)d_in[4];
    const float* Wq   = (const float*)d_in[5];
    const float* bq   = (const float*)d_in[6];
    const float* Wkp  = (const float*)d_in[7];
    const float* bkp  = (const float*)d_in[8];
    const float* Wqp  = (const float*)d_in[9];
    const float* bqp  = (const float*)d_in[10];
    const float* ln_g = (const float*)d_in[11];
    const float* ln_b = (const float*)d_in[12];
    const float* Wo   = (const float*)d_in[13];
    const float* bo   = (const float*)d_in[14];
    const int*   idx  = (const int*)d_in[15];
    const int*   csp  = (const int*)d_in[16];

    const int D  = in_sizes[2];        // 1024
    const int M  = in_sizes[0] / D;    // 16384
    const int Bb = 4;
    const int S  = M / Bb;             // 4096
    const int n  = in_sizes[15];       // 32

    __half *val, *kc, *ks, *qc, *qs, *xh, *kh, *wbase;
    float* beff;
    cudaGetSymbolAddress((void**)&val, g_val);
    cudaGetSymbolAddress((void**)&kc,  g_kc);
    cudaGetSymbolAddress((void**)&ks,  g_ks);
    cudaGetSymbolAddress((void**)&qc,  g_qc);
    cudaGetSymbolAddress((void**)&qs,  g_qs);
    cudaGetSymbolAddress((void**)&xh,  g_xh);
    cudaGetSymbolAddress((void**)&kh,  g_kh);
    cudaGetSymbolAddress((void**)&wbase, g_w);
    cudaGetSymbolAddress((void**)&beff, g_beff);
    const size_t WSZ = (size_t)D * D;
    #define WSLOT(i) (wbase + (size_t)(i) * WSZ)

    float* out = (float*)d_out;

    cudaFuncSetAttribute(mma_gemm<3>, cudaFuncAttributeMaxDynamicSharedMemorySize, GSMEM);
    cudaFuncSetAttribute(mma_gemm<5>, cudaFuncAttributeMaxDynamicSharedMemorySize, GSMEM);
    cudaFuncSetAttribute(mma_gemm<6>, cudaFuncAttributeMaxDynamicSharedMemorySize, GSMEM);

    const int n4w = (int)(WSZ / 4);

    // 1) x -> fp16
    const int n4 = (int)(NELEM / 4);
    f32_to_f16s<<<(n4 + 255) / 256, 256>>>(x, xh, 1.0f, n4);

    // 2) transposed converts: Wv->0, Wo->3, Wkp->4, Wqp->5
    WT4 wt;
    wt.src[0] = Wv;  wt.slot[0] = 0;
    wt.src[1] = Wo;  wt.slot[1] = 3;
    wt.src[2] = Wkp; wt.slot[2] = 4;
    wt.src[3] = Wqp; wt.slot[3] = 5;
    wtransT<<<dim3(D / 32, D / 32, 4), dim3(32, 32)>>>(wt, wbase, D, D);

    // 3) straight converts: Wk->6, Wq->7
    C2 c2; c2.src[0] = Wk; c2.src[1] = Wq;
    f16conv2<<<dim3((n4w + 255) / 256, 1, 2), 256>>>(c2, WSLOT(6), WSZ, n4w);

    // 4) effective phase biases
    bias_eff<<<dim3(D, 1, 2), 256>>>(bk, Wkp, bkp, bq, Wqp, bqp, beff, D);

    // 5) weight composition: slot1 = Wkc^T, slot2 = Wqc^T
    mma_gemm<6><<<dim3(D / GBN, D / GBM, 2), NTHREADS, GSMEM>>>(
        WSLOT(4), WSLOT(5), WSLOT(6), WSLOT(7), nullptr, nullptr, nullptr,
        nullptr, WSLOT(1), WSLOT(2), nullptr, nullptr, nullptr, nullptr,
        D, D, D);

    // 6) mega GEMM: [val | kphase | qphase], N = 3*D
    mma_gemm<5><<<dim3(3 * D / GBN, M / GBM), NTHREADS, GSMEM>>>(
        xh, nullptr, WSLOT(0), nullptr, bv, beff, beff + D,
        nullptr, val, kc, ks, qc, qs, nullptr, M, 3 * D, D);

    // 7) fused cumsum + retrieve + layernorm -> kh (fp16)
    cumsum_ln<<<256, CLN_T>>>(val, kc, ks, qc, qs, ln_g, ln_b, kh,
                              Bb, S, D, csp, 1.0f / sqrtf((float)S));

    // 8) ortho partial
    ortho_partial<<<Bb * n * n, 256>>>(kc, ks, idx, S, D, n);

    // 9) output projection + residual -> d_out
    mma_gemm<3><<<dim3(D / GBN, M / GBM), NTHREADS, GSMEM>>>(
        kh, nullptr, WSLOT(3), nullptr, bo, nullptr, nullptr,
        out, nullptr, nullptr, nullptr, nullptr, nullptr, x, M, D, D);

    // 10) ortho reduce -> last output element
    const float denom = (float)(n * (n - 1)) * (float)D + 1e-6f;
    ortho_reduce<<<1, 256>>>(out + (out_size - 1), Bb * n * n, denom);
}

// round 16
// speedup vs baseline: 7.8853x; 1.0125x over previous
#include <cuda_runtime.h>
#include <cuda_fp16.h>
#include <math.h>
#include <cstdint>

// ---------------------------------------------------------------------------
// Problem constants (B=4, S=4096, D=1024)
// ---------------------------------------------------------------------------
#define MM    16384
#define DDIM  1024
#define NELEM ((size_t)MM * DDIM)

#define WSCALE     64.0f
#define INV_WSCALE (1.0f / 64.0f)

// fp16 intermediates
__device__ __half g_val[NELEM];
__device__ __half g_kc [NELEM];
__device__ __half g_ks [NELEM];
__device__ __half g_qc [NELEM];
__device__ __half g_qs [NELEM];
__device__ __half g_xh[NELEM];
__device__ __half g_kh[NELEM];
// weight slots (all x64-scaled fp16):
// 0 = Wv^T, 1 = Wkc^T (composed), 2 = Wqc^T (composed), 3 = Wo^T,
// 4 = Wkp^T, 5 = Wqp^T, 6 = Wk (row-major), 7 = Wq (row-major)
__device__ __half g_w[8][(size_t)DDIM * DDIM];
__device__ float g_beff[2 * DDIM];     // effective phase biases
__device__ float g_ortho_part[8192];

// ---------------------------------------------------------------------------
// Warp-MMA helpers (baseline PTX: sm_80 features only)
// ---------------------------------------------------------------------------
__device__ __forceinline__ uint32_t smem_u32(const void* p) {
    return (uint32_t)__cvta_generic_to_shared(p);
}

__device__ __forceinline__ void ldsm_x4(uint32_t* r, uint32_t addr) {
    asm volatile("ldmatrix.sync.aligned.m8n8.x4.shared.b16 {%0,%1,%2,%3}, [%4];"
                 : "=r"(r[0]), "=r"(r[1]), "=r"(r[2]), "=r"(r[3]) : "r"(addr));
}

__device__ __forceinline__ void mma16816(float* d, const uint32_t* a, const uint32_t* b) {
    asm volatile(
        "mma.sync.aligned.m16n8k16.row.col.f32.f16.f16.f32 "
        "{%0,%1,%2,%3}, {%4,%5,%6,%7}, {%8,%9}, {%0,%1,%2,%3};"
        : "+f"(d[0]), "+f"(d[1]), "+f"(d[2]), "+f"(d[3])
        : "r"(a[0]), "r"(a[1]), "r"(a[2]), "r"(a[3]), "r"(b[0]), "r"(b[1]));
}

#define CP_ASYNC16(dst, src) \
    asm volatile("cp.async.cg.shared.global [%0], [%1], 16;" :: "r"(dst), "l"(src))
#define CP_COMMIT() asm volatile("cp.async.commit_group;" ::: "memory")
#define CP_WAIT1()  asm volatile("cp.async.wait_group 1;" ::: "memory")
#define CP_WAIT0()  asm volatile("cp.async.wait_group 0;" ::: "memory")

// ---------------------------------------------------------------------------
// fp16 single-pass GEMM: C[M,N] = (1/64) * A[M,K] @ W^T[N,K]  (+ bias)
// CTA tile 256x128x64, 512 threads = 16 warps (warp tile 64x32), 3 stages.
// EPI: 3 = +bias +resid -> fp32 (d_out)
//      5 = fused val/kphase/qphase
//      6 = weight composition (batched via blockIdx.z)
// ---------------------------------------------------------------------------
#define GBM 256
#define GBN 128
#define GBK 64
#define NTHREADS 512
#define ROWB 144
#define A_TILEB (GBM * ROWB)
#define B_TILEB (GBN * ROWB)
#define STAGEB (A_TILEB + B_TILEB)
#define GSTAGES 3
#define GSMEM (GSTAGES * STAGEB)       // 165888 B

template <int ROWS>
__device__ __forceinline__ void ld_tile(uint32_t sdst, const __half* g,
                                        int K, int k0, int tid) {
    #pragma unroll
    for (int t = 0; t < ROWS * 8 / NTHREADS; ++t) {
        const int c   = tid + t * NTHREADS;
        const int row = c >> 3;
        const int cc  = c & 7;
        CP_ASYNC16(sdst + row * ROWB + cc * 16,
                   g + (size_t)row * K + k0 + cc * 8);
    }
}

template <int EPI>
__global__ void __launch_bounds__(NTHREADS, 1) mma_gemm(
    const __half* __restrict__ A,  const __half* __restrict__ A2,
    const __half* __restrict__ W,  const __half* __restrict__ W2,
    const float* __restrict__ b0, const float* __restrict__ b1,
    const float* __restrict__ b2,
    float* __restrict__ of0,
    __half* __restrict__ oh0, __half* __restrict__ oh1,
    __half* __restrict__ oh2, __half* __restrict__ oh3,
    __half* __restrict__ oh4,
    const float* __restrict__ resid,
    int M, int N, int K)
{
    extern __shared__ __align__(128) char smem[];
    const uint32_t sb = smem_u32(smem);
    const int tid  = threadIdx.x;
    const int wid  = tid >> 5, lane = tid & 31;
    const int wm   = (wid >> 2) * 64;
    const int wn   = (wid & 3) * 32;
    const int m0   = blockIdx.y * GBM, n0 = blockIdx.x * GBN;
    const int z    = (EPI == 6) ? (int)blockIdx.z : 0;

    const __half* Ap = (EPI == 6 && z) ? A2 : A;
    const __half* Wp = (EPI == 6 && z) ? W2 : W;

    const __half* A0 = Ap + (size_t)m0 * K;
    const __half* B0 = Wp + (size_t)n0 * K;

    const int KT = K / GBK;

    #pragma unroll
    for (int p = 0; p < 2; ++p) {
        const uint32_t st = sb + p * STAGEB;
        ld_tile<GBM>(st, A0, K, p * GBK, tid);
        ld_tile<GBN>(st + A_TILEB, B0, K, p * GBK, tid);
        CP_COMMIT();
    }

    float acc[4][4][4];
    #pragma unroll
    for (int i = 0; i < 4; ++i)
        #pragma unroll
        for (int j = 0; j < 4; ++j)
            #pragma unroll
            for (int e = 0; e < 4; ++e) acc[i][j][e] = 0.0f;

    const int aRow = lane & 15;
    const int aCol = lane & 16;
    const int bRow = (lane & 7) + ((lane & 16) >> 1);
    const int bCol = (lane & 8) * 2;

    for (int kt = 0; kt < KT; ++kt) {
        if (kt + 1 < KT) { CP_WAIT1(); } else { CP_WAIT0(); }
        __syncthreads();

        if (kt + 2 < KT) {
            const uint32_t st = sb + ((kt + 2) % GSTAGES) * STAGEB;
            const int k0 = (kt + 2) * GBK;
            ld_tile<GBM>(st, A0, K, k0, tid);
            ld_tile<GBN>(st + A_TILEB, B0, K, k0, tid);
            CP_COMMIT();
        }

        const uint32_t st = sb + (kt % GSTAGES) * STAGEB;
        const uint32_t sA = st;
        const uint32_t sB = st + A_TILEB;

        #pragma unroll
        for (int h = 0; h < 4; ++h) {
            const int kb = h * 32;

            uint32_t a[4][4], b[2][4];
            #pragma unroll
            for (int mi = 0; mi < 4; ++mi) {
                const uint32_t off = (uint32_t)(wm + mi * 16 + aRow) * ROWB + kb + aCol;
                ldsm_x4(a[mi], sA + off);
            }
            #pragma unroll
            for (int bi = 0; bi < 2; ++bi) {
                const uint32_t off = (uint32_t)(wn + bi * 16 + bRow) * ROWB + kb + bCol;
                ldsm_x4(b[bi], sB + off);
            }

            #pragma unroll
            for (int mi = 0; mi < 4; ++mi) {
                #pragma unroll
                for (int ni = 0; ni < 4; ++ni) {
                    mma16816(acc[mi][ni], a[mi], &b[ni >> 1][(ni & 1) * 2]);
                }
            }
        }
    }

    // epilogue
    #pragma unroll
    for (int mi = 0; mi < 4; ++mi) {
        #pragma unroll
        for (int ni = 0; ni < 4; ++ni) {
            const int nn = n0 + wn + ni * 8 + (lane & 3) * 2;
            #pragma unroll
            for (int half_ = 0; half_ < 2; ++half_) {
                const int row = m0 + wm + mi * 16 + (lane >> 2) + half_ * 8;
                float v0 = acc[mi][ni][half_ * 2 + 0] * INV_WSCALE;
                float v1 = acc[mi][ni][half_ * 2 + 1] * INV_WSCALE;
                if (EPI == 5) {
                    const int sel  = nn >> 10;
                    const int cold = nn & 1023;
                    const float* bp = (sel == 0) ? b0 : (sel == 1) ? b1 : b2;
                    const float2 bv = *(const float2*)(bp + cold);
                    v0 += bv.x; v1 += bv.y;
                    const size_t off = (size_t)row * DDIM + cold;
                    if (sel == 0) {
                        *(__half2*)(oh0 + off) = __floats2half2_rn(v0, v1);
                    } else {
                        float s0, c0, s1, c1;
                        __sincosf(v0, &s0, &c0);
                        __sincosf(v1, &s1, &c1);
                        __half* oc = (sel == 1) ? oh1 : oh3;
                        __half* os = (sel == 1) ? oh2 : oh4;
                        *(__half2*)(oc + off) = __floats2half2_rn(c0, c1);
                        *(__half2*)(os + off) = __floats2half2_rn(s0, s1);
                    }
                } else if (EPI == 6) {
                    // composed weight out: acc = 4096*Wc^T, v = 64*Wc^T
                    __half* op = z ? oh1 : oh0;
                    *(__half2*)(op + (size_t)row * N + nn) =
                        __floats2half2_rn(v0, v1);
                } else {   // EPI 3: +bias +resid -> fp32 d_out
                    const float2 bv = *(const float2*)(b0 + nn);
                    const size_t off = (size_t)row * N + nn;
                    const float2 rv = *(const float2*)(resid + off);
                    *(float2*)(of0 + off) = make_float2(v0 + bv.x + rv.x,
                                                        v1 + bv.y + rv.y);
                }
            }
        }
    }
}

// ---------------------------------------------------------------------------
// fp32 -> fp16 with scale (vectorized)
// ---------------------------------------------------------------------------
__global__ __launch_bounds__(256)
void f32_to_f16s(const float* __restrict__ a, __half* __restrict__ h,
                 float scale, int n4)
{
    const int i = blockIdx.x * 256 + threadIdx.x;
    if (i >= n4) return;
    const float4 v = ((const float4*)a)[i];
    __half2* H = (__half2*)h;
    H[2 * i]     = __floats2half2_rn(v.x * scale, v.y * scale);
    H[2 * i + 1] = __floats2half2_rn(v.z * scale, v.w * scale);
}

// two straight (non-transposed) weight converts in one launch, x64 scale
struct C2 { const float* src[2]; };
__global__ __launch_bounds__(256)
void f16conv2(C2 c, __half* __restrict__ outbase, size_t wsz, int n4)
{
    const float* a = c.src[blockIdx.z];
    __half* h = outbase + blockIdx.z * wsz;
    const int i = blockIdx.x * 256 + threadIdx.x;
    if (i >= n4) return;
    const float4 v = ((const float4*)a)[i];
    __half2* H = (__half2*)h;
    H[2 * i]     = __floats2half2_rn(v.x * WSCALE, v.y * WSCALE);
    H[2 * i + 1] = __floats2half2_rn(v.z * WSCALE, v.w * WSCALE);
}

// transposed weight convert + x64 scale, explicit slot mapping
struct WT4 { const float* src[4]; int slot[4]; };
__global__ __launch_bounds__(1024)
void wtransT(WT4 ws, __half* __restrict__ outbase, int Kd, int Nd)
{
    __shared__ float t[32][33];
    const float* W = ws.src[blockIdx.z];
    __half* th = outbase + (size_t)ws.slot[blockIdx.z] * Kd * Nd;
    const int tx = threadIdx.x, ty = threadIdx.y;
    const int k0 = blockIdx.y * 32, n0 = blockIdx.x * 32;
    t[ty][tx] = W[(size_t)(k0 + ty) * Nd + n0 + tx];
    __syncthreads();
    const float v = t[tx][ty] * WSCALE;
    th[(size_t)(n0 + ty) * Kd + k0 + tx] = __float2half(v);
}

// effective phase bias from the fp16 TRANSPOSED weights (coalesced rows):
// beff[n] = (1/64) * sum_d bin[d] * W64T[n,d] + badd[n]
__global__ __launch_bounds__(256)
void bias_eff16(const float* __restrict__ bin0, const __half* __restrict__ Wt0,
                const float* __restrict__ badd0,
                const float* __restrict__ bin1, const __half* __restrict__ Wt1,
                const float* __restrict__ badd1,
                float* __restrict__ beff, int D)
{
    const int nidx = blockIdx.x;
    const int zi   = blockIdx.z;
    const float* bin  = zi ? bin1 : bin0;
    const float* badd = zi ? badd1 : badd0;
    const __half* row = (zi ? Wt1 : Wt0) + (size_t)nidx * D;

    float acc = 0.0f;
    for (int d = threadIdx.x; d < D; d += 256)
        acc = fmaf(bin[d], __half2float(row[d]), acc);

    __shared__ float sh[32];
    const int lane = threadIdx.x & 31, w = threadIdx.x >> 5;
    #pragma unroll
    for (int o = 16; o; o >>= 1) acc += __shfl_down_sync(0xffffffffu, acc, o);
    if (lane == 0) sh[w] = acc;
    __syncthreads();
    if (w == 0) {
        acc = (lane < 8) ? sh[lane] : 0.0f;
        #pragma unroll
        for (int o = 4; o; o >>= 1) acc += __shfl_down_sync(0xffffffffu, acc, o);
        if (lane == 0) beff[zi * D + nidx] = acc * INV_WSCALE + badd[nidx];
    }
}

// ---------------------------------------------------------------------------
// FUSED chunked cumsum + retrieve + LayerNorm -> fp16 kh (R15 version)
// ---------------------------------------------------------------------------
#define CLN_T 512
__global__ __launch_bounds__(CLN_T)
void cumsum_ln(const __half* __restrict__ value,
               const __half* __restrict__ kc, const __half* __restrict__ ks,
               const __half* __restrict__ qc, const __half* __restrict__ qs,
               const float* __restrict__ gamma, const float* __restrict__ beta,
               __half* __restrict__ okh,
               int Bb, int S, int D,
               const int* __restrict__ cs_ptr, float inv_sqrt_S)
{
    const int cs = cs_ptr[0];
    const int nc = (S + cs - 1) / cs;
    const int total = Bb * nc;
    const int tid = threadIdx.x;
    const int D2 = D >> 1;
    const int c0 = tid;

    const __half2* V2 = (const __half2*)value;
    const __half2* KC = (const __half2*)kc;
    const __half2* KS = (const __half2*)ks;
    const __half2* QC = (const __half2*)qc;
    const __half2* QS = (const __half2*)qs;
    __half2* OK = (__half2*)okh;

    const float2 ga = *(const float2*)(gamma + 2 * c0);
    const float2 bt = *(const float2*)(beta  + 2 * c0);

    __shared__ float s1[4][16], s2[4][16];
    __shared__ float sMean[4], sRstd[4];
    const int lane = tid & 31, w = tid >> 5;
    const float invD = 1.0f / (float)D;

    for (int t = blockIdx.x; t < total; t += gridDim.x) {
        const int b  = t / nc;
        const int s0 = (t % nc) * cs;
        const int smax = min(cs, S - s0);
        const size_t base = ((size_t)b * S + s0) * D2 + c0;

        float rr = 0.0f, ii = 0.0f;
        float rr2 = 0.0f, ii2 = 0.0f;

        for (int sq0 = 0; sq0 < smax; sq0 += 4) {
            const int R = min(4, smax - sq0);

            __half2 pv[4], pkc[4], pks[4], pqc[4], pqs[4];
            #pragma unroll
            for (int r = 0; r < 4; ++r) {
                if (r < R) {
                    const size_t o = base + (size_t)(sq0 + r) * D2;
                    pv[r]  = V2[o];
                    pkc[r] = KC[o];
                    pks[r] = KS[o];
                    pqc[r] = QC[o];
                    pqs[r] = QS[o];
                }
            }

            float tx[4], ty[4];
            #pragma unroll
            for (int r = 0; r < 4; ++r) {
                if (r < R) {
                    const float2 vv = __half22float2(pv[r]);
                    const float2 cc = __half22float2(pkc[r]);
                    const float2 ss = __half22float2(pks[r]);
                    rr  = fmaf(vv.x, cc.x, rr);
                    rr2 = fmaf(vv.y, cc.y, rr2);
                    ii  = fmaf(vv.x, ss.x, ii);
                    ii2 = fmaf(vv.y, ss.y, ii2);
                    const float2 qcc = __half22float2(pqc[r]);
                    const float2 qss = __half22float2(pqs[r]);
                    tx[r] = (rr  * qcc.x + ii  * qss.x) * inv_sqrt_S;
                    ty[r] = (rr2 * qcc.y + ii2 * qss.y) * inv_sqrt_S;
                } else { tx[r] = 0.0f; ty[r] = 0.0f; }
            }

            float sum[4], sqv[4];
            #pragma unroll
            for (int r = 0; r < 4; ++r) {
                sum[r] = tx[r] + ty[r];
                sqv[r] = tx[r] * tx[r] + ty[r] * ty[r];
                #pragma unroll
                for (int o = 16; o; o >>= 1) {
                    sum[r] += __shfl_down_sync(0xffffffffu, sum[r], o);
                    sqv[r] += __shfl_down_sync(0xffffffffu, sqv[r], o);
                }
            }
            if (lane == 0) {
                #pragma unroll
                for (int r = 0; r < 4; ++r) { s1[r][w] = sum[r]; s2[r][w] = sqv[r]; }
            }
            __syncthreads();
            if (w == 0 && lane < 4) {
                float su = 0.0f, qu = 0.0f;
                #pragma unroll
                for (int k = 0; k < 16; ++k) { su += s1[lane][k]; qu += s2[lane][k]; }
                const float mean = su * invD;
                const float var  = qu * invD - mean * mean;
                sMean[lane] = mean;
                sRstd[lane] = rsqrtf(var + 1e-5f);
            }
            __syncthreads();

            #pragma unroll
            for (int r = 0; r < 4; ++r) {
                if (r < R) {
                    const float mean = sMean[r], rstd = sRstd[r];
                    const size_t o = base + (size_t)(sq0 + r) * D2;
                    OK[o] = __floats2half2_rn(
                        (tx[r] - mean) * rstd * ga.x + bt.x,
                        (ty[r] - mean) * rstd * ga.y + bt.y);
                }
            }
        }
    }
}

// ---------------------------------------------------------------------------
// Ortho loss (fp16 inputs, fp32 math)
// ---------------------------------------------------------------------------
__global__ __launch_bounds__(256)
void ortho_partial(const __half* __restrict__ kc, const __half* __restrict__ ks,
                   const int* __restrict__ idx, int S, int D, int n)
{
    const int t = blockIdx.x;
    const int j = t % n;
    const int i = (t / n) % n;
    const int b = t / (n * n);

    if (i == j) {
        if (threadIdx.x == 0) g_ortho_part[t] = 0.0f;
        return;
    }
    const int si = idx[i], sj = idx[j];
    const __half* ci = kc + ((size_t)b * S + si) * D;
    const __half* cj = kc + ((size_t)b * S + sj) * D;
    const __half* ni = ks + ((size_t)b * S + si) * D;
    const __half* nj = ks + ((size_t)b * S + sj) * D;

    float acc = 0.0f;
    for (int d = threadIdx.x; d < D; d += blockDim.x) {
        const float v = __half2float(ci[d]) * __half2float(cj[d])
                      + __half2float(ni[d]) * __half2float(nj[d]);
        acc = fmaf(v, v, acc);
    }

    __shared__ float sh[32];
    const int lane = threadIdx.x & 31, w = threadIdx.x >> 5;
    #pragma unroll
    for (int o = 16; o; o >>= 1) acc += __shfl_down_sync(0xffffffffu, acc, o);
    if (lane == 0) sh[w] = acc;
    __syncthreads();
    if (w == 0) {
        acc = (lane < 8) ? sh[lane] : 0.0f;
        #pragma unroll
        for (int o = 4; o; o >>= 1) acc += __shfl_down_sync(0xffffffffu, acc, o);
        if (lane == 0) g_ortho_part[t] = acc;
    }
}

__global__ __launch_bounds__(256)
void ortho_reduce(float* __restrict__ out_loc, int total, float denom)
{
    float acc = 0.0f;
    for (int t = threadIdx.x; t < total; t += 256) acc += g_ortho_part[t];

    __shared__ float sh[32];
    const int lane = threadIdx.x & 31, w = threadIdx.x >> 5;
    #pragma unroll
    for (int o = 16; o; o >>= 1) acc += __shfl_down_sync(0xffffffffu, acc, o);
    if (lane == 0) sh[w] = acc;
    __syncthreads();
    if (w == 0) {
        acc = (lane < 8) ? sh[lane] : 0.0f;
        #pragma unroll
        for (int o = 4; o; o >>= 1) acc += __shfl_down_sync(0xffffffffu, acc, o);
        if (lane == 0) *out_loc = acc / denom;
    }
}

// ---------------------------------------------------------------------------
// Launcher with graph-level fork/join parallelism
// ---------------------------------------------------------------------------
static cudaStream_t g_s1, g_s2;
static cudaEvent_t  g_e0, g_e1, g_e2, g_e3;
static int g_res_init = 0;

extern "C" void kernel_launch(void* const* d_in, const int* in_sizes, int n_in,
                              void* d_out, int out_size)
{
    if (!g_res_init) {
        cudaStreamCreateWithFlags(&g_s1, cudaStreamNonBlocking);
        cudaStreamCreateWithFlags(&g_s2, cudaStreamNonBlocking);
        cudaEventCreateWithFlags(&g_e0, cudaEventDisableTiming);
        cudaEventCreateWithFlags(&g_e1, cudaEventDisableTiming);
        cudaEventCreateWithFlags(&g_e2, cudaEventDisableTiming);
        cudaEventCreateWithFlags(&g_e3, cudaEventDisableTiming);
        g_res_init = 1;
    }

    const float* x    = (const float*)d_in[0];
    const float* Wk   = (const float*)d_in[1];
    const float* bk   = (const float*)d_in[2];
    const float* Wv   = (const float*)d_in[3];
    const float* bv   = (const float*)d_in[4];
    const float* Wq   = (const float*)d_in[5];
    const float* bq   = (const float*)d_in[6];
    const float* Wkp  = (const float*)d_in[7];
    const float* bkp  = (const float*)d_in[8];
    const float* Wqp  = (const float*)d_in[9];
    const float* bqp  = (const float*)d_in[10];
    const float* ln_g = (const float*)d_in[11];
    const float* ln_b = (const float*)d_in[12];
    const float* Wo   = (const float*)d_in[13];
    const float* bo   = (const float*)d_in[14];
    const int*   idx  = (const int*)d_in[15];
    const int*   csp  = (const int*)d_in[16];

    const int D  = in_sizes[2];        // 1024
    const int M  = in_sizes[0] / D;    // 16384
    const int Bb = 4;
    const int S  = M / Bb;             // 4096
    const int n  = in_sizes[15];       // 32

    __half *val, *kc, *ks, *qc, *qs, *xh, *kh, *wbase;
    float* beff;
    cudaGetSymbolAddress((void**)&val, g_val);
    cudaGetSymbolAddress((void**)&kc,  g_kc);
    cudaGetSymbolAddress((void**)&ks,  g_ks);
    cudaGetSymbolAddress((void**)&qc,  g_qc);
    cudaGetSymbolAddress((void**)&qs,  g_qs);
    cudaGetSymbolAddress((void**)&xh,  g_xh);
    cudaGetSymbolAddress((void**)&kh,  g_kh);
    cudaGetSymbolAddress((void**)&wbase, g_w);
    cudaGetSymbolAddress((void**)&beff, g_beff);
    const size_t WSZ = (size_t)D * D;
    #define WSLOT(i) (wbase + (size_t)(i) * WSZ)

    float* out = (float*)d_out;

    cudaFuncSetAttribute(mma_gemm<3>, cudaFuncAttributeMaxDynamicSharedMemorySize, GSMEM);
    cudaFuncSetAttribute(mma_gemm<5>, cudaFuncAttributeMaxDynamicSharedMemorySize, GSMEM);
    cudaFuncSetAttribute(mma_gemm<6>, cudaFuncAttributeMaxDynamicSharedMemorySize, GSMEM);

    const int n4w = (int)(WSZ / 4);
    const int n4  = (int)(NELEM / 4);

    // ---- fork: branch B (weights) on s1, branch A (x conv) on default ----
    cudaEventRecord(g_e0, 0);
    cudaStreamWaitEvent(g_s1, g_e0, 0);

    // branch A (default stream): x -> fp16
    f32_to_f16s<<<(n4 + 255) / 256, 256>>>(x, xh, 1.0f, n4);

    // branch B (s1): weight pipeline
    WT4 wt;
    wt.src[0] = Wv;  wt.slot[0] = 0;
    wt.src[1] = Wo;  wt.slot[1] = 3;
    wt.src[2] = Wkp; wt.slot[2] = 4;
    wt.src[3] = Wqp; wt.slot[3] = 5;
    wtransT<<<dim3(D / 32, D / 32, 4), dim3(32, 32), 0, g_s1>>>(wt, wbase, D, D);

    C2 c2; c2.src[0] = Wk; c2.src[1] = Wq;
    f16conv2<<<dim3((n4w + 255) / 256, 1, 2), 256, 0, g_s1>>>(c2, WSLOT(6), WSZ, n4w);

    bias_eff16<<<dim3(D, 1, 2), 256, 0, g_s1>>>(bk, WSLOT(4), bkp,
                                                bq, WSLOT(5), bqp, beff, D);

    mma_gemm<6><<<dim3(D / GBN, D / GBM, 2), NTHREADS, GSMEM, g_s1>>>(
        WSLOT(4), WSLOT(5), WSLOT(6), WSLOT(7), nullptr, nullptr, nullptr,
        nullptr, WSLOT(1), WSLOT(2), nullptr, nullptr, nullptr, nullptr,
        D, D, D);

    // ---- join branch B into default ----
    cudaEventRecord(g_e1, g_s1);
    cudaStreamWaitEvent(0, g_e1, 0);

    // mega GEMM: [val | kphase | qphase], N = 3*D
    mma_gemm<5><<<dim3(3 * D / GBN, M / GBM), NTHREADS, GSMEM>>>(
        xh, nullptr, WSLOT(0), nullptr, bv, beff, beff + D,
        nullptr, val, kc, ks, qc, qs, nullptr, M, 3 * D, D);

    // ---- fork: ortho branch on s2 ----
    cudaEventRecord(g_e2, 0);
    cudaStreamWaitEvent(g_s2, g_e2, 0);

    ortho_partial<<<Bb * n * n, 256, 0, g_s2>>>(kc, ks, idx, S, D, n);
    const float denom = (float)(n * (n - 1)) * (float)D + 1e-6f;
    ortho_reduce<<<1, 256, 0, g_s2>>>(out + (out_size - 1), Bb * n * n, denom);

    // default: fused cumsum + retrieve + layernorm -> kh
    cumsum_ln<<<256, CLN_T>>>(val, kc, ks, qc, qs, ln_g, ln_b, kh,
                              Bb, S, D, csp, 1.0f / sqrtf((float)S));

    // default: output projection + residual -> d_out
    mma_gemm<3><<<dim3(D / GBN, M / GBM), NTHREADS, GSMEM>>>(
        kh, nullptr, WSLOT(3), nullptr, bo, nullptr, nullptr,
        out, nullptr, nullptr, nullptr, nullptr, nullptr, x, M, D, D);

    // ---- join ortho branch ----
    cudaEventRecord(g_e3, g_s2);
    cudaStreamWaitEvent(0, g_e3, 0);
}